// round 4
// baseline (speedup 1.0000x reference)
#include <cuda_runtime.h>
#include <math.h>
#include <stdint.h>

#define B_  16
#define L_  1024
#define D_  256
#define H_  8
#define NL_ 3
#define M_  (B_ * L_)   // 16384

// ---------------- scratch ----------------
__device__ float g_x[M_ * D_];
__device__ float g_qkv[M_ * 3 * D_];
__device__ float g_ao[M_ * D_];
__device__ float g_h1[M_ * D_];
__device__ float g_red[B_ * 8 * D_];

// ---------------- helpers ----------------
__device__ __forceinline__ uint32_t f2tf32(float x) {
    uint32_t u;
    asm("cvt.rna.tf32.f32 %0, %1;" : "=r"(u) : "f"(x));
    return u;
}

__device__ __forceinline__ void mma_tf32(float c[4], const uint32_t a[4],
                                         const uint32_t b[2]) {
    asm volatile(
        "mma.sync.aligned.m16n8k8.row.col.f32.tf32.tf32.f32 "
        "{%0,%1,%2,%3}, {%4,%5,%6,%7}, {%8,%9}, {%0,%1,%2,%3};\n"
        : "+f"(c[0]), "+f"(c[1]), "+f"(c[2]), "+f"(c[3])
        : "r"(a[0]), "r"(a[1]), "r"(a[2]), "r"(a[3]), "r"(b[0]), "r"(b[1]));
}

// ---------------- embedding gather ----------------
__global__ void embed_kernel(const int* __restrict__ ut,
                             const float* __restrict__ emb,
                             float* __restrict__ x) {
    int row = blockIdx.x;
    int d = threadIdx.x;
    x[(size_t)row * D_ + d] = emb[(size_t)ut[row] * D_ + d];
}

// ---------------- tf32 tensor-core GEMM, 128x128 block, double-buffered ------
// C[M,N] = A[M,K] @ W[N,K]^T + bias (+res) (relu); ragged row-block early exit.
// 256 threads = 8 warps (4 M x 2 N), warp tile 32x64 via m16n8k8.
#define GPAD 36
#define TILE_F (128 * GPAD)   // floats per (A or B) tile buffer
__global__ void __launch_bounds__(256) gemm_tc_kernel(
    const float* __restrict__ A, const float* __restrict__ W,
    const float* __restrict__ bias, const float* __restrict__ res,
    float* __restrict__ C, const int* __restrict__ lengths,
    int N, int K, int doRelu) {
    const int row0 = blockIdx.y * 128;
    {
        int b = row0 >> 10, l0 = row0 & 1023;
        if (l0 >= lengths[b]) return;
    }
    extern __shared__ float smem[];
    float* As[2] = {smem, smem + 2 * TILE_F};
    float* Bs[2] = {smem + TILE_F, smem + 3 * TILE_F};

    const int tid = threadIdx.x;
    const int warp = tid >> 5, lane = tid & 31;
    const int g = lane >> 2, t4 = lane & 3;
    const int wm = (warp & 3) * 32;    // warp M offset
    const int wn = (warp >> 2) * 64;   // warp N offset
    const int col0 = blockIdx.x * 128;

    const int srow = tid >> 1, scol0 = (tid & 1) * 16;

    float acc[2][8][4];
#pragma unroll
    for (int mi = 0; mi < 2; mi++)
#pragma unroll
        for (int ni = 0; ni < 8; ni++)
#pragma unroll
            for (int j = 0; j < 4; j++) acc[mi][ni][j] = 0.f;

    const float* ap = A + (size_t)(row0 + srow) * K + scol0;
    const float* wp = W + (size_t)(col0 + srow) * K + scol0;

    float4 ra[4], rb[4];
#pragma unroll
    for (int i = 0; i < 4; i++) {
        ra[i] = *(const float4*)(ap + i * 4);
        rb[i] = *(const float4*)(wp + i * 4);
    }
    // store tile 0
#pragma unroll
    for (int i = 0; i < 4; i++) {
        uint4 u, v;
        u.x = f2tf32(ra[i].x); u.y = f2tf32(ra[i].y);
        u.z = f2tf32(ra[i].z); u.w = f2tf32(ra[i].w);
        v.x = f2tf32(rb[i].x); v.y = f2tf32(rb[i].y);
        v.z = f2tf32(rb[i].z); v.w = f2tf32(rb[i].w);
        *(uint4*)&As[0][srow * GPAD + scol0 + i * 4] = u;
        *(uint4*)&Bs[0][srow * GPAD + scol0 + i * 4] = v;
    }
    __syncthreads();

    for (int kt = 0; kt < K; kt += 32) {
        const int cur = (kt >> 5) & 1, nxt = cur ^ 1;
        const bool more = (kt + 32) < K;
        if (more) {   // issue global loads for next tile early
#pragma unroll
            for (int i = 0; i < 4; i++) {
                ra[i] = *(const float4*)(ap + kt + 32 + i * 4);
                rb[i] = *(const float4*)(wp + kt + 32 + i * 4);
            }
        }

        const float* Ac = As[cur];
        const float* Bc = Bs[cur];
#pragma unroll
        for (int ks = 0; ks < 4; ks++) {
            const int k0 = ks * 8;
            uint32_t a[2][4];
#pragma unroll
            for (int mi = 0; mi < 2; mi++) {
                int r = wm + mi * 16;
                a[mi][0] = __float_as_uint(Ac[(r + g) * GPAD + k0 + t4]);
                a[mi][1] = __float_as_uint(Ac[(r + g + 8) * GPAD + k0 + t4]);
                a[mi][2] = __float_as_uint(Ac[(r + g) * GPAD + k0 + t4 + 4]);
                a[mi][3] = __float_as_uint(Ac[(r + g + 8) * GPAD + k0 + t4 + 4]);
            }
#pragma unroll
            for (int ni = 0; ni < 8; ni++) {
                int c = wn + ni * 8;
                uint32_t bf[2];
                bf[0] = __float_as_uint(Bc[(c + g) * GPAD + k0 + t4]);
                bf[1] = __float_as_uint(Bc[(c + g) * GPAD + k0 + t4 + 4]);
                mma_tf32(acc[0][ni], a[0], bf);
                mma_tf32(acc[1][ni], a[1], bf);
            }
        }

        if (more) {
#pragma unroll
            for (int i = 0; i < 4; i++) {
                uint4 u, v;
                u.x = f2tf32(ra[i].x); u.y = f2tf32(ra[i].y);
                u.z = f2tf32(ra[i].z); u.w = f2tf32(ra[i].w);
                v.x = f2tf32(rb[i].x); v.y = f2tf32(rb[i].y);
                v.z = f2tf32(rb[i].z); v.w = f2tf32(rb[i].w);
                *(uint4*)&As[nxt][srow * GPAD + scol0 + i * 4] = u;
                *(uint4*)&Bs[nxt][srow * GPAD + scol0 + i * 4] = v;
            }
        }
        __syncthreads();
    }

    // ---- epilogue ----
#pragma unroll
    for (int ni = 0; ni < 8; ni++) {
        int c = col0 + wn + ni * 8 + 2 * t4;
        float b0 = bias[c], b1 = bias[c + 1];
#pragma unroll
        for (int mi = 0; mi < 2; mi++) {
#pragma unroll
            for (int half = 0; half < 2; half++) {
                int r = row0 + wm + mi * 16 + g + half * 8;
                float v0 = acc[mi][ni][half * 2 + 0] + b0;
                float v1 = acc[mi][ni][half * 2 + 1] + b1;
                if (res) {
                    float2 rr = *(const float2*)(res + (size_t)r * N + c);
                    v0 += rr.x; v1 += rr.y;
                }
                if (doRelu) { v0 = fmaxf(v0, 0.f); v1 = fmaxf(v1, 0.f); }
                float2 o; o.x = v0; o.y = v1;
                *(float2*)(C + (size_t)r * N + c) = o;
            }
        }
    }
}

// ---------------- tensor-core masked flash attention (tf32 mma, fp32 softmax) ---
#define QPAD 36
#define KPAD 36
#define VPAD 40
#define PPAD 72
__global__ void __launch_bounds__(128) attn_tc_kernel(
    const float* __restrict__ qkv, float* __restrict__ ao,
    const int* __restrict__ lengths) {
    const int b = blockIdx.z, h = blockIdx.y;
    const int len = lengths[b];
    const int q0 = blockIdx.x * 64;
    if (q0 >= len) return;

    __shared__ float Qs[64 * QPAD];
    __shared__ float Ks[64 * KPAD];
    __shared__ float Vs[64 * VPAD];
    __shared__ float Ps[64 * PPAD];

    const int tid = threadIdx.x, w = tid >> 5, lane = tid & 31;
    const int g = lane >> 2, t4 = lane & 3;
    const int wq = w * 16;
    const float scale = 0.17677669529663687f;  // 1/sqrt(32)
    const float* base = qkv + (size_t)b * L_ * 768;

#pragma unroll
    for (int i = 0; i < 4; i++) {
        int c = tid + i * 128;
        int row = c >> 3, ch = (c & 7) * 4;
        float4 v = *(const float4*)(base + (size_t)(q0 + row) * 768 + h * 32 + ch);
        uint4 u;
        u.x = f2tf32(v.x); u.y = f2tf32(v.y);
        u.z = f2tf32(v.z); u.w = f2tf32(v.w);
        *(uint4*)&Qs[row * QPAD + ch] = u;
    }
    __syncthreads();

    uint32_t qa[4][4];
#pragma unroll
    for (int kc = 0; kc < 4; kc++) {
        qa[kc][0] = __float_as_uint(Qs[(wq + g) * QPAD + kc * 8 + t4]);
        qa[kc][1] = __float_as_uint(Qs[(wq + g + 8) * QPAD + kc * 8 + t4]);
        qa[kc][2] = __float_as_uint(Qs[(wq + g) * QPAD + kc * 8 + t4 + 4]);
        qa[kc][3] = __float_as_uint(Qs[(wq + g + 8) * QPAD + kc * 8 + t4 + 4]);
    }

    float o[4][4];
#pragma unroll
    for (int nv = 0; nv < 4; nv++)
#pragma unroll
        for (int j = 0; j < 4; j++) o[nv][j] = 0.f;
    float m0 = -1e30f, m1 = -1e30f, ls0 = 0.f, ls1 = 0.f;

    for (int kt = 0; kt < len; kt += 64) {
        __syncthreads();
#pragma unroll
        for (int i = 0; i < 4; i++) {
            int c = tid + i * 128;
            int row = c >> 3, ch = (c & 7) * 4;
            const float* kp = base + (size_t)(kt + row) * 768 + 256 + h * 32 + ch;
            float4 kv = *(const float4*)kp;
            float4 vv = *(const float4*)(kp + 256);
            uint4 ku, vu;
            ku.x = f2tf32(kv.x); ku.y = f2tf32(kv.y);
            ku.z = f2tf32(kv.z); ku.w = f2tf32(kv.w);
            vu.x = f2tf32(vv.x); vu.y = f2tf32(vv.y);
            vu.z = f2tf32(vv.z); vu.w = f2tf32(vv.w);
            *(uint4*)&Ks[row * KPAD + ch] = ku;
            *(uint4*)&Vs[row * VPAD + ch] = vu;
        }
        __syncthreads();

        float sc[8][4];
#pragma unroll
        for (int n = 0; n < 8; n++) {
            sc[n][0] = sc[n][1] = sc[n][2] = sc[n][3] = 0.f;
#pragma unroll
            for (int kc = 0; kc < 4; kc++) {
                uint32_t bb[2];
                bb[0] = __float_as_uint(Ks[(n * 8 + g) * KPAD + kc * 8 + t4]);
                bb[1] = __float_as_uint(Ks[(n * 8 + g) * KPAD + kc * 8 + t4 + 4]);
                mma_tf32(sc[n], qa[kc], bb);
            }
        }

        float rmax0 = -1e30f, rmax1 = -1e30f;
#pragma unroll
        for (int n = 0; n < 8; n++) {
            int c0 = kt + n * 8 + 2 * t4;
            bool v0 = c0 < len, v1 = (c0 + 1) < len;
            sc[n][0] = v0 ? sc[n][0] * scale : -1e30f;
            sc[n][1] = v1 ? sc[n][1] * scale : -1e30f;
            sc[n][2] = v0 ? sc[n][2] * scale : -1e30f;
            sc[n][3] = v1 ? sc[n][3] * scale : -1e30f;
            rmax0 = fmaxf(rmax0, fmaxf(sc[n][0], sc[n][1]));
            rmax1 = fmaxf(rmax1, fmaxf(sc[n][2], sc[n][3]));
        }
        rmax0 = fmaxf(rmax0, __shfl_xor_sync(0xffffffffu, rmax0, 1));
        rmax0 = fmaxf(rmax0, __shfl_xor_sync(0xffffffffu, rmax0, 2));
        rmax1 = fmaxf(rmax1, __shfl_xor_sync(0xffffffffu, rmax1, 1));
        rmax1 = fmaxf(rmax1, __shfl_xor_sync(0xffffffffu, rmax1, 2));

        float nm0 = fmaxf(m0, rmax0), nm1 = fmaxf(m1, rmax1);
        float cr0 = __expf(m0 - nm0), cr1 = __expf(m1 - nm1);
        ls0 *= cr0; ls1 *= cr1;
#pragma unroll
        for (int nv = 0; nv < 4; nv++) {
            o[nv][0] *= cr0; o[nv][1] *= cr0;
            o[nv][2] *= cr1; o[nv][3] *= cr1;
        }
        m0 = nm0; m1 = nm1;

#pragma unroll
        for (int n = 0; n < 8; n++) {
            float p0 = __expf(sc[n][0] - m0), p1 = __expf(sc[n][1] - m0);
            float p2 = __expf(sc[n][2] - m1), p3 = __expf(sc[n][3] - m1);
            ls0 += p0 + p1;
            ls1 += p2 + p3;
            float2 lo, hi;
            lo.x = __uint_as_float(f2tf32(p0)); lo.y = __uint_as_float(f2tf32(p1));
            hi.x = __uint_as_float(f2tf32(p2)); hi.y = __uint_as_float(f2tf32(p3));
            *(float2*)&Ps[(wq + g) * PPAD + n * 8 + 2 * t4] = lo;
            *(float2*)&Ps[(wq + g + 8) * PPAD + n * 8 + 2 * t4] = hi;
        }
        __syncwarp();

#pragma unroll
        for (int kc2 = 0; kc2 < 8; kc2++) {
            uint32_t pa[4];
            pa[0] = __float_as_uint(Ps[(wq + g) * PPAD + kc2 * 8 + t4]);
            pa[1] = __float_as_uint(Ps[(wq + g + 8) * PPAD + kc2 * 8 + t4]);
            pa[2] = __float_as_uint(Ps[(wq + g) * PPAD + kc2 * 8 + t4 + 4]);
            pa[3] = __float_as_uint(Ps[(wq + g + 8) * PPAD + kc2 * 8 + t4 + 4]);
#pragma unroll
            for (int nv = 0; nv < 4; nv++) {
                uint32_t vb[2];
                vb[0] = __float_as_uint(Vs[(kc2 * 8 + t4) * VPAD + nv * 8 + g]);
                vb[1] = __float_as_uint(Vs[(kc2 * 8 + t4 + 4) * VPAD + nv * 8 + g]);
                mma_tf32(o[nv], pa, vb);
            }
        }
        __syncwarp();
    }

    ls0 += __shfl_xor_sync(0xffffffffu, ls0, 1);
    ls0 += __shfl_xor_sync(0xffffffffu, ls0, 2);
    ls1 += __shfl_xor_sync(0xffffffffu, ls1, 1);
    ls1 += __shfl_xor_sync(0xffffffffu, ls1, 2);
    float i0 = 1.f / ls0, i1 = 1.f / ls1;

    const int r0 = q0 + wq + g;
    float* op0 = ao + (size_t)(b * L_ + r0) * D_ + h * 32;
    float* op1 = ao + (size_t)(b * L_ + r0 + 8) * D_ + h * 32;
#pragma unroll
    for (int nv = 0; nv < 4; nv++) {
        float2 lo, hi;
        lo.x = o[nv][0] * i0; lo.y = o[nv][1] * i0;
        hi.x = o[nv][2] * i1; hi.y = o[nv][3] * i1;
        *(float2*)(op0 + nv * 8 + 2 * t4) = lo;
        *(float2*)(op1 + nv * 8 + 2 * t4) = hi;
    }
}

// ---------------- readout ----------------
__global__ void graph_partial_kernel(const float* __restrict__ x,
                                     const int* __restrict__ lengths,
                                     float* __restrict__ red) {
    int chunk = blockIdx.x, b = blockIdx.y, d = threadIdx.x;
    int len = lengths[b];
    int l0 = chunk * 128;
    int l1 = min(l0 + 128, len);
    float s = 0.f;
    for (int l = l0; l < l1; l++) s += x[((size_t)b * L_ + l) * D_ + d];
    red[((size_t)b * 8 + chunk) * D_ + d] = s;
}

__global__ void graph_final_kernel(const float* __restrict__ red,
                                   const int* __restrict__ lengths,
                                   float* __restrict__ out) {
    int b = blockIdx.x, d = threadIdx.x;
    float s = 0.f;
#pragma unroll
    for (int c = 0; c < 8; c++) s += red[((size_t)b * 8 + c) * D_ + d];
    int cnt = lengths[b] > 1 ? lengths[b] : 1;
    out[b * D_ + d] = s / (float)cnt;
}

__global__ void node_out_kernel(const float* __restrict__ x,
                                const int* __restrict__ lengths,
                                float* __restrict__ out) {
    int row = blockIdx.x, d = threadIdx.x;
    int b = row >> 10, l = row & 1023;
    float v = (l < lengths[b]) ? x[(size_t)row * D_ + d] : 0.f;
    out[(size_t)row * D_ + d] = v;
}

// ---------------- launch ----------------
extern "C" void kernel_launch(void* const* d_in, const int* in_sizes, int n_in,
                              void* d_out, int out_size) {
    const int*   ut      = (const int*)d_in[0];
    const int*   lengths = (const int*)d_in[1];
    const float* emb     = (const float*)d_in[2];
    const float* wqkv    = (const float*)d_in[3];
    const float* bqkv    = (const float*)d_in[4];
    const float* wo      = (const float*)d_in[5];
    const float* bo      = (const float*)d_in[6];
    const float* wlin    = (const float*)d_in[7];
    const float* blin    = (const float*)d_in[8];
    float* out = (float*)d_out;

    float *x, *qkvb, *aob, *h1b, *redb;
    cudaGetSymbolAddress((void**)&x, g_x);
    cudaGetSymbolAddress((void**)&qkvb, g_qkv);
    cudaGetSymbolAddress((void**)&aob, g_ao);
    cudaGetSymbolAddress((void**)&h1b, g_h1);
    cudaGetSymbolAddress((void**)&redb, g_red);

    const int gemm_smem = 4 * TILE_F * (int)sizeof(float);  // 73728 B
    cudaFuncSetAttribute(gemm_tc_kernel,
                         cudaFuncAttributeMaxDynamicSharedMemorySize, gemm_smem);

    embed_kernel<<<M_, 256>>>(ut, emb, x);

    for (int i = 0; i < NL_; i++) {
        gemm_tc_kernel<<<dim3(768 / 128, M_ / 128), 256, gemm_smem>>>(
            x, wqkv + (size_t)i * 3 * D_ * D_, bqkv + (size_t)i * 3 * D_,
            nullptr, qkvb, lengths, 3 * D_, D_, 0);
        attn_tc_kernel<<<dim3(L_ / 64, H_, B_), 128>>>(qkvb, aob, lengths);
        gemm_tc_kernel<<<dim3(D_ / 128, M_ / 128), 256, gemm_smem>>>(
            aob, wo + (size_t)i * D_ * D_, bo + (size_t)i * D_,
            x, h1b, lengths, D_, D_, 0);
        gemm_tc_kernel<<<dim3(D_ / 128, M_ / 128), 256, gemm_smem>>>(
            h1b, wlin + (size_t)i * D_ * D_, blin + (size_t)i * D_,
            nullptr, x, lengths, D_, D_, (i < NL_ - 1) ? 1 : 0);
    }

    graph_partial_kernel<<<dim3(8, B_), 256>>>(x, lengths, redb);
    graph_final_kernel<<<B_, 256>>>(redb, lengths, out);
    node_out_kernel<<<M_, 256>>>(x, lengths, out + B_ * D_);
}

// round 5
// speedup vs baseline: 1.0355x; 1.0355x over previous
#include <cuda_runtime.h>
#include <math.h>
#include <stdint.h>

#define B_  16
#define L_  1024
#define D_  256
#define H_  8
#define NL_ 3
#define M_  (B_ * L_)   // 16384

// ---------------- scratch ----------------
__device__ float g_x[M_ * D_];
__device__ float g_qkv[M_ * 3 * D_];
__device__ float g_ao[M_ * D_];
__device__ float g_h1[M_ * D_];
__device__ float g_red[B_ * 8 * D_];

// ---------------- helpers ----------------
__device__ __forceinline__ uint32_t f2tf32(float x) {
    uint32_t u;
    asm("cvt.rna.tf32.f32 %0, %1;" : "=r"(u) : "f"(x));
    return u;
}

__device__ __forceinline__ void mma_tf32(float c[4], const uint32_t a[4],
                                         const uint32_t b[2]) {
    asm volatile(
        "mma.sync.aligned.m16n8k8.row.col.f32.tf32.tf32.f32 "
        "{%0,%1,%2,%3}, {%4,%5,%6,%7}, {%8,%9}, {%0,%1,%2,%3};\n"
        : "+f"(c[0]), "+f"(c[1]), "+f"(c[2]), "+f"(c[3])
        : "r"(a[0]), "r"(a[1]), "r"(a[2]), "r"(a[3]), "r"(b[0]), "r"(b[1]));
}

__device__ __forceinline__ void cp16(uint32_t smem_dst, const void* gsrc) {
    asm volatile("cp.async.cg.shared.global [%0], [%1], 16;\n"
                 :: "r"(smem_dst), "l"(gsrc));
}
__device__ __forceinline__ void cp_commit() {
    asm volatile("cp.async.commit_group;\n");
}
__device__ __forceinline__ void cp_wait0() {
    asm volatile("cp.async.wait_group 0;\n");
}

// ---------------- embedding gather ----------------
__global__ void embed_kernel(const int* __restrict__ ut,
                             const float* __restrict__ emb,
                             float* __restrict__ x) {
    int row = blockIdx.x;
    int d = threadIdx.x;
    x[(size_t)row * D_ + d] = emb[(size_t)ut[row] * D_ + d];
}

// ---------------- tf32 tensor-core GEMM, cp.async double-buffered ------------
// C[M,N] = A[M,K] @ W[N,K]^T + bias (+res) (relu); ragged row-block early exit.
// BM=128, BN=64, BK=32; 256 threads = 8 warps (4 M x 2 N), warp tile 32x32.
#define GPAD 36
#define ATILE (128 * GPAD)
#define BTILE (64 * GPAD)
#define BUF_F (ATILE + BTILE)
__global__ void __launch_bounds__(256) gemm_tc_kernel(
    const float* __restrict__ A, const float* __restrict__ W,
    const float* __restrict__ bias, const float* __restrict__ res,
    float* __restrict__ C, const int* __restrict__ lengths,
    int N, int K, int doRelu) {
    const int row0 = blockIdx.y * 128;
    {
        int b = row0 >> 10, l0 = row0 & 1023;
        if (l0 >= lengths[b]) return;
    }
    extern __shared__ float smem[];

    const int tid = threadIdx.x;
    const int warp = tid >> 5, lane = tid & 31;
    const int g = lane >> 2, t4 = lane & 3;
    const int wm = (warp & 3) * 32;
    const int wn = (warp >> 2) * 32;
    const int col0 = blockIdx.x * 64;

    const int arow = tid >> 1, acol = (tid & 1) * 16;
    const int brow = tid >> 2, bcol = (tid & 3) * 8;

    uint32_t smem_u32 = (uint32_t)__cvta_generic_to_shared(smem);
    const float* agp = A + (size_t)(row0 + arow) * K + acol;
    const float* wgp = W + (size_t)(col0 + brow) * K + bcol;
    // per-thread smem destinations (byte addresses)
    const uint32_t adst = smem_u32 + (arow * GPAD + acol) * 4;
    const uint32_t bdst = smem_u32 + (ATILE + brow * GPAD + bcol) * 4;
    const uint32_t bufB = BUF_F * 4;  // byte stride between buffers

    float acc[2][4][4];
#pragma unroll
    for (int mi = 0; mi < 2; mi++)
#pragma unroll
        for (int ni = 0; ni < 4; ni++)
#pragma unroll
            for (int j = 0; j < 4; j++) acc[mi][ni][j] = 0.f;

    // prologue: issue tile 0
#pragma unroll
    for (int c = 0; c < 4; c++) cp16(adst + c * 16, agp + c * 4);
#pragma unroll
    for (int c = 0; c < 2; c++) cp16(bdst + c * 16, wgp + c * 4);
    cp_commit();

    const int niter = K >> 5;
    for (int it = 0; it < niter; it++) {
        const int cur = it & 1;
        cp_wait0();
        __syncthreads();

        if (it + 1 < niter) {   // issue next tile; overlaps with mma below
            const int kn = (it + 1) << 5;
            const uint32_t ad = adst + (cur ? 0u : bufB);
            const uint32_t bd = bdst + (cur ? 0u : bufB);
#pragma unroll
            for (int c = 0; c < 4; c++) cp16(ad + c * 16, agp + kn + c * 4);
#pragma unroll
            for (int c = 0; c < 2; c++) cp16(bd + c * 16, wgp + kn + c * 4);
            cp_commit();
        }

        const float* Ac = smem + cur * BUF_F;
        const float* Bc = Ac + ATILE;
#pragma unroll
        for (int ks = 0; ks < 4; ks++) {
            const int k0 = ks * 8;
            uint32_t a[2][4];
#pragma unroll
            for (int mi = 0; mi < 2; mi++) {
                int r = wm + mi * 16;
                a[mi][0] = f2tf32(Ac[(r + g) * GPAD + k0 + t4]);
                a[mi][1] = f2tf32(Ac[(r + g + 8) * GPAD + k0 + t4]);
                a[mi][2] = f2tf32(Ac[(r + g) * GPAD + k0 + t4 + 4]);
                a[mi][3] = f2tf32(Ac[(r + g + 8) * GPAD + k0 + t4 + 4]);
            }
#pragma unroll
            for (int ni = 0; ni < 4; ni++) {
                int c = wn + ni * 8;
                uint32_t bf[2];
                bf[0] = f2tf32(Bc[(c + g) * GPAD + k0 + t4]);
                bf[1] = f2tf32(Bc[(c + g) * GPAD + k0 + t4 + 4]);
                mma_tf32(acc[0][ni], a[0], bf);
                mma_tf32(acc[1][ni], a[1], bf);
            }
        }
        __syncthreads();
    }

    // ---- epilogue ----
#pragma unroll
    for (int ni = 0; ni < 4; ni++) {
        int c = col0 + wn + ni * 8 + 2 * t4;
        float b0 = bias[c], b1 = bias[c + 1];
#pragma unroll
        for (int mi = 0; mi < 2; mi++) {
#pragma unroll
            for (int half = 0; half < 2; half++) {
                int r = row0 + wm + mi * 16 + g + half * 8;
                float v0 = acc[mi][ni][half * 2 + 0] + b0;
                float v1 = acc[mi][ni][half * 2 + 1] + b1;
                if (res) {
                    float2 rr = *(const float2*)(res + (size_t)r * N + c);
                    v0 += rr.x; v1 += rr.y;
                }
                if (doRelu) { v0 = fmaxf(v0, 0.f); v1 = fmaxf(v1, 0.f); }
                float2 o; o.x = v0; o.y = v1;
                *(float2*)(C + (size_t)r * N + c) = o;
            }
        }
    }
}

// ---------------- tensor-core masked flash attention (tf32 mma, fp32 softmax) ---
#define QPAD 36
#define KPAD 36
#define VPAD 40
#define PPAD 72
__global__ void __launch_bounds__(128) attn_tc_kernel(
    const float* __restrict__ qkv, float* __restrict__ ao,
    const int* __restrict__ lengths) {
    const int b = blockIdx.z, h = blockIdx.y;
    const int len = lengths[b];
    const int q0 = blockIdx.x * 64;
    if (q0 >= len) return;

    __shared__ float Qs[64 * QPAD];
    __shared__ float Ks[64 * KPAD];
    __shared__ float Vs[64 * VPAD];
    __shared__ float Ps[64 * PPAD];

    const int tid = threadIdx.x, w = tid >> 5, lane = tid & 31;
    const int g = lane >> 2, t4 = lane & 3;
    const int wq = w * 16;
    const float scale = 0.17677669529663687f;  // 1/sqrt(32)
    const float* base = qkv + (size_t)b * L_ * 768;

#pragma unroll
    for (int i = 0; i < 4; i++) {
        int c = tid + i * 128;
        int row = c >> 3, ch = (c & 7) * 4;
        float4 v = *(const float4*)(base + (size_t)(q0 + row) * 768 + h * 32 + ch);
        uint4 u;
        u.x = f2tf32(v.x); u.y = f2tf32(v.y);
        u.z = f2tf32(v.z); u.w = f2tf32(v.w);
        *(uint4*)&Qs[row * QPAD + ch] = u;
    }
    __syncthreads();

    uint32_t qa[4][4];
#pragma unroll
    for (int kc = 0; kc < 4; kc++) {
        qa[kc][0] = __float_as_uint(Qs[(wq + g) * QPAD + kc * 8 + t4]);
        qa[kc][1] = __float_as_uint(Qs[(wq + g + 8) * QPAD + kc * 8 + t4]);
        qa[kc][2] = __float_as_uint(Qs[(wq + g) * QPAD + kc * 8 + t4 + 4]);
        qa[kc][3] = __float_as_uint(Qs[(wq + g + 8) * QPAD + kc * 8 + t4 + 4]);
    }

    float o[4][4];
#pragma unroll
    for (int nv = 0; nv < 4; nv++)
#pragma unroll
        for (int j = 0; j < 4; j++) o[nv][j] = 0.f;
    float m0 = -1e30f, m1 = -1e30f, ls0 = 0.f, ls1 = 0.f;

    for (int kt = 0; kt < len; kt += 64) {
        __syncthreads();
#pragma unroll
        for (int i = 0; i < 4; i++) {
            int c = tid + i * 128;
            int row = c >> 3, ch = (c & 7) * 4;
            const float* kp = base + (size_t)(kt + row) * 768 + 256 + h * 32 + ch;
            float4 kv = *(const float4*)kp;
            float4 vv = *(const float4*)(kp + 256);
            uint4 ku, vu;
            ku.x = f2tf32(kv.x); ku.y = f2tf32(kv.y);
            ku.z = f2tf32(kv.z); ku.w = f2tf32(kv.w);
            vu.x = f2tf32(vv.x); vu.y = f2tf32(vv.y);
            vu.z = f2tf32(vv.z); vu.w = f2tf32(vv.w);
            *(uint4*)&Ks[row * KPAD + ch] = ku;
            *(uint4*)&Vs[row * VPAD + ch] = vu;
        }
        __syncthreads();

        float sc[8][4];
#pragma unroll
        for (int n = 0; n < 8; n++) {
            sc[n][0] = sc[n][1] = sc[n][2] = sc[n][3] = 0.f;
#pragma unroll
            for (int kc = 0; kc < 4; kc++) {
                uint32_t bb[2];
                bb[0] = __float_as_uint(Ks[(n * 8 + g) * KPAD + kc * 8 + t4]);
                bb[1] = __float_as_uint(Ks[(n * 8 + g) * KPAD + kc * 8 + t4 + 4]);
                mma_tf32(sc[n], qa[kc], bb);
            }
        }

        float rmax0 = -1e30f, rmax1 = -1e30f;
#pragma unroll
        for (int n = 0; n < 8; n++) {
            int c0 = kt + n * 8 + 2 * t4;
            bool v0 = c0 < len, v1 = (c0 + 1) < len;
            sc[n][0] = v0 ? sc[n][0] * scale : -1e30f;
            sc[n][1] = v1 ? sc[n][1] * scale : -1e30f;
            sc[n][2] = v0 ? sc[n][2] * scale : -1e30f;
            sc[n][3] = v1 ? sc[n][3] * scale : -1e30f;
            rmax0 = fmaxf(rmax0, fmaxf(sc[n][0], sc[n][1]));
            rmax1 = fmaxf(rmax1, fmaxf(sc[n][2], sc[n][3]));
        }
        rmax0 = fmaxf(rmax0, __shfl_xor_sync(0xffffffffu, rmax0, 1));
        rmax0 = fmaxf(rmax0, __shfl_xor_sync(0xffffffffu, rmax0, 2));
        rmax1 = fmaxf(rmax1, __shfl_xor_sync(0xffffffffu, rmax1, 1));
        rmax1 = fmaxf(rmax1, __shfl_xor_sync(0xffffffffu, rmax1, 2));

        float nm0 = fmaxf(m0, rmax0), nm1 = fmaxf(m1, rmax1);
        float cr0 = __expf(m0 - nm0), cr1 = __expf(m1 - nm1);
        ls0 *= cr0; ls1 *= cr1;
#pragma unroll
        for (int nv = 0; nv < 4; nv++) {
            o[nv][0] *= cr0; o[nv][1] *= cr0;
            o[nv][2] *= cr1; o[nv][3] *= cr1;
        }
        m0 = nm0; m1 = nm1;

#pragma unroll
        for (int n = 0; n < 8; n++) {
            float p0 = __expf(sc[n][0] - m0), p1 = __expf(sc[n][1] - m0);
            float p2 = __expf(sc[n][2] - m1), p3 = __expf(sc[n][3] - m1);
            ls0 += p0 + p1;
            ls1 += p2 + p3;
            float2 lo, hi;
            lo.x = __uint_as_float(f2tf32(p0)); lo.y = __uint_as_float(f2tf32(p1));
            hi.x = __uint_as_float(f2tf32(p2)); hi.y = __uint_as_float(f2tf32(p3));
            *(float2*)&Ps[(wq + g) * PPAD + n * 8 + 2 * t4] = lo;
            *(float2*)&Ps[(wq + g + 8) * PPAD + n * 8 + 2 * t4] = hi;
        }
        __syncwarp();

#pragma unroll
        for (int kc2 = 0; kc2 < 8; kc2++) {
            uint32_t pa[4];
            pa[0] = __float_as_uint(Ps[(wq + g) * PPAD + kc2 * 8 + t4]);
            pa[1] = __float_as_uint(Ps[(wq + g + 8) * PPAD + kc2 * 8 + t4]);
            pa[2] = __float_as_uint(Ps[(wq + g) * PPAD + kc2 * 8 + t4 + 4]);
            pa[3] = __float_as_uint(Ps[(wq + g + 8) * PPAD + kc2 * 8 + t4 + 4]);
#pragma unroll
            for (int nv = 0; nv < 4; nv++) {
                uint32_t vb[2];
                vb[0] = __float_as_uint(Vs[(kc2 * 8 + t4) * VPAD + nv * 8 + g]);
                vb[1] = __float_as_uint(Vs[(kc2 * 8 + t4 + 4) * VPAD + nv * 8 + g]);
                mma_tf32(o[nv], pa, vb);
            }
        }
        __syncwarp();
    }

    ls0 += __shfl_xor_sync(0xffffffffu, ls0, 1);
    ls0 += __shfl_xor_sync(0xffffffffu, ls0, 2);
    ls1 += __shfl_xor_sync(0xffffffffu, ls1, 1);
    ls1 += __shfl_xor_sync(0xffffffffu, ls1, 2);
    float i0 = 1.f / ls0, i1 = 1.f / ls1;

    const int r0 = q0 + wq + g;
    float* op0 = ao + (size_t)(b * L_ + r0) * D_ + h * 32;
    float* op1 = ao + (size_t)(b * L_ + r0 + 8) * D_ + h * 32;
#pragma unroll
    for (int nv = 0; nv < 4; nv++) {
        float2 lo, hi;
        lo.x = o[nv][0] * i0; lo.y = o[nv][1] * i0;
        hi.x = o[nv][2] * i1; hi.y = o[nv][3] * i1;
        *(float2*)(op0 + nv * 8 + 2 * t4) = lo;
        *(float2*)(op1 + nv * 8 + 2 * t4) = hi;
    }
}

// ---------------- readout ----------------
__global__ void graph_partial_kernel(const float* __restrict__ x,
                                     const int* __restrict__ lengths,
                                     float* __restrict__ red) {
    int chunk = blockIdx.x, b = blockIdx.y, d = threadIdx.x;
    int len = lengths[b];
    int l0 = chunk * 128;
    int l1 = min(l0 + 128, len);
    float s = 0.f;
    for (int l = l0; l < l1; l++) s += x[((size_t)b * L_ + l) * D_ + d];
    red[((size_t)b * 8 + chunk) * D_ + d] = s;
}

__global__ void graph_final_kernel(const float* __restrict__ red,
                                   const int* __restrict__ lengths,
                                   float* __restrict__ out) {
    int b = blockIdx.x, d = threadIdx.x;
    float s = 0.f;
#pragma unroll
    for (int c = 0; c < 8; c++) s += red[((size_t)b * 8 + c) * D_ + d];
    int cnt = lengths[b] > 1 ? lengths[b] : 1;
    out[b * D_ + d] = s / (float)cnt;
}

__global__ void node_out_kernel(const float* __restrict__ x,
                                const int* __restrict__ lengths,
                                float* __restrict__ out) {
    int row = blockIdx.x, d = threadIdx.x;
    int b = row >> 10, l = row & 1023;
    float v = (l < lengths[b]) ? x[(size_t)row * D_ + d] : 0.f;
    out[(size_t)row * D_ + d] = v;
}

// ---------------- launch ----------------
extern "C" void kernel_launch(void* const* d_in, const int* in_sizes, int n_in,
                              void* d_out, int out_size) {
    const int*   ut      = (const int*)d_in[0];
    const int*   lengths = (const int*)d_in[1];
    const float* emb     = (const float*)d_in[2];
    const float* wqkv    = (const float*)d_in[3];
    const float* bqkv    = (const float*)d_in[4];
    const float* wo      = (const float*)d_in[5];
    const float* bo      = (const float*)d_in[6];
    const float* wlin    = (const float*)d_in[7];
    const float* blin    = (const float*)d_in[8];
    float* out = (float*)d_out;

    float *x, *qkvb, *aob, *h1b, *redb;
    cudaGetSymbolAddress((void**)&x, g_x);
    cudaGetSymbolAddress((void**)&qkvb, g_qkv);
    cudaGetSymbolAddress((void**)&aob, g_ao);
    cudaGetSymbolAddress((void**)&h1b, g_h1);
    cudaGetSymbolAddress((void**)&redb, g_red);

    const int gemm_smem = 2 * BUF_F * (int)sizeof(float);  // 55296 B
    cudaFuncSetAttribute(gemm_tc_kernel,
                         cudaFuncAttributeMaxDynamicSharedMemorySize, gemm_smem);

    embed_kernel<<<M_, 256>>>(ut, emb, x);

    for (int i = 0; i < NL_; i++) {
        gemm_tc_kernel<<<dim3(768 / 64, M_ / 128), 256, gemm_smem>>>(
            x, wqkv + (size_t)i * 3 * D_ * D_, bqkv + (size_t)i * 3 * D_,
            nullptr, qkvb, lengths, 3 * D_, D_, 0);
        attn_tc_kernel<<<dim3(L_ / 64, H_, B_), 128>>>(qkvb, aob, lengths);
        gemm_tc_kernel<<<dim3(D_ / 64, M_ / 128), 256, gemm_smem>>>(
            aob, wo + (size_t)i * D_ * D_, bo + (size_t)i * D_,
            x, h1b, lengths, D_, D_, 0);
        gemm_tc_kernel<<<dim3(D_ / 64, M_ / 128), 256, gemm_smem>>>(
            h1b, wlin + (size_t)i * D_ * D_, blin + (size_t)i * D_,
            nullptr, x, lengths, D_, D_, (i < NL_ - 1) ? 1 : 0);
    }

    graph_partial_kernel<<<dim3(8, B_), 256>>>(x, lengths, redb);
    graph_final_kernel<<<B_, 256>>>(redb, lengths, out);
    node_out_kernel<<<M_, 256>>>(x, lengths, out + B_ * D_);
}

// round 6
// speedup vs baseline: 1.1064x; 1.0685x over previous
#include <cuda_runtime.h>
#include <cuda_fp16.h>
#include <math.h>
#include <stdint.h>

#define B_  16
#define L_  1024
#define D_  256
#define H_  8
#define NL_ 3
#define M_  (B_ * L_)   // 16384

// ---------------- scratch ----------------
__device__ float g_x[M_ * D_];
__device__ float g_qkv[M_ * 3 * D_];
__device__ float g_ao[M_ * D_];
__device__ float g_h1[M_ * D_];
__device__ float g_red[B_ * 8 * D_];

// ---------------- helpers ----------------
__device__ __forceinline__ uint32_t f2tf32(float x) {
    uint32_t u;
    asm("cvt.rna.tf32.f32 %0, %1;" : "=r"(u) : "f"(x));
    return u;
}

__device__ __forceinline__ void mma_tf32(float c[4], const uint32_t a[4],
                                         const uint32_t b[2]) {
    asm volatile(
        "mma.sync.aligned.m16n8k8.row.col.f32.tf32.tf32.f32 "
        "{%0,%1,%2,%3}, {%4,%5,%6,%7}, {%8,%9}, {%0,%1,%2,%3};\n"
        : "+f"(c[0]), "+f"(c[1]), "+f"(c[2]), "+f"(c[3])
        : "r"(a[0]), "r"(a[1]), "r"(a[2]), "r"(a[3]), "r"(b[0]), "r"(b[1]));
}

__device__ __forceinline__ void mma_f16(float c[4], const uint32_t a[4],
                                        const uint32_t b[2]) {
    asm volatile(
        "mma.sync.aligned.m16n8k16.row.col.f32.f16.f16.f32 "
        "{%0,%1,%2,%3}, {%4,%5,%6,%7}, {%8,%9}, {%0,%1,%2,%3};\n"
        : "+f"(c[0]), "+f"(c[1]), "+f"(c[2]), "+f"(c[3])
        : "r"(a[0]), "r"(a[1]), "r"(a[2]), "r"(a[3]), "r"(b[0]), "r"(b[1]));
}

// ---------------- embedding gather ----------------
__global__ void embed_kernel(const int* __restrict__ ut,
                             const float* __restrict__ emb,
                             float* __restrict__ x) {
    int row = blockIdx.x;
    int d = threadIdx.x;
    x[(size_t)row * D_ + d] = emb[(size_t)ut[row] * D_ + d];
}

// ---------------- fp16 tensor-core GEMM (fp32 accumulate) --------------------
// C[M,N] = A[M,K] @ W[N,K]^T + bias (+res) (relu); ragged row-block early exit.
// BM=128, BN=64, BK=64; 256 threads = 8 warps (4 M x 2 N), warp tile 32x32
// via m16n8k16. smem rows padded to 72 halves -> conflict-free fragments.
#define KPH 72
__global__ void __launch_bounds__(256) gemm_tc_kernel(
    const float* __restrict__ A, const float* __restrict__ W,
    const float* __restrict__ bias, const float* __restrict__ res,
    float* __restrict__ C, const int* __restrict__ lengths,
    int N, int K, int doRelu) {
    const int row0 = blockIdx.y * 128;
    {
        int b = row0 >> 10, l0 = row0 & 1023;
        if (l0 >= lengths[b]) return;
    }
    __shared__ __half Ah[128 * KPH];
    __shared__ __half Bh[64 * KPH];

    const int tid = threadIdx.x;
    const int warp = tid >> 5, lane = tid & 31;
    const int g = lane >> 2, t4 = lane & 3;
    const int wm = (warp & 3) * 32;
    const int wn = (warp >> 2) * 32;
    const int col0 = blockIdx.x * 64;

    const int lrow = tid >> 2;           // 0..63
    const int lcol = (tid & 3) * 16;     // 0,16,32,48

    float acc[2][4][4];
#pragma unroll
    for (int mi = 0; mi < 2; mi++)
#pragma unroll
        for (int ni = 0; ni < 4; ni++)
#pragma unroll
            for (int j = 0; j < 4; j++) acc[mi][ni][j] = 0.f;

    const float* a0p = A + (size_t)(row0 + lrow) * K + lcol;
    const float* a1p = A + (size_t)(row0 + 64 + lrow) * K + lcol;
    const float* wp  = W + (size_t)(col0 + lrow) * K + lcol;

    for (int kt = 0; kt < K; kt += 64) {
        // ---- load 16 floats per source, convert to half ----
        float4 fa0[4], fa1[4], fw[4];
#pragma unroll
        for (int i = 0; i < 4; i++) {
            fa0[i] = *(const float4*)(a0p + kt + i * 4);
            fa1[i] = *(const float4*)(a1p + kt + i * 4);
            fw[i]  = *(const float4*)(wp + kt + i * 4);
        }
        __syncthreads();   // prior mma done reading smem
        __half2 h[8];
#pragma unroll
        for (int i = 0; i < 4; i++) {
            h[2 * i]     = __floats2half2_rn(fa0[i].x, fa0[i].y);
            h[2 * i + 1] = __floats2half2_rn(fa0[i].z, fa0[i].w);
        }
        *(uint4*)&Ah[lrow * KPH + lcol]     = *(uint4*)&h[0];
        *(uint4*)&Ah[lrow * KPH + lcol + 8] = *(uint4*)&h[4];
#pragma unroll
        for (int i = 0; i < 4; i++) {
            h[2 * i]     = __floats2half2_rn(fa1[i].x, fa1[i].y);
            h[2 * i + 1] = __floats2half2_rn(fa1[i].z, fa1[i].w);
        }
        *(uint4*)&Ah[(64 + lrow) * KPH + lcol]     = *(uint4*)&h[0];
        *(uint4*)&Ah[(64 + lrow) * KPH + lcol + 8] = *(uint4*)&h[4];
#pragma unroll
        for (int i = 0; i < 4; i++) {
            h[2 * i]     = __floats2half2_rn(fw[i].x, fw[i].y);
            h[2 * i + 1] = __floats2half2_rn(fw[i].z, fw[i].w);
        }
        *(uint4*)&Bh[lrow * KPH + lcol]     = *(uint4*)&h[0];
        *(uint4*)&Bh[lrow * KPH + lcol + 8] = *(uint4*)&h[4];
        __syncthreads();

        // ---- 4 k-steps of 16 ----
#pragma unroll
        for (int ks = 0; ks < 4; ks++) {
            const int k0 = ks * 16;
            uint32_t a[2][4];
#pragma unroll
            for (int mi = 0; mi < 2; mi++) {
                int r = wm + mi * 16;
                a[mi][0] = *(const uint32_t*)&Ah[(r + g) * KPH + k0 + 2 * t4];
                a[mi][1] = *(const uint32_t*)&Ah[(r + g + 8) * KPH + k0 + 2 * t4];
                a[mi][2] = *(const uint32_t*)&Ah[(r + g) * KPH + k0 + 2 * t4 + 8];
                a[mi][3] = *(const uint32_t*)&Ah[(r + g + 8) * KPH + k0 + 2 * t4 + 8];
            }
#pragma unroll
            for (int ni = 0; ni < 4; ni++) {
                int c = wn + ni * 8;
                uint32_t bf[2];
                bf[0] = *(const uint32_t*)&Bh[(c + g) * KPH + k0 + 2 * t4];
                bf[1] = *(const uint32_t*)&Bh[(c + g) * KPH + k0 + 2 * t4 + 8];
                mma_f16(acc[0][ni], a[0], bf);
                mma_f16(acc[1][ni], a[1], bf);
            }
        }
    }

    // ---- epilogue (c0,c1 -> row g cols 2t4..; c2,c3 -> row g+8) ----
#pragma unroll
    for (int ni = 0; ni < 4; ni++) {
        int c = col0 + wn + ni * 8 + 2 * t4;
        float b0 = bias[c], b1 = bias[c + 1];
#pragma unroll
        for (int mi = 0; mi < 2; mi++) {
#pragma unroll
            for (int half = 0; half < 2; half++) {
                int r = row0 + wm + mi * 16 + g + half * 8;
                float v0 = acc[mi][ni][half * 2 + 0] + b0;
                float v1 = acc[mi][ni][half * 2 + 1] + b1;
                if (res) {
                    float2 rr = *(const float2*)(res + (size_t)r * N + c);
                    v0 += rr.x; v1 += rr.y;
                }
                if (doRelu) { v0 = fmaxf(v0, 0.f); v1 = fmaxf(v1, 0.f); }
                float2 o; o.x = v0; o.y = v1;
                *(float2*)(C + (size_t)r * N + c) = o;
            }
        }
    }
}

// ---------------- tensor-core masked flash attention (tf32 mma, fp32 softmax) ---
#define QPAD 36
#define KPAD 36
#define VPAD 40
#define PPAD 72
__global__ void __launch_bounds__(128) attn_tc_kernel(
    const float* __restrict__ qkv, float* __restrict__ ao,
    const int* __restrict__ lengths) {
    const int b = blockIdx.z, h = blockIdx.y;
    const int len = lengths[b];
    const int q0 = blockIdx.x * 64;
    if (q0 >= len) return;

    __shared__ float Qs[64 * QPAD];
    __shared__ float Ks[64 * KPAD];
    __shared__ float Vs[64 * VPAD];
    __shared__ float Ps[64 * PPAD];

    const int tid = threadIdx.x, w = tid >> 5, lane = tid & 31;
    const int g = lane >> 2, t4 = lane & 3;
    const int wq = w * 16;
    const float scale = 0.17677669529663687f;  // 1/sqrt(32)
    const float* base = qkv + (size_t)b * L_ * 768;

#pragma unroll
    for (int i = 0; i < 4; i++) {
        int c = tid + i * 128;
        int row = c >> 3, ch = (c & 7) * 4;
        float4 v = *(const float4*)(base + (size_t)(q0 + row) * 768 + h * 32 + ch);
        uint4 u;
        u.x = f2tf32(v.x); u.y = f2tf32(v.y);
        u.z = f2tf32(v.z); u.w = f2tf32(v.w);
        *(uint4*)&Qs[row * QPAD + ch] = u;
    }
    __syncthreads();

    uint32_t qa[4][4];
#pragma unroll
    for (int kc = 0; kc < 4; kc++) {
        qa[kc][0] = __float_as_uint(Qs[(wq + g) * QPAD + kc * 8 + t4]);
        qa[kc][1] = __float_as_uint(Qs[(wq + g + 8) * QPAD + kc * 8 + t4]);
        qa[kc][2] = __float_as_uint(Qs[(wq + g) * QPAD + kc * 8 + t4 + 4]);
        qa[kc][3] = __float_as_uint(Qs[(wq + g + 8) * QPAD + kc * 8 + t4 + 4]);
    }

    float o[4][4];
#pragma unroll
    for (int nv = 0; nv < 4; nv++)
#pragma unroll
        for (int j = 0; j < 4; j++) o[nv][j] = 0.f;
    float m0 = -1e30f, m1 = -1e30f, ls0 = 0.f, ls1 = 0.f;

    for (int kt = 0; kt < len; kt += 64) {
        __syncthreads();
#pragma unroll
        for (int i = 0; i < 4; i++) {
            int c = tid + i * 128;
            int row = c >> 3, ch = (c & 7) * 4;
            const float* kp = base + (size_t)(kt + row) * 768 + 256 + h * 32 + ch;
            float4 kv = *(const float4*)kp;
            float4 vv = *(const float4*)(kp + 256);
            uint4 ku, vu;
            ku.x = f2tf32(kv.x); ku.y = f2tf32(kv.y);
            ku.z = f2tf32(kv.z); ku.w = f2tf32(kv.w);
            vu.x = f2tf32(vv.x); vu.y = f2tf32(vv.y);
            vu.z = f2tf32(vv.z); vu.w = f2tf32(vv.w);
            *(uint4*)&Ks[row * KPAD + ch] = ku;
            *(uint4*)&Vs[row * VPAD + ch] = vu;
        }
        __syncthreads();

        float sc[8][4];
#pragma unroll
        for (int n = 0; n < 8; n++) {
            sc[n][0] = sc[n][1] = sc[n][2] = sc[n][3] = 0.f;
#pragma unroll
            for (int kc = 0; kc < 4; kc++) {
                uint32_t bb[2];
                bb[0] = __float_as_uint(Ks[(n * 8 + g) * KPAD + kc * 8 + t4]);
                bb[1] = __float_as_uint(Ks[(n * 8 + g) * KPAD + kc * 8 + t4 + 4]);
                mma_tf32(sc[n], qa[kc], bb);
            }
        }

        float rmax0 = -1e30f, rmax1 = -1e30f;
#pragma unroll
        for (int n = 0; n < 8; n++) {
            int c0 = kt + n * 8 + 2 * t4;
            bool v0 = c0 < len, v1 = (c0 + 1) < len;
            sc[n][0] = v0 ? sc[n][0] * scale : -1e30f;
            sc[n][1] = v1 ? sc[n][1] * scale : -1e30f;
            sc[n][2] = v0 ? sc[n][2] * scale : -1e30f;
            sc[n][3] = v1 ? sc[n][3] * scale : -1e30f;
            rmax0 = fmaxf(rmax0, fmaxf(sc[n][0], sc[n][1]));
            rmax1 = fmaxf(rmax1, fmaxf(sc[n][2], sc[n][3]));
        }
        rmax0 = fmaxf(rmax0, __shfl_xor_sync(0xffffffffu, rmax0, 1));
        rmax0 = fmaxf(rmax0, __shfl_xor_sync(0xffffffffu, rmax0, 2));
        rmax1 = fmaxf(rmax1, __shfl_xor_sync(0xffffffffu, rmax1, 1));
        rmax1 = fmaxf(rmax1, __shfl_xor_sync(0xffffffffu, rmax1, 2));

        float nm0 = fmaxf(m0, rmax0), nm1 = fmaxf(m1, rmax1);
        float cr0 = __expf(m0 - nm0), cr1 = __expf(m1 - nm1);
        ls0 *= cr0; ls1 *= cr1;
#pragma unroll
        for (int nv = 0; nv < 4; nv++) {
            o[nv][0] *= cr0; o[nv][1] *= cr0;
            o[nv][2] *= cr1; o[nv][3] *= cr1;
        }
        m0 = nm0; m1 = nm1;

#pragma unroll
        for (int n = 0; n < 8; n++) {
            float p0 = __expf(sc[n][0] - m0), p1 = __expf(sc[n][1] - m0);
            float p2 = __expf(sc[n][2] - m1), p3 = __expf(sc[n][3] - m1);
            ls0 += p0 + p1;
            ls1 += p2 + p3;
            float2 lo, hi;
            lo.x = __uint_as_float(f2tf32(p0)); lo.y = __uint_as_float(f2tf32(p1));
            hi.x = __uint_as_float(f2tf32(p2)); hi.y = __uint_as_float(f2tf32(p3));
            *(float2*)&Ps[(wq + g) * PPAD + n * 8 + 2 * t4] = lo;
            *(float2*)&Ps[(wq + g + 8) * PPAD + n * 8 + 2 * t4] = hi;
        }
        __syncwarp();

#pragma unroll
        for (int kc2 = 0; kc2 < 8; kc2++) {
            uint32_t pa[4];
            pa[0] = __float_as_uint(Ps[(wq + g) * PPAD + kc2 * 8 + t4]);
            pa[1] = __float_as_uint(Ps[(wq + g + 8) * PPAD + kc2 * 8 + t4]);
            pa[2] = __float_as_uint(Ps[(wq + g) * PPAD + kc2 * 8 + t4 + 4]);
            pa[3] = __float_as_uint(Ps[(wq + g + 8) * PPAD + kc2 * 8 + t4 + 4]);
#pragma unroll
            for (int nv = 0; nv < 4; nv++) {
                uint32_t vb[2];
                vb[0] = __float_as_uint(Vs[(kc2 * 8 + t4) * VPAD + nv * 8 + g]);
                vb[1] = __float_as_uint(Vs[(kc2 * 8 + t4 + 4) * VPAD + nv * 8 + g]);
                mma_tf32(o[nv], pa, vb);
            }
        }
        __syncwarp();
    }

    ls0 += __shfl_xor_sync(0xffffffffu, ls0, 1);
    ls0 += __shfl_xor_sync(0xffffffffu, ls0, 2);
    ls1 += __shfl_xor_sync(0xffffffffu, ls1, 1);
    ls1 += __shfl_xor_sync(0xffffffffu, ls1, 2);
    float i0 = 1.f / ls0, i1 = 1.f / ls1;

    const int r0 = q0 + wq + g;
    float* op0 = ao + (size_t)(b * L_ + r0) * D_ + h * 32;
    float* op1 = ao + (size_t)(b * L_ + r0 + 8) * D_ + h * 32;
#pragma unroll
    for (int nv = 0; nv < 4; nv++) {
        float2 lo, hi;
        lo.x = o[nv][0] * i0; lo.y = o[nv][1] * i0;
        hi.x = o[nv][2] * i1; hi.y = o[nv][3] * i1;
        *(float2*)(op0 + nv * 8 + 2 * t4) = lo;
        *(float2*)(op1 + nv * 8 + 2 * t4) = hi;
    }
}

// ---------------- readout ----------------
__global__ void graph_partial_kernel(const float* __restrict__ x,
                                     const int* __restrict__ lengths,
                                     float* __restrict__ red) {
    int chunk = blockIdx.x, b = blockIdx.y, d = threadIdx.x;
    int len = lengths[b];
    int l0 = chunk * 128;
    int l1 = min(l0 + 128, len);
    float s = 0.f;
    for (int l = l0; l < l1; l++) s += x[((size_t)b * L_ + l) * D_ + d];
    red[((size_t)b * 8 + chunk) * D_ + d] = s;
}

__global__ void graph_final_kernel(const float* __restrict__ red,
                                   const int* __restrict__ lengths,
                                   float* __restrict__ out) {
    int b = blockIdx.x, d = threadIdx.x;
    float s = 0.f;
#pragma unroll
    for (int c = 0; c < 8; c++) s += red[((size_t)b * 8 + c) * D_ + d];
    int cnt = lengths[b] > 1 ? lengths[b] : 1;
    out[b * D_ + d] = s / (float)cnt;
}

__global__ void node_out_kernel(const float* __restrict__ x,
                                const int* __restrict__ lengths,
                                float* __restrict__ out) {
    int row = blockIdx.x, d = threadIdx.x;
    int b = row >> 10, l = row & 1023;
    float v = (l < lengths[b]) ? x[(size_t)row * D_ + d] : 0.f;
    out[(size_t)row * D_ + d] = v;
}

// ---------------- launch ----------------
extern "C" void kernel_launch(void* const* d_in, const int* in_sizes, int n_in,
                              void* d_out, int out_size) {
    const int*   ut      = (const int*)d_in[0];
    const int*   lengths = (const int*)d_in[1];
    const float* emb     = (const float*)d_in[2];
    const float* wqkv    = (const float*)d_in[3];
    const float* bqkv    = (const float*)d_in[4];
    const float* wo      = (const float*)d_in[5];
    const float* bo      = (const float*)d_in[6];
    const float* wlin    = (const float*)d_in[7];
    const float* blin    = (const float*)d_in[8];
    float* out = (float*)d_out;

    float *x, *qkvb, *aob, *h1b, *redb;
    cudaGetSymbolAddress((void**)&x, g_x);
    cudaGetSymbolAddress((void**)&qkvb, g_qkv);
    cudaGetSymbolAddress((void**)&aob, g_ao);
    cudaGetSymbolAddress((void**)&h1b, g_h1);
    cudaGetSymbolAddress((void**)&redb, g_red);

    embed_kernel<<<M_, 256>>>(ut, emb, x);

    for (int i = 0; i < NL_; i++) {
        gemm_tc_kernel<<<dim3(768 / 64, M_ / 128), 256>>>(
            x, wqkv + (size_t)i * 3 * D_ * D_, bqkv + (size_t)i * 3 * D_,
            nullptr, qkvb, lengths, 3 * D_, D_, 0);
        attn_tc_kernel<<<dim3(L_ / 64, H_, B_), 128>>>(qkvb, aob, lengths);
        gemm_tc_kernel<<<dim3(D_ / 64, M_ / 128), 256>>>(
            aob, wo + (size_t)i * D_ * D_, bo + (size_t)i * D_,
            x, h1b, lengths, D_, D_, 0);
        gemm_tc_kernel<<<dim3(D_ / 64, M_ / 128), 256>>>(
            h1b, wlin + (size_t)i * D_ * D_, blin + (size_t)i * D_,
            nullptr, x, lengths, D_, D_, (i < NL_ - 1) ? 1 : 0);
    }

    graph_partial_kernel<<<dim3(8, B_), 256>>>(x, lengths, redb);
    graph_final_kernel<<<B_, 256>>>(redb, lengths, out);
    node_out_kernel<<<M_, 256>>>(x, lengths, out + B_ * D_);
}

// round 8
// speedup vs baseline: 1.1870x; 1.0729x over previous
#include <cuda_runtime.h>
#include <cuda_fp16.h>
#include <math.h>
#include <stdint.h>

#define B_  16
#define L_  1024
#define D_  256
#define H_  8
#define NL_ 3
#define M_  (B_ * L_)   // 16384

// ---------------- scratch ----------------
__device__ float g_x[M_ * D_];
__device__ float g_qkv[M_ * 3 * D_];
__device__ float g_ao[M_ * D_];
__device__ float g_h1[M_ * D_];
__device__ float g_red[B_ * 8 * D_];

// compacted work lists (built by sched_kernel each call; deterministic)
__device__ int g_nrb;            // # active 128-row blocks
__device__ int g_rowblk[128];    // global row0 of each active block
__device__ int g_nab;            // # active 64-query attention tiles
__device__ int g_attnblk[256];   // (graph<<16) | qtile

// ---------------- helpers ----------------
__device__ __forceinline__ uint32_t f2tf32(float x) {
    uint32_t u;
    asm("cvt.rna.tf32.f32 %0, %1;" : "=r"(u) : "f"(x));
    return u;
}

__device__ __forceinline__ void mma_tf32(float c[4], const uint32_t a[4],
                                         const uint32_t b[2]) {
    asm volatile(
        "mma.sync.aligned.m16n8k8.row.col.f32.tf32.tf32.f32 "
        "{%0,%1,%2,%3}, {%4,%5,%6,%7}, {%8,%9}, {%0,%1,%2,%3};\n"
        : "+f"(c[0]), "+f"(c[1]), "+f"(c[2]), "+f"(c[3])
        : "r"(a[0]), "r"(a[1]), "r"(a[2]), "r"(a[3]), "r"(b[0]), "r"(b[1]));
}

__device__ __forceinline__ void mma_f16(float c[4], const uint32_t a[4],
                                        const uint32_t b[2]) {
    asm volatile(
        "mma.sync.aligned.m16n8k16.row.col.f32.f16.f16.f32 "
        "{%0,%1,%2,%3}, {%4,%5,%6,%7}, {%8,%9}, {%0,%1,%2,%3};\n"
        : "+f"(c[0]), "+f"(c[1]), "+f"(c[2]), "+f"(c[3])
        : "r"(a[0]), "r"(a[1]), "r"(a[2]), "r"(a[3]), "r"(b[0]), "r"(b[1]));
}

// ---------------- scheduler: compact + longest-first ordering ----------------
__global__ void sched_kernel(const int* __restrict__ lengths) {
    if (threadIdx.x != 0) return;
    int idx[B_], len[B_];
#pragma unroll
    for (int b = 0; b < B_; b++) { idx[b] = b; len[b] = lengths[b]; }
    // selection sort: descending len, ties by ascending index (deterministic)
#pragma unroll
    for (int i = 0; i < B_ - 1; i++) {
        int best = i;
        for (int j = i + 1; j < B_; j++)
            if (len[j] > len[best] || (len[j] == len[best] && idx[j] < idx[best]))
                best = j;
        int tl = len[i]; len[i] = len[best]; len[best] = tl;
        int ti = idx[i]; idx[i] = idx[best]; idx[best] = ti;
    }
    int n = 0, m = 0;
    for (int i = 0; i < B_; i++) {
        int b = idx[i], ln = len[i];
        int nrb = (ln + 127) >> 7;
        for (int r = 0; r < nrb; r++) g_rowblk[n++] = b * L_ + r * 128;
        int nab = (ln + 63) >> 6;
        for (int q = 0; q < nab; q++) g_attnblk[m++] = (b << 16) | q;
    }
    g_nrb = n;
    g_nab = m;
}

// ---------------- embedding gather ----------------
__global__ void embed_kernel(const int* __restrict__ ut,
                             const float* __restrict__ emb,
                             float* __restrict__ x) {
    int row = blockIdx.x;
    int d = threadIdx.x;
    x[(size_t)row * D_ + d] = emb[(size_t)ut[row] * D_ + d];
}

// ---------------- fp16 tensor-core GEMM (fp32 accumulate), compacted --------
// C[M,N] = A[M,K] @ W[N,K]^T + bias (+res) (relu).
// BM=128, BN=64, BK=64; 256 threads = 8 warps (4 M x 2 N), warp tile 32x32.
#define KPH 72
__global__ void __launch_bounds__(256) gemm_tc_kernel(
    const float* __restrict__ A, const float* __restrict__ W,
    const float* __restrict__ bias, const float* __restrict__ res,
    float* __restrict__ C, int N, int K, int doRelu) {
    if ((int)blockIdx.y >= g_nrb) return;   // contiguous dead tail
    const int row0 = g_rowblk[blockIdx.y];

    __shared__ __half Ah[128 * KPH];
    __shared__ __half Bh[64 * KPH];

    const int tid = threadIdx.x;
    const int warp = tid >> 5, lane = tid & 31;
    const int g = lane >> 2, t4 = lane & 3;
    const int wm = (warp & 3) * 32;
    const int wn = (warp >> 2) * 32;
    const int col0 = blockIdx.x * 64;

    const int lrow = tid >> 2;           // 0..63
    const int lcol = (tid & 3) * 16;     // 0,16,32,48

    float acc[2][4][4];
#pragma unroll
    for (int mi = 0; mi < 2; mi++)
#pragma unroll
        for (int ni = 0; ni < 4; ni++)
#pragma unroll
            for (int j = 0; j < 4; j++) acc[mi][ni][j] = 0.f;

    const float* a0p = A + (size_t)(row0 + lrow) * K + lcol;
    const float* a1p = A + (size_t)(row0 + 64 + lrow) * K + lcol;
    const float* wp  = W + (size_t)(col0 + lrow) * K + lcol;

    for (int kt = 0; kt < K; kt += 64) {
        float4 fa0[4], fa1[4], fw[4];
#pragma unroll
        for (int i = 0; i < 4; i++) {
            fa0[i] = *(const float4*)(a0p + kt + i * 4);
            fa1[i] = *(const float4*)(a1p + kt + i * 4);
            fw[i]  = *(const float4*)(wp + kt + i * 4);
        }
        __syncthreads();   // prior mma done reading smem
        __half2 h[8];
#pragma unroll
        for (int i = 0; i < 4; i++) {
            h[2 * i]     = __floats2half2_rn(fa0[i].x, fa0[i].y);
            h[2 * i + 1] = __floats2half2_rn(fa0[i].z, fa0[i].w);
        }
        *(uint4*)&Ah[lrow * KPH + lcol]     = *(uint4*)&h[0];
        *(uint4*)&Ah[lrow * KPH + lcol + 8] = *(uint4*)&h[4];
#pragma unroll
        for (int i = 0; i < 4; i++) {
            h[2 * i]     = __floats2half2_rn(fa1[i].x, fa1[i].y);
            h[2 * i + 1] = __floats2half2_rn(fa1[i].z, fa1[i].w);
        }
        *(uint4*)&Ah[(64 + lrow) * KPH + lcol]     = *(uint4*)&h[0];
        *(uint4*)&Ah[(64 + lrow) * KPH + lcol + 8] = *(uint4*)&h[4];
#pragma unroll
        for (int i = 0; i < 4; i++) {
            h[2 * i]     = __floats2half2_rn(fw[i].x, fw[i].y);
            h[2 * i + 1] = __floats2half2_rn(fw[i].z, fw[i].w);
        }
        *(uint4*)&Bh[lrow * KPH + lcol]     = *(uint4*)&h[0];
        *(uint4*)&Bh[lrow * KPH + lcol + 8] = *(uint4*)&h[4];
        __syncthreads();

#pragma unroll
        for (int ks = 0; ks < 4; ks++) {
            const int k0 = ks * 16;
            uint32_t a[2][4];
#pragma unroll
            for (int mi = 0; mi < 2; mi++) {
                int r = wm + mi * 16;
                a[mi][0] = *(const uint32_t*)&Ah[(r + g) * KPH + k0 + 2 * t4];
                a[mi][1] = *(const uint32_t*)&Ah[(r + g + 8) * KPH + k0 + 2 * t4];
                a[mi][2] = *(const uint32_t*)&Ah[(r + g) * KPH + k0 + 2 * t4 + 8];
                a[mi][3] = *(const uint32_t*)&Ah[(r + g + 8) * KPH + k0 + 2 * t4 + 8];
            }
#pragma unroll
            for (int ni = 0; ni < 4; ni++) {
                int c = wn + ni * 8;
                uint32_t bf[2];
                bf[0] = *(const uint32_t*)&Bh[(c + g) * KPH + k0 + 2 * t4];
                bf[1] = *(const uint32_t*)&Bh[(c + g) * KPH + k0 + 2 * t4 + 8];
                mma_f16(acc[0][ni], a[0], bf);
                mma_f16(acc[1][ni], a[1], bf);
            }
        }
    }

#pragma unroll
    for (int ni = 0; ni < 4; ni++) {
        int c = col0 + wn + ni * 8 + 2 * t4;
        float b0 = bias[c], b1 = bias[c + 1];
#pragma unroll
        for (int mi = 0; mi < 2; mi++) {
#pragma unroll
            for (int half = 0; half < 2; half++) {
                int r = row0 + wm + mi * 16 + g + half * 8;
                float v0 = acc[mi][ni][half * 2 + 0] + b0;
                float v1 = acc[mi][ni][half * 2 + 1] + b1;
                if (res) {
                    float2 rr = *(const float2*)(res + (size_t)r * N + c);
                    v0 += rr.x; v1 += rr.y;
                }
                if (doRelu) { v0 = fmaxf(v0, 0.f); v1 = fmaxf(v1, 0.f); }
                float2 o; o.x = v0; o.y = v1;
                *(float2*)(C + (size_t)r * N + c) = o;
            }
        }
    }
}

// ---------------- tensor-core masked flash attention (tf32 mma), compacted ---
// grid (H, 256): blockIdx.x = head, blockIdx.y indexes g_attnblk (max 256).
#define QPAD 36
#define KPAD 36
#define VPAD 40
#define PPAD 72
__global__ void __launch_bounds__(128) attn_tc_kernel(
    const float* __restrict__ qkv, float* __restrict__ ao,
    const int* __restrict__ lengths) {
    if ((int)blockIdx.y >= g_nab) return;   // contiguous dead tail
    const int packed = g_attnblk[blockIdx.y];
    const int b = packed >> 16;
    const int q0 = (packed & 0xffff) * 64;
    const int h = blockIdx.x;
    const int len = lengths[b];

    __shared__ float Qs[64 * QPAD];
    __shared__ float Ks[64 * KPAD];
    __shared__ float Vs[64 * VPAD];
    __shared__ float Ps[64 * PPAD];

    const int tid = threadIdx.x, w = tid >> 5, lane = tid & 31;
    const int g = lane >> 2, t4 = lane & 3;
    const int wq = w * 16;
    const float scale = 0.17677669529663687f;  // 1/sqrt(32)
    const float* base = qkv + (size_t)b * L_ * 768;

#pragma unroll
    for (int i = 0; i < 4; i++) {
        int c = tid + i * 128;
        int row = c >> 3, ch = (c & 7) * 4;
        float4 v = *(const float4*)(base + (size_t)(q0 + row) * 768 + h * 32 + ch);
        uint4 u;
        u.x = f2tf32(v.x); u.y = f2tf32(v.y);
        u.z = f2tf32(v.z); u.w = f2tf32(v.w);
        *(uint4*)&Qs[row * QPAD + ch] = u;
    }
    __syncthreads();

    uint32_t qa[4][4];
#pragma unroll
    for (int kc = 0; kc < 4; kc++) {
        qa[kc][0] = __float_as_uint(Qs[(wq + g) * QPAD + kc * 8 + t4]);
        qa[kc][1] = __float_as_uint(Qs[(wq + g + 8) * QPAD + kc * 8 + t4]);
        qa[kc][2] = __float_as_uint(Qs[(wq + g) * QPAD + kc * 8 + t4 + 4]);
        qa[kc][3] = __float_as_uint(Qs[(wq + g + 8) * QPAD + kc * 8 + t4 + 4]);
    }

    float o[4][4];
#pragma unroll
    for (int nv = 0; nv < 4; nv++)
#pragma unroll
        for (int j = 0; j < 4; j++) o[nv][j] = 0.f;
    float m0 = -1e30f, m1 = -1e30f, ls0 = 0.f, ls1 = 0.f;

    for (int kt = 0; kt < len; kt += 64) {
        __syncthreads();
#pragma unroll
        for (int i = 0; i < 4; i++) {
            int c = tid + i * 128;
            int row = c >> 3, ch = (c & 7) * 4;
            const float* kp = base + (size_t)(kt + row) * 768 + 256 + h * 32 + ch;
            float4 kv = *(const float4*)kp;
            float4 vv = *(const float4*)(kp + 256);
            uint4 ku, vu;
            ku.x = f2tf32(kv.x); ku.y = f2tf32(kv.y);
            ku.z = f2tf32(kv.z); ku.w = f2tf32(kv.w);
            vu.x = f2tf32(vv.x); vu.y = f2tf32(vv.y);
            vu.z = f2tf32(vv.z); vu.w = f2tf32(vv.w);
            *(uint4*)&Ks[row * KPAD + ch] = ku;
            *(uint4*)&Vs[row * VPAD + ch] = vu;
        }
        __syncthreads();

        float sc[8][4];
#pragma unroll
        for (int n = 0; n < 8; n++) {
            sc[n][0] = sc[n][1] = sc[n][2] = sc[n][3] = 0.f;
#pragma unroll
            for (int kc = 0; kc < 4; kc++) {
                uint32_t bb[2];
                bb[0] = __float_as_uint(Ks[(n * 8 + g) * KPAD + kc * 8 + t4]);
                bb[1] = __float_as_uint(Ks[(n * 8 + g) * KPAD + kc * 8 + t4 + 4]);
                mma_tf32(sc[n], qa[kc], bb);
            }
        }

        float rmax0 = -1e30f, rmax1 = -1e30f;
#pragma unroll
        for (int n = 0; n < 8; n++) {
            int c0 = kt + n * 8 + 2 * t4;
            bool v0 = c0 < len, v1 = (c0 + 1) < len;
            sc[n][0] = v0 ? sc[n][0] * scale : -1e30f;
            sc[n][1] = v1 ? sc[n][1] * scale : -1e30f;
            sc[n][2] = v0 ? sc[n][2] * scale : -1e30f;
            sc[n][3] = v1 ? sc[n][3] * scale : -1e30f;
            rmax0 = fmaxf(rmax0, fmaxf(sc[n][0], sc[n][1]));
            rmax1 = fmaxf(rmax1, fmaxf(sc[n][2], sc[n][3]));
        }
        rmax0 = fmaxf(rmax0, __shfl_xor_sync(0xffffffffu, rmax0, 1));
        rmax0 = fmaxf(rmax0, __shfl_xor_sync(0xffffffffu, rmax0, 2));
        rmax1 = fmaxf(rmax1, __shfl_xor_sync(0xffffffffu, rmax1, 1));
        rmax1 = fmaxf(rmax1, __shfl_xor_sync(0xffffffffu, rmax1, 2));

        float nm0 = fmaxf(m0, rmax0), nm1 = fmaxf(m1, rmax1);
        float cr0 = __expf(m0 - nm0), cr1 = __expf(m1 - nm1);
        ls0 *= cr0; ls1 *= cr1;
#pragma unroll
        for (int nv = 0; nv < 4; nv++) {
            o[nv][0] *= cr0; o[nv][1] *= cr0;
            o[nv][2] *= cr1; o[nv][3] *= cr1;
        }
        m0 = nm0; m1 = nm1;

#pragma unroll
        for (int n = 0; n < 8; n++) {
            float p0 = __expf(sc[n][0] - m0), p1 = __expf(sc[n][1] - m0);
            float p2 = __expf(sc[n][2] - m1), p3 = __expf(sc[n][3] - m1);
            ls0 += p0 + p1;
            ls1 += p2 + p3;
            float2 lo, hi;
            lo.x = __uint_as_float(f2tf32(p0)); lo.y = __uint_as_float(f2tf32(p1));
            hi.x = __uint_as_float(f2tf32(p2)); hi.y = __uint_as_float(f2tf32(p3));
            *(float2*)&Ps[(wq + g) * PPAD + n * 8 + 2 * t4] = lo;
            *(float2*)&Ps[(wq + g + 8) * PPAD + n * 8 + 2 * t4] = hi;
        }
        __syncwarp();

#pragma unroll
        for (int kc2 = 0; kc2 < 8; kc2++) {
            uint32_t pa[4];
            pa[0] = __float_as_uint(Ps[(wq + g) * PPAD + kc2 * 8 + t4]);
            pa[1] = __float_as_uint(Ps[(wq + g + 8) * PPAD + kc2 * 8 + t4]);
            pa[2] = __float_as_uint(Ps[(wq + g) * PPAD + kc2 * 8 + t4 + 4]);
            pa[3] = __float_as_uint(Ps[(wq + g + 8) * PPAD + kc2 * 8 + t4 + 4]);
#pragma unroll
            for (int nv = 0; nv < 4; nv++) {
                uint32_t vb[2];
                vb[0] = __float_as_uint(Vs[(kc2 * 8 + t4) * VPAD + nv * 8 + g]);
                vb[1] = __float_as_uint(Vs[(kc2 * 8 + t4 + 4) * VPAD + nv * 8 + g]);
                mma_tf32(o[nv], pa, vb);
            }
        }
        __syncwarp();
    }

    ls0 += __shfl_xor_sync(0xffffffffu, ls0, 1);
    ls0 += __shfl_xor_sync(0xffffffffu, ls0, 2);
    ls1 += __shfl_xor_sync(0xffffffffu, ls1, 1);
    ls1 += __shfl_xor_sync(0xffffffffu, ls1, 2);
    float i0 = 1.f / ls0, i1 = 1.f / ls1;

    const int r0 = q0 + wq + g;
    float* op0 = ao + (size_t)(b * L_ + r0) * D_ + h * 32;
    float* op1 = ao + (size_t)(b * L_ + r0 + 8) * D_ + h * 32;
#pragma unroll
    for (int nv = 0; nv < 4; nv++) {
        float2 lo, hi;
        lo.x = o[nv][0] * i0; lo.y = o[nv][1] * i0;
        hi.x = o[nv][2] * i1; hi.y = o[nv][3] * i1;
        *(float2*)(op0 + nv * 8 + 2 * t4) = lo;
        *(float2*)(op1 + nv * 8 + 2 * t4) = hi;
    }
}

// ---------------- readout ----------------
__global__ void graph_partial_kernel(const float* __restrict__ x,
                                     const int* __restrict__ lengths,
                                     float* __restrict__ red) {
    int chunk = blockIdx.x, b = blockIdx.y, d = threadIdx.x;
    int len = lengths[b];
    int l0 = chunk * 128;
    int l1 = min(l0 + 128, len);
    float s = 0.f;
    for (int l = l0; l < l1; l++) s += x[((size_t)b * L_ + l) * D_ + d];
    red[((size_t)b * 8 + chunk) * D_ + d] = s;
}

__global__ void graph_final_kernel(const float* __restrict__ red,
                                   const int* __restrict__ lengths,
                                   float* __restrict__ out) {
    int b = blockIdx.x, d = threadIdx.x;
    float s = 0.f;
#pragma unroll
    for (int c = 0; c < 8; c++) s += red[((size_t)b * 8 + c) * D_ + d];
    int cnt = lengths[b] > 1 ? lengths[b] : 1;
    out[b * D_ + d] = s / (float)cnt;
}

__global__ void node_out_kernel(const float* __restrict__ x,
                                const int* __restrict__ lengths,
                                float* __restrict__ out) {
    int row = blockIdx.x, d = threadIdx.x;
    int b = row >> 10, l = row & 1023;
    float v = (l < lengths[b]) ? x[(size_t)row * D_ + d] : 0.f;
    out[(size_t)row * D_ + d] = v;
}

// ---------------- launch ----------------
extern "C" void kernel_launch(void* const* d_in, const int* in_sizes, int n_in,
                              void* d_out, int out_size) {
    const int*   ut      = (const int*)d_in[0];
    const int*   lengths = (const int*)d_in[1];
    const float* emb     = (const float*)d_in[2];
    const float* wqkv    = (const float*)d_in[3];
    const float* bqkv    = (const float*)d_in[4];
    const float* wo      = (const float*)d_in[5];
    const float* bo      = (const float*)d_in[6];
    const float* wlin    = (const float*)d_in[7];
    const float* blin    = (const float*)d_in[8];
    float* out = (float*)d_out;

    float *x, *qkvb, *aob, *h1b, *redb;
    cudaGetSymbolAddress((void**)&x, g_x);
    cudaGetSymbolAddress((void**)&qkvb, g_qkv);
    cudaGetSymbolAddress((void**)&aob, g_ao);
    cudaGetSymbolAddress((void**)&h1b, g_h1);
    cudaGetSymbolAddress((void**)&redb, g_red);

    sched_kernel<<<1, 32>>>(lengths);
    embed_kernel<<<M_, 256>>>(ut, emb, x);

    for (int i = 0; i < NL_; i++) {
        gemm_tc_kernel<<<dim3(768 / 64, M_ / 128), 256>>>(
            x, wqkv + (size_t)i * 3 * D_ * D_, bqkv + (size_t)i * 3 * D_,
            nullptr, qkvb, 3 * D_, D_, 0);
        attn_tc_kernel<<<dim3(H_, B_ * L_ / 64), 128>>>(qkvb, aob, lengths);
        gemm_tc_kernel<<<dim3(D_ / 64, M_ / 128), 256>>>(
            aob, wo + (size_t)i * D_ * D_, bo + (size_t)i * D_,
            x, h1b, D_, D_, 0);
        gemm_tc_kernel<<<dim3(D_ / 64, M_ / 128), 256>>>(
            h1b, wlin + (size_t)i * D_ * D_, blin + (size_t)i * D_,
            nullptr, x, D_, D_, (i < NL_ - 1) ? 1 : 0);
    }

    graph_partial_kernel<<<dim3(8, B_), 256>>>(x, lengths, redb);
    graph_final_kernel<<<B_, 256>>>(redb, lengths, out);
    node_out_kernel<<<M_, 256>>>(x, lengths, out + B_ * D_);
}

// round 9
// speedup vs baseline: 1.2522x; 1.0549x over previous
#include <cuda_runtime.h>
#include <cuda_fp16.h>
#include <math.h>
#include <stdint.h>

#define B_  16
#define L_  1024
#define D_  256
#define H_  8
#define NL_ 3
#define M_  (B_ * L_)   // 16384

// ---------------- scratch ----------------
__device__ float g_x[M_ * D_];
__device__ float g_qkv[M_ * 3 * D_];
__device__ float g_ao[M_ * D_];
__device__ float g_h1[M_ * D_];
__device__ float g_red[B_ * 8 * D_];

// compacted work lists (built by sched_kernel each call; deterministic)
__device__ int g_nrb;
__device__ int g_rowblk[128];
__device__ int g_nab;
__device__ int g_attnblk[256];

// ---------------- helpers ----------------
__device__ __forceinline__ uint32_t f2tf32(float x) {
    uint32_t u;
    asm("cvt.rna.tf32.f32 %0, %1;" : "=r"(u) : "f"(x));
    return u;
}

__device__ __forceinline__ void mma_tf32(float c[4], const uint32_t a[4],
                                         const uint32_t b[2]) {
    asm volatile(
        "mma.sync.aligned.m16n8k8.row.col.f32.tf32.tf32.f32 "
        "{%0,%1,%2,%3}, {%4,%5,%6,%7}, {%8,%9}, {%0,%1,%2,%3};\n"
        : "+f"(c[0]), "+f"(c[1]), "+f"(c[2]), "+f"(c[3])
        : "r"(a[0]), "r"(a[1]), "r"(a[2]), "r"(a[3]), "r"(b[0]), "r"(b[1]));
}

__device__ __forceinline__ void mma_f16(float c[4], const uint32_t a[4],
                                        const uint32_t b[2]) {
    asm volatile(
        "mma.sync.aligned.m16n8k16.row.col.f32.f16.f16.f32 "
        "{%0,%1,%2,%3}, {%4,%5,%6,%7}, {%8,%9}, {%0,%1,%2,%3};\n"
        : "+f"(c[0]), "+f"(c[1]), "+f"(c[2]), "+f"(c[3])
        : "r"(a[0]), "r"(a[1]), "r"(a[2]), "r"(a[3]), "r"(b[0]), "r"(b[1]));
}

// ---------------- scheduler ----------------
__global__ void sched_kernel(const int* __restrict__ lengths) {
    if (threadIdx.x != 0) return;
    int idx[B_], len[B_];
#pragma unroll
    for (int b = 0; b < B_; b++) { idx[b] = b; len[b] = lengths[b]; }
#pragma unroll
    for (int i = 0; i < B_ - 1; i++) {
        int best = i;
        for (int j = i + 1; j < B_; j++)
            if (len[j] > len[best] || (len[j] == len[best] && idx[j] < idx[best]))
                best = j;
        int tl = len[i]; len[i] = len[best]; len[best] = tl;
        int ti = idx[i]; idx[i] = idx[best]; idx[best] = ti;
    }
    int n = 0, m = 0;
    for (int i = 0; i < B_; i++) {
        int b = idx[i], ln = len[i];
        int nrb = (ln + 127) >> 7;
        for (int r = 0; r < nrb; r++) g_rowblk[n++] = b * L_ + r * 128;
        int nab = (ln + 63) >> 6;
        for (int q = 0; q < nab; q++) g_attnblk[m++] = (b << 16) | q;
    }
    g_nrb = n;
    g_nab = m;
}

// ---------------- embedding gather ----------------
__global__ void embed_kernel(const int* __restrict__ ut,
                             const float* __restrict__ emb,
                             float* __restrict__ x) {
    int row = blockIdx.x;
    int d = threadIdx.x;
    x[(size_t)row * D_ + d] = emb[(size_t)ut[row] * D_ + d];
}

// ---------------- fp16 tensor-core GEMM (fp32 accumulate), compacted --------
#define KPH 72
__global__ void __launch_bounds__(256) gemm_tc_kernel(
    const float* __restrict__ A, const float* __restrict__ W,
    const float* __restrict__ bias, const float* __restrict__ res,
    float* __restrict__ C, int N, int K, int doRelu) {
    if ((int)blockIdx.y >= g_nrb) return;
    const int row0 = g_rowblk[blockIdx.y];

    __shared__ __half Ah[128 * KPH];
    __shared__ __half Bh[64 * KPH];

    const int tid = threadIdx.x;
    const int warp = tid >> 5, lane = tid & 31;
    const int g = lane >> 2, t4 = lane & 3;
    const int wm = (warp & 3) * 32;
    const int wn = (warp >> 2) * 32;
    const int col0 = blockIdx.x * 64;

    const int lrow = tid >> 2;
    const int lcol = (tid & 3) * 16;

    float acc[2][4][4];
#pragma unroll
    for (int mi = 0; mi < 2; mi++)
#pragma unroll
        for (int ni = 0; ni < 4; ni++)
#pragma unroll
            for (int j = 0; j < 4; j++) acc[mi][ni][j] = 0.f;

    const float* a0p = A + (size_t)(row0 + lrow) * K + lcol;
    const float* a1p = A + (size_t)(row0 + 64 + lrow) * K + lcol;
    const float* wp  = W + (size_t)(col0 + lrow) * K + lcol;

    for (int kt = 0; kt < K; kt += 64) {
        float4 fa0[4], fa1[4], fw[4];
#pragma unroll
        for (int i = 0; i < 4; i++) {
            fa0[i] = *(const float4*)(a0p + kt + i * 4);
            fa1[i] = *(const float4*)(a1p + kt + i * 4);
            fw[i]  = *(const float4*)(wp + kt + i * 4);
        }
        __syncthreads();
        __half2 h[8];
#pragma unroll
        for (int i = 0; i < 4; i++) {
            h[2 * i]     = __floats2half2_rn(fa0[i].x, fa0[i].y);
            h[2 * i + 1] = __floats2half2_rn(fa0[i].z, fa0[i].w);
        }
        *(uint4*)&Ah[lrow * KPH + lcol]     = *(uint4*)&h[0];
        *(uint4*)&Ah[lrow * KPH + lcol + 8] = *(uint4*)&h[4];
#pragma unroll
        for (int i = 0; i < 4; i++) {
            h[2 * i]     = __floats2half2_rn(fa1[i].x, fa1[i].y);
            h[2 * i + 1] = __floats2half2_rn(fa1[i].z, fa1[i].w);
        }
        *(uint4*)&Ah[(64 + lrow) * KPH + lcol]     = *(uint4*)&h[0];
        *(uint4*)&Ah[(64 + lrow) * KPH + lcol + 8] = *(uint4*)&h[4];
#pragma unroll
        for (int i = 0; i < 4; i++) {
            h[2 * i]     = __floats2half2_rn(fw[i].x, fw[i].y);
            h[2 * i + 1] = __floats2half2_rn(fw[i].z, fw[i].w);
        }
        *(uint4*)&Bh[lrow * KPH + lcol]     = *(uint4*)&h[0];
        *(uint4*)&Bh[lrow * KPH + lcol + 8] = *(uint4*)&h[4];
        __syncthreads();

#pragma unroll
        for (int ks = 0; ks < 4; ks++) {
            const int k0 = ks * 16;
            uint32_t a[2][4];
#pragma unroll
            for (int mi = 0; mi < 2; mi++) {
                int r = wm + mi * 16;
                a[mi][0] = *(const uint32_t*)&Ah[(r + g) * KPH + k0 + 2 * t4];
                a[mi][1] = *(const uint32_t*)&Ah[(r + g + 8) * KPH + k0 + 2 * t4];
                a[mi][2] = *(const uint32_t*)&Ah[(r + g) * KPH + k0 + 2 * t4 + 8];
                a[mi][3] = *(const uint32_t*)&Ah[(r + g + 8) * KPH + k0 + 2 * t4 + 8];
            }
#pragma unroll
            for (int ni = 0; ni < 4; ni++) {
                int c = wn + ni * 8;
                uint32_t bf[2];
                bf[0] = *(const uint32_t*)&Bh[(c + g) * KPH + k0 + 2 * t4];
                bf[1] = *(const uint32_t*)&Bh[(c + g) * KPH + k0 + 2 * t4 + 8];
                mma_f16(acc[0][ni], a[0], bf);
                mma_f16(acc[1][ni], a[1], bf);
            }
        }
    }

#pragma unroll
    for (int ni = 0; ni < 4; ni++) {
        int c = col0 + wn + ni * 8 + 2 * t4;
        float b0 = bias[c], b1 = bias[c + 1];
#pragma unroll
        for (int mi = 0; mi < 2; mi++) {
#pragma unroll
            for (int half = 0; half < 2; half++) {
                int r = row0 + wm + mi * 16 + g + half * 8;
                float v0 = acc[mi][ni][half * 2 + 0] + b0;
                float v1 = acc[mi][ni][half * 2 + 1] + b1;
                if (res) {
                    float2 rr = *(const float2*)(res + (size_t)r * N + c);
                    v0 += rr.x; v1 += rr.y;
                }
                if (doRelu) { v0 = fmaxf(v0, 0.f); v1 = fmaxf(v1, 0.f); }
                float2 o; o.x = v0; o.y = v1;
                *(float2*)(C + (size_t)r * N + c) = o;
            }
        }
    }
}

// ---------------- attention: f16 QK^T, tf32 PV, tail-split masking ----------
#define QPH2 40   // halves per row (20 words -> conflict-free fragments)
#define VPAD 40
#define PPAD 72
__global__ void __launch_bounds__(128) attn_tc_kernel(
    const float* __restrict__ qkv, float* __restrict__ ao,
    const int* __restrict__ lengths) {
    if ((int)blockIdx.y >= g_nab) return;
    const int packed = g_attnblk[blockIdx.y];
    const int b = packed >> 16;
    const int q0 = (packed & 0xffff) * 64;
    const int h = blockIdx.x;
    const int len = lengths[b];

    __shared__ __half Qh[64 * QPH2];
    __shared__ __half Kh[64 * QPH2];
    __shared__ float Vs[64 * VPAD];
    __shared__ float Ps[64 * PPAD];

    const int tid = threadIdx.x, w = tid >> 5, lane = tid & 31;
    const int g = lane >> 2, t4 = lane & 3;
    const int wq = w * 16;
    const float scale = 0.17677669529663687f;  // 1/sqrt(32)
    const float* base = qkv + (size_t)b * L_ * 768;

    // ---- load Q tile (64 x 32) as half ----
#pragma unroll
    for (int i = 0; i < 4; i++) {
        int c = tid + i * 128;
        int row = c >> 3, ch = (c & 7) * 4;
        float4 v = *(const float4*)(base + (size_t)(q0 + row) * 768 + h * 32 + ch);
        __half2 h0 = __floats2half2_rn(v.x, v.y);
        __half2 h1 = __floats2half2_rn(v.z, v.w);
        uint2 u; u.x = *(uint32_t*)&h0; u.y = *(uint32_t*)&h1;
        *(uint2*)&Qh[row * QPH2 + ch] = u;
    }
    __syncthreads();

    // ---- Q A-fragments (f16 m16n8k16), register-resident ----
    uint32_t qa[2][4];
#pragma unroll
    for (int kc = 0; kc < 2; kc++) {
        qa[kc][0] = *(const uint32_t*)&Qh[(wq + g) * QPH2 + kc * 16 + 2 * t4];
        qa[kc][1] = *(const uint32_t*)&Qh[(wq + g + 8) * QPH2 + kc * 16 + 2 * t4];
        qa[kc][2] = *(const uint32_t*)&Qh[(wq + g) * QPH2 + kc * 16 + 2 * t4 + 8];
        qa[kc][3] = *(const uint32_t*)&Qh[(wq + g + 8) * QPH2 + kc * 16 + 2 * t4 + 8];
    }

    float o[4][4];
#pragma unroll
    for (int nv = 0; nv < 4; nv++)
#pragma unroll
        for (int j = 0; j < 4; j++) o[nv][j] = 0.f;
    float m0 = -1e30f, m1 = -1e30f, ls0 = 0.f, ls1 = 0.f;

    for (int kt = 0; kt < len; kt += 64) {
        const bool tailTile = (kt + 64 > len);
        __syncthreads();
        // ---- load K (half) and V (tf32) tiles ----
#pragma unroll
        for (int i = 0; i < 4; i++) {
            int c = tid + i * 128;
            int row = c >> 3, ch = (c & 7) * 4;
            const float* kp = base + (size_t)(kt + row) * 768 + 256 + h * 32 + ch;
            float4 kv = *(const float4*)kp;
            float4 vv = *(const float4*)(kp + 256);
            __half2 h0 = __floats2half2_rn(kv.x, kv.y);
            __half2 h1 = __floats2half2_rn(kv.z, kv.w);
            uint2 ku; ku.x = *(uint32_t*)&h0; ku.y = *(uint32_t*)&h1;
            *(uint2*)&Kh[row * QPH2 + ch] = ku;
            uint4 vu;
            vu.x = f2tf32(vv.x); vu.y = f2tf32(vv.y);
            vu.z = f2tf32(vv.z); vu.w = f2tf32(vv.w);
            *(uint4*)&Vs[row * VPAD + ch] = vu;
        }
        __syncthreads();

        // ---- S = Q @ K^T (f16): 8 n-tiles x 2 k-steps ----
        float sc[8][4];
#pragma unroll
        for (int n = 0; n < 8; n++) {
            sc[n][0] = sc[n][1] = sc[n][2] = sc[n][3] = 0.f;
#pragma unroll
            for (int kc = 0; kc < 2; kc++) {
                uint32_t bb[2];
                bb[0] = *(const uint32_t*)&Kh[(n * 8 + g) * QPH2 + kc * 16 + 2 * t4];
                bb[1] = *(const uint32_t*)&Kh[(n * 8 + g) * QPH2 + kc * 16 + 2 * t4 + 8];
                mma_f16(sc[n], qa[kc], bb);
            }
        }

        // ---- scale (+ mask only on the tail tile) + row max ----
        float rmax0 = -1e30f, rmax1 = -1e30f;
        if (tailTile) {
#pragma unroll
            for (int n = 0; n < 8; n++) {
                int c0 = kt + n * 8 + 2 * t4;
                bool v0 = c0 < len, v1 = (c0 + 1) < len;
                sc[n][0] = v0 ? sc[n][0] * scale : -1e30f;
                sc[n][1] = v1 ? sc[n][1] * scale : -1e30f;
                sc[n][2] = v0 ? sc[n][2] * scale : -1e30f;
                sc[n][3] = v1 ? sc[n][3] * scale : -1e30f;
                rmax0 = fmaxf(rmax0, fmaxf(sc[n][0], sc[n][1]));
                rmax1 = fmaxf(rmax1, fmaxf(sc[n][2], sc[n][3]));
            }
        } else {
#pragma unroll
            for (int n = 0; n < 8; n++) {
                sc[n][0] *= scale; sc[n][1] *= scale;
                sc[n][2] *= scale; sc[n][3] *= scale;
                rmax0 = fmaxf(rmax0, fmaxf(sc[n][0], sc[n][1]));
                rmax1 = fmaxf(rmax1, fmaxf(sc[n][2], sc[n][3]));
            }
        }
        rmax0 = fmaxf(rmax0, __shfl_xor_sync(0xffffffffu, rmax0, 1));
        rmax0 = fmaxf(rmax0, __shfl_xor_sync(0xffffffffu, rmax0, 2));
        rmax1 = fmaxf(rmax1, __shfl_xor_sync(0xffffffffu, rmax1, 1));
        rmax1 = fmaxf(rmax1, __shfl_xor_sync(0xffffffffu, rmax1, 2));

        float nm0 = fmaxf(m0, rmax0), nm1 = fmaxf(m1, rmax1);
        float cr0 = __expf(m0 - nm0), cr1 = __expf(m1 - nm1);
        ls0 *= cr0; ls1 *= cr1;
#pragma unroll
        for (int nv = 0; nv < 4; nv++) {
            o[nv][0] *= cr0; o[nv][1] *= cr0;
            o[nv][2] *= cr1; o[nv][3] *= cr1;
        }
        m0 = nm0; m1 = nm1;

        // ---- exp -> P (tf32) into per-warp smem slab ----
#pragma unroll
        for (int n = 0; n < 8; n++) {
            float p0 = __expf(sc[n][0] - m0), p1 = __expf(sc[n][1] - m0);
            float p2 = __expf(sc[n][2] - m1), p3 = __expf(sc[n][3] - m1);
            ls0 += p0 + p1;
            ls1 += p2 + p3;
            float2 lo, hi;
            lo.x = __uint_as_float(f2tf32(p0)); lo.y = __uint_as_float(f2tf32(p1));
            hi.x = __uint_as_float(f2tf32(p2)); hi.y = __uint_as_float(f2tf32(p3));
            *(float2*)&Ps[(wq + g) * PPAD + n * 8 + 2 * t4] = lo;
            *(float2*)&Ps[(wq + g + 8) * PPAD + n * 8 + 2 * t4] = hi;
        }
        __syncwarp();

        // ---- O += P @ V (tf32): 8 k-chunks x 4 n-tiles ----
#pragma unroll
        for (int kc2 = 0; kc2 < 8; kc2++) {
            uint32_t pa[4];
            pa[0] = __float_as_uint(Ps[(wq + g) * PPAD + kc2 * 8 + t4]);
            pa[1] = __float_as_uint(Ps[(wq + g + 8) * PPAD + kc2 * 8 + t4]);
            pa[2] = __float_as_uint(Ps[(wq + g) * PPAD + kc2 * 8 + t4 + 4]);
            pa[3] = __float_as_uint(Ps[(wq + g + 8) * PPAD + kc2 * 8 + t4 + 4]);
#pragma unroll
            for (int nv = 0; nv < 4; nv++) {
                uint32_t vb[2];
                vb[0] = __float_as_uint(Vs[(kc2 * 8 + t4) * VPAD + nv * 8 + g]);
                vb[1] = __float_as_uint(Vs[(kc2 * 8 + t4 + 4) * VPAD + nv * 8 + g]);
                mma_tf32(o[nv], pa, vb);
            }
        }
        __syncwarp();
    }

    ls0 += __shfl_xor_sync(0xffffffffu, ls0, 1);
    ls0 += __shfl_xor_sync(0xffffffffu, ls0, 2);
    ls1 += __shfl_xor_sync(0xffffffffu, ls1, 1);
    ls1 += __shfl_xor_sync(0xffffffffu, ls1, 2);
    float i0 = 1.f / ls0, i1 = 1.f / ls1;

    const int r0 = q0 + wq + g;
    float* op0 = ao + (size_t)(b * L_ + r0) * D_ + h * 32;
    float* op1 = ao + (size_t)(b * L_ + r0 + 8) * D_ + h * 32;
#pragma unroll
    for (int nv = 0; nv < 4; nv++) {
        float2 lo, hi;
        lo.x = o[nv][0] * i0; lo.y = o[nv][1] * i0;
        hi.x = o[nv][2] * i1; hi.y = o[nv][3] * i1;
        *(float2*)(op0 + nv * 8 + 2 * t4) = lo;
        *(float2*)(op1 + nv * 8 + 2 * t4) = hi;
    }
}

// ---------------- readout ----------------
__global__ void graph_partial_kernel(const float* __restrict__ x,
                                     const int* __restrict__ lengths,
                                     float* __restrict__ red) {
    int chunk = blockIdx.x, b = blockIdx.y, d = threadIdx.x;
    int len = lengths[b];
    int l0 = chunk * 128;
    int l1 = min(l0 + 128, len);
    float s = 0.f;
    for (int l = l0; l < l1; l++) s += x[((size_t)b * L_ + l) * D_ + d];
    red[((size_t)b * 8 + chunk) * D_ + d] = s;
}

__global__ void graph_final_kernel(const float* __restrict__ red,
                                   const int* __restrict__ lengths,
                                   float* __restrict__ out) {
    int b = blockIdx.x, d = threadIdx.x;
    float s = 0.f;
#pragma unroll
    for (int c = 0; c < 8; c++) s += red[((size_t)b * 8 + c) * D_ + d];
    int cnt = lengths[b] > 1 ? lengths[b] : 1;
    out[b * D_ + d] = s / (float)cnt;
}

__global__ void node_out_kernel(const float* __restrict__ x,
                                const int* __restrict__ lengths,
                                float* __restrict__ out) {
    int row = blockIdx.x, d = threadIdx.x;
    int b = row >> 10, l = row & 1023;
    float v = (l < lengths[b]) ? x[(size_t)row * D_ + d] : 0.f;
    out[(size_t)row * D_ + d] = v;
}

// ---------------- launch ----------------
extern "C" void kernel_launch(void* const* d_in, const int* in_sizes, int n_in,
                              void* d_out, int out_size) {
    const int*   ut      = (const int*)d_in[0];
    const int*   lengths = (const int*)d_in[1];
    const float* emb     = (const float*)d_in[2];
    const float* wqkv    = (const float*)d_in[3];
    const float* bqkv    = (const float*)d_in[4];
    const float* wo      = (const float*)d_in[5];
    const float* bo      = (const float*)d_in[6];
    const float* wlin    = (const float*)d_in[7];
    const float* blin    = (const float*)d_in[8];
    float* out = (float*)d_out;

    float *x, *qkvb, *aob, *h1b, *redb;
    cudaGetSymbolAddress((void**)&x, g_x);
    cudaGetSymbolAddress((void**)&qkvb, g_qkv);
    cudaGetSymbolAddress((void**)&aob, g_ao);
    cudaGetSymbolAddress((void**)&h1b, g_h1);
    cudaGetSymbolAddress((void**)&redb, g_red);

    sched_kernel<<<1, 32>>>(lengths);
    embed_kernel<<<M_, 256>>>(ut, emb, x);

    for (int i = 0; i < NL_; i++) {
        gemm_tc_kernel<<<dim3(768 / 64, M_ / 128), 256>>>(
            x, wqkv + (size_t)i * 3 * D_ * D_, bqkv + (size_t)i * 3 * D_,
            nullptr, qkvb, 3 * D_, D_, 0);
        attn_tc_kernel<<<dim3(H_, B_ * L_ / 64), 128>>>(qkvb, aob, lengths);
        gemm_tc_kernel<<<dim3(D_ / 64, M_ / 128), 256>>>(
            aob, wo + (size_t)i * D_ * D_, bo + (size_t)i * D_,
            x, h1b, D_, D_, 0);
        gemm_tc_kernel<<<dim3(D_ / 64, M_ / 128), 256>>>(
            h1b, wlin + (size_t)i * D_ * D_, blin + (size_t)i * D_,
            nullptr, x, D_, D_, (i < NL_ - 1) ? 1 : 0);
    }

    graph_partial_kernel<<<dim3(8, B_), 256>>>(x, lengths, redb);
    graph_final_kernel<<<B_, 256>>>(redb, lengths, out);
    node_out_kernel<<<M_, 256>>>(x, lengths, out + B_ * D_);
}

// round 10
// speedup vs baseline: 1.4105x; 1.1264x over previous
#include <cuda_runtime.h>
#include <cuda_fp16.h>
#include <math.h>
#include <stdint.h>

#define B_  16
#define L_  1024
#define D_  256
#define H_  8
#define NL_ 3
#define M_  (B_ * L_)   // 16384

// ---------------- scratch ----------------
__device__ float g_x[M_ * D_];
__device__ float g_qkv[M_ * 3 * D_];
__device__ float g_ao[M_ * D_];
__device__ float g_h1[M_ * D_];
__device__ float g_red[B_ * 8 * D_];

// compacted work lists
__device__ int g_nrb;
__device__ int g_rowblk[128];
__device__ int g_nab;
__device__ int g_attnblk[256];

// ---------------- helpers ----------------
__device__ __forceinline__ void mma_f16(float c[4], const uint32_t a[4],
                                        const uint32_t b[2]) {
    asm volatile(
        "mma.sync.aligned.m16n8k16.row.col.f32.f16.f16.f32 "
        "{%0,%1,%2,%3}, {%4,%5,%6,%7}, {%8,%9}, {%0,%1,%2,%3};\n"
        : "+f"(c[0]), "+f"(c[1]), "+f"(c[2]), "+f"(c[3])
        : "r"(a[0]), "r"(a[1]), "r"(a[2]), "r"(a[3]), "r"(b[0]), "r"(b[1]));
}

__device__ __forceinline__ void ldm_x4(uint32_t& r0, uint32_t& r1,
                                       uint32_t& r2, uint32_t& r3,
                                       uint32_t addr) {
    asm volatile(
        "ldmatrix.sync.aligned.m8n8.x4.shared.b16 {%0,%1,%2,%3}, [%4];"
        : "=r"(r0), "=r"(r1), "=r"(r2), "=r"(r3) : "r"(addr));
}

__device__ __forceinline__ void ldm_x4_t(uint32_t& r0, uint32_t& r1,
                                         uint32_t& r2, uint32_t& r3,
                                         uint32_t addr) {
    asm volatile(
        "ldmatrix.sync.aligned.m8n8.x4.trans.shared.b16 {%0,%1,%2,%3}, [%4];"
        : "=r"(r0), "=r"(r1), "=r"(r2), "=r"(r3) : "r"(addr));
}

// ---------------- scheduler ----------------
__global__ void sched_kernel(const int* __restrict__ lengths) {
    if (threadIdx.x != 0) return;
    int idx[B_], len[B_];
#pragma unroll
    for (int b = 0; b < B_; b++) { idx[b] = b; len[b] = lengths[b]; }
#pragma unroll
    for (int i = 0; i < B_ - 1; i++) {
        int best = i;
        for (int j = i + 1; j < B_; j++)
            if (len[j] > len[best] || (len[j] == len[best] && idx[j] < idx[best]))
                best = j;
        int tl = len[i]; len[i] = len[best]; len[best] = tl;
        int ti = idx[i]; idx[i] = idx[best]; idx[best] = ti;
    }
    int n = 0, m = 0;
    for (int i = 0; i < B_; i++) {
        int b = idx[i], ln = len[i];
        int nrb = (ln + 127) >> 7;
        for (int r = 0; r < nrb; r++) g_rowblk[n++] = b * L_ + r * 128;
        int nab = (ln + 63) >> 6;
        for (int q = 0; q < nab; q++) g_attnblk[m++] = (b << 16) | q;
    }
    g_nrb = n;
    g_nab = m;
}

// ---------------- embedding gather ----------------
__global__ void embed_kernel(const int* __restrict__ ut,
                             const float* __restrict__ emb,
                             float* __restrict__ x) {
    int row = blockIdx.x;
    int d = threadIdx.x;
    x[(size_t)row * D_ + d] = emb[(size_t)ut[row] * D_ + d];
}

// ---------------- fp16 tensor-core GEMM (fp32 accumulate), compacted --------
#define KPH 72
__global__ void __launch_bounds__(256) gemm_tc_kernel(
    const float* __restrict__ A, const float* __restrict__ W,
    const float* __restrict__ bias, const float* __restrict__ res,
    float* __restrict__ C, int N, int K, int doRelu) {
    if ((int)blockIdx.y >= g_nrb) return;
    const int row0 = g_rowblk[blockIdx.y];

    __shared__ __half Ah[128 * KPH];
    __shared__ __half Bh[64 * KPH];

    const int tid = threadIdx.x;
    const int warp = tid >> 5, lane = tid & 31;
    const int g = lane >> 2, t4 = lane & 3;
    const int wm = (warp & 3) * 32;
    const int wn = (warp >> 2) * 32;
    const int col0 = blockIdx.x * 64;

    const int lrow = tid >> 2;
    const int lcol = (tid & 3) * 16;

    float acc[2][4][4];
#pragma unroll
    for (int mi = 0; mi < 2; mi++)
#pragma unroll
        for (int ni = 0; ni < 4; ni++)
#pragma unroll
            for (int j = 0; j < 4; j++) acc[mi][ni][j] = 0.f;

    const float* a0p = A + (size_t)(row0 + lrow) * K + lcol;
    const float* a1p = A + (size_t)(row0 + 64 + lrow) * K + lcol;
    const float* wp  = W + (size_t)(col0 + lrow) * K + lcol;

    for (int kt = 0; kt < K; kt += 64) {
        float4 fa0[4], fa1[4], fw[4];
#pragma unroll
        for (int i = 0; i < 4; i++) {
            fa0[i] = *(const float4*)(a0p + kt + i * 4);
            fa1[i] = *(const float4*)(a1p + kt + i * 4);
            fw[i]  = *(const float4*)(wp + kt + i * 4);
        }
        __syncthreads();
        __half2 h[8];
#pragma unroll
        for (int i = 0; i < 4; i++) {
            h[2 * i]     = __floats2half2_rn(fa0[i].x, fa0[i].y);
            h[2 * i + 1] = __floats2half2_rn(fa0[i].z, fa0[i].w);
        }
        *(uint4*)&Ah[lrow * KPH + lcol]     = *(uint4*)&h[0];
        *(uint4*)&Ah[lrow * KPH + lcol + 8] = *(uint4*)&h[4];
#pragma unroll
        for (int i = 0; i < 4; i++) {
            h[2 * i]     = __floats2half2_rn(fa1[i].x, fa1[i].y);
            h[2 * i + 1] = __floats2half2_rn(fa1[i].z, fa1[i].w);
        }
        *(uint4*)&Ah[(64 + lrow) * KPH + lcol]     = *(uint4*)&h[0];
        *(uint4*)&Ah[(64 + lrow) * KPH + lcol + 8] = *(uint4*)&h[4];
#pragma unroll
        for (int i = 0; i < 4; i++) {
            h[2 * i]     = __floats2half2_rn(fw[i].x, fw[i].y);
            h[2 * i + 1] = __floats2half2_rn(fw[i].z, fw[i].w);
        }
        *(uint4*)&Bh[lrow * KPH + lcol]     = *(uint4*)&h[0];
        *(uint4*)&Bh[lrow * KPH + lcol + 8] = *(uint4*)&h[4];
        __syncthreads();

#pragma unroll
        for (int ks = 0; ks < 4; ks++) {
            const int k0 = ks * 16;
            uint32_t a[2][4];
#pragma unroll
            for (int mi = 0; mi < 2; mi++) {
                int r = wm + mi * 16;
                a[mi][0] = *(const uint32_t*)&Ah[(r + g) * KPH + k0 + 2 * t4];
                a[mi][1] = *(const uint32_t*)&Ah[(r + g + 8) * KPH + k0 + 2 * t4];
                a[mi][2] = *(const uint32_t*)&Ah[(r + g) * KPH + k0 + 2 * t4 + 8];
                a[mi][3] = *(const uint32_t*)&Ah[(r + g + 8) * KPH + k0 + 2 * t4 + 8];
            }
#pragma unroll
            for (int ni = 0; ni < 4; ni++) {
                int c = wn + ni * 8;
                uint32_t bf[2];
                bf[0] = *(const uint32_t*)&Bh[(c + g) * KPH + k0 + 2 * t4];
                bf[1] = *(const uint32_t*)&Bh[(c + g) * KPH + k0 + 2 * t4 + 8];
                mma_f16(acc[0][ni], a[0], bf);
                mma_f16(acc[1][ni], a[1], bf);
            }
        }
    }

#pragma unroll
    for (int ni = 0; ni < 4; ni++) {
        int c = col0 + wn + ni * 8 + 2 * t4;
        float b0 = bias[c], b1 = bias[c + 1];
#pragma unroll
        for (int mi = 0; mi < 2; mi++) {
#pragma unroll
            for (int half = 0; half < 2; half++) {
                int r = row0 + wm + mi * 16 + g + half * 8;
                float v0 = acc[mi][ni][half * 2 + 0] + b0;
                float v1 = acc[mi][ni][half * 2 + 1] + b1;
                if (res) {
                    float2 rr = *(const float2*)(res + (size_t)r * N + c);
                    v0 += rr.x; v1 += rr.y;
                }
                if (doRelu) { v0 = fmaxf(v0, 0.f); v1 = fmaxf(v1, 0.f); }
                float2 o; o.x = v0; o.y = v1;
                *(float2*)(C + (size_t)r * N + c) = o;
            }
        }
    }
}

// ---------------- attention: all-f16 mma, ldmatrix fragments -----------------
#define KP 40    // halves per row for Qh/Kh/Vs (80B rows -> conflict-free ldm)
#define PP 72    // halves per row for Psh (144B rows)
__global__ void __launch_bounds__(128) attn_tc_kernel(
    const float* __restrict__ qkv, float* __restrict__ ao,
    const int* __restrict__ lengths) {
    if ((int)blockIdx.y >= g_nab) return;
    const int packed = g_attnblk[blockIdx.y];
    const int b = packed >> 16;
    const int q0 = (packed & 0xffff) * 64;
    const int h = blockIdx.x;
    const int len = lengths[b];

    __shared__ __half Qh[64 * KP];
    __shared__ __half Kh[64 * KP];
    __shared__ __half Vs[64 * KP];
    __shared__ __half Psh[64 * PP];

    const int tid = threadIdx.x, w = tid >> 5, lane = tid & 31;
    const int g = lane >> 2, t4 = lane & 3;
    const int gl = lane >> 3, lr = lane & 7;   // ldmatrix group / row
    const int wq = w * 16;
    const float scale = 0.17677669529663687f;  // 1/sqrt(32)
    const float* base = qkv + (size_t)b * L_ * 768;

    const uint32_t khB = (uint32_t)__cvta_generic_to_shared(Kh);
    const uint32_t vsB = (uint32_t)__cvta_generic_to_shared(Vs);
    const uint32_t psB = (uint32_t)__cvta_generic_to_shared(Psh);

    // ---- load Q tile (64 x 32) as half ----
#pragma unroll
    for (int i = 0; i < 4; i++) {
        int c = tid + i * 128;
        int row = c >> 3, ch = (c & 7) * 4;
        float4 v = *(const float4*)(base + (size_t)(q0 + row) * 768 + h * 32 + ch);
        __half2 h0 = __floats2half2_rn(v.x, v.y);
        __half2 h1 = __floats2half2_rn(v.z, v.w);
        uint2 u; u.x = *(uint32_t*)&h0; u.y = *(uint32_t*)&h1;
        *(uint2*)&Qh[row * KP + ch] = u;
    }
    __syncthreads();

    // ---- Q A-fragments, register-resident ----
    uint32_t qa[2][4];
#pragma unroll
    for (int kc = 0; kc < 2; kc++) {
        qa[kc][0] = *(const uint32_t*)&Qh[(wq + g) * KP + kc * 16 + 2 * t4];
        qa[kc][1] = *(const uint32_t*)&Qh[(wq + g + 8) * KP + kc * 16 + 2 * t4];
        qa[kc][2] = *(const uint32_t*)&Qh[(wq + g) * KP + kc * 16 + 2 * t4 + 8];
        qa[kc][3] = *(const uint32_t*)&Qh[(wq + g + 8) * KP + kc * 16 + 2 * t4 + 8];
    }

    float o[4][4];
#pragma unroll
    for (int nv = 0; nv < 4; nv++)
#pragma unroll
        for (int j = 0; j < 4; j++) o[nv][j] = 0.f;
    float m0 = -1e30f, m1 = -1e30f, ls0 = 0.f, ls1 = 0.f;

    for (int kt = 0; kt < len; kt += 64) {
        const bool tailTile = (kt + 64 > len);
        __syncthreads();
        // ---- load K and V tiles as half ----
#pragma unroll
        for (int i = 0; i < 4; i++) {
            int c = tid + i * 128;
            int row = c >> 3, ch = (c & 7) * 4;
            const float* kp = base + (size_t)(kt + row) * 768 + 256 + h * 32 + ch;
            float4 kv = *(const float4*)kp;
            float4 vv = *(const float4*)(kp + 256);
            __half2 k0 = __floats2half2_rn(kv.x, kv.y);
            __half2 k1 = __floats2half2_rn(kv.z, kv.w);
            __half2 v0 = __floats2half2_rn(vv.x, vv.y);
            __half2 v1 = __floats2half2_rn(vv.z, vv.w);
            uint2 ku; ku.x = *(uint32_t*)&k0; ku.y = *(uint32_t*)&k1;
            uint2 vu; vu.x = *(uint32_t*)&v0; vu.y = *(uint32_t*)&v1;
            *(uint2*)&Kh[row * KP + ch] = ku;
            *(uint2*)&Vs[row * KP + ch] = vu;
        }
        __syncthreads();

        // ---- S = Q @ K^T : ldmatrix K B-frags, f16 mma ----
        float sc[8][4];
#pragma unroll
        for (int n = 0; n < 8; n++)
            sc[n][0] = sc[n][1] = sc[n][2] = sc[n][3] = 0.f;
#pragma unroll
        for (int kc = 0; kc < 2; kc++) {
            uint32_t kb[8][2];
#pragma unroll
            for (int j = 0; j < 8; j += 2) {
                // m0:(j,dlo) m1:(j,dhi) m2:(j+1,dlo) m3:(j+1,dhi)
                int key = (j + (gl >> 1)) * 8 + lr;
                int col = kc * 16 + (gl & 1) * 8;
                ldm_x4(kb[j][0], kb[j][1], kb[j + 1][0], kb[j + 1][1],
                       khB + (key * KP + col) * 2);
            }
#pragma unroll
            for (int n = 0; n < 8; n++)
                mma_f16(sc[n], qa[kc], kb[n]);
        }

        // ---- scale (+ tail mask) + row max ----
        float rmax0 = -1e30f, rmax1 = -1e30f;
        if (tailTile) {
#pragma unroll
            for (int n = 0; n < 8; n++) {
                int c0 = kt + n * 8 + 2 * t4;
                bool v0 = c0 < len, v1 = (c0 + 1) < len;
                sc[n][0] = v0 ? sc[n][0] * scale : -1e30f;
                sc[n][1] = v1 ? sc[n][1] * scale : -1e30f;
                sc[n][2] = v0 ? sc[n][2] * scale : -1e30f;
                sc[n][3] = v1 ? sc[n][3] * scale : -1e30f;
                rmax0 = fmaxf(rmax0, fmaxf(sc[n][0], sc[n][1]));
                rmax1 = fmaxf(rmax1, fmaxf(sc[n][2], sc[n][3]));
            }
        } else {
#pragma unroll
            for (int n = 0; n < 8; n++) {
                sc[n][0] *= scale; sc[n][1] *= scale;
                sc[n][2] *= scale; sc[n][3] *= scale;
                rmax0 = fmaxf(rmax0, fmaxf(sc[n][0], sc[n][1]));
                rmax1 = fmaxf(rmax1, fmaxf(sc[n][2], sc[n][3]));
            }
        }
        rmax0 = fmaxf(rmax0, __shfl_xor_sync(0xffffffffu, rmax0, 1));
        rmax0 = fmaxf(rmax0, __shfl_xor_sync(0xffffffffu, rmax0, 2));
        rmax1 = fmaxf(rmax1, __shfl_xor_sync(0xffffffffu, rmax1, 1));
        rmax1 = fmaxf(rmax1, __shfl_xor_sync(0xffffffffu, rmax1, 2));

        float nm0 = fmaxf(m0, rmax0), nm1 = fmaxf(m1, rmax1);
        float cr0 = __expf(m0 - nm0), cr1 = __expf(m1 - nm1);
        ls0 *= cr0; ls1 *= cr1;
#pragma unroll
        for (int nv = 0; nv < 4; nv++) {
            o[nv][0] *= cr0; o[nv][1] *= cr0;
            o[nv][2] *= cr1; o[nv][3] *= cr1;
        }
        m0 = nm0; m1 = nm1;

        // ---- exp -> P (half) into per-warp smem slab ----
#pragma unroll
        for (int n = 0; n < 8; n++) {
            float p0 = __expf(sc[n][0] - m0), p1 = __expf(sc[n][1] - m0);
            float p2 = __expf(sc[n][2] - m1), p3 = __expf(sc[n][3] - m1);
            ls0 += p0 + p1;
            ls1 += p2 + p3;
            __half2 lo = __floats2half2_rn(p0, p1);
            __half2 hi = __floats2half2_rn(p2, p3);
            *(uint32_t*)&Psh[(wq + g) * PP + n * 8 + 2 * t4] = *(uint32_t*)&lo;
            *(uint32_t*)&Psh[(wq + g + 8) * PP + n * 8 + 2 * t4] = *(uint32_t*)&hi;
        }
        __syncwarp();

        // ---- O += P @ V : ldmatrix P A-frags + V B-frags (trans), f16 mma ---
#pragma unroll
        for (int kc2 = 0; kc2 < 4; kc2++) {
            uint32_t pa[4];
            {
                int row = wq + (gl & 1) * 8 + lr;
                int col = kc2 * 16 + (gl >> 1) * 8;
                ldm_x4(pa[0], pa[1], pa[2], pa[3], psB + (row * PP + col) * 2);
            }
            uint32_t vb[4][2];
#pragma unroll
            for (int vh = 0; vh < 2; vh++) {
                // m0:(klo,dlo) m1:(khi,dlo) m2:(klo,dhi) m3:(khi,dhi)
                int key = kc2 * 16 + (gl & 1) * 8 + lr;
                int dcol = vh * 16 + (gl >> 1) * 8;
                ldm_x4_t(vb[vh * 2][0], vb[vh * 2][1],
                         vb[vh * 2 + 1][0], vb[vh * 2 + 1][1],
                         vsB + (key * KP + dcol) * 2);
            }
#pragma unroll
            for (int nv = 0; nv < 4; nv++)
                mma_f16(o[nv], pa, vb[nv]);
        }
        __syncwarp();
    }

    ls0 += __shfl_xor_sync(0xffffffffu, ls0, 1);
    ls0 += __shfl_xor_sync(0xffffffffu, ls0, 2);
    ls1 += __shfl_xor_sync(0xffffffffu, ls1, 1);
    ls1 += __shfl_xor_sync(0xffffffffu, ls1, 2);
    float i0 = 1.f / ls0, i1 = 1.f / ls1;

    const int r0 = q0 + wq + g;
    float* op0 = ao + (size_t)(b * L_ + r0) * D_ + h * 32;
    float* op1 = ao + (size_t)(b * L_ + r0 + 8) * D_ + h * 32;
#pragma unroll
    for (int nv = 0; nv < 4; nv++) {
        float2 lo, hi;
        lo.x = o[nv][0] * i0; lo.y = o[nv][1] * i0;
        hi.x = o[nv][2] * i1; hi.y = o[nv][3] * i1;
        *(float2*)(op0 + nv * 8 + 2 * t4) = lo;
        *(float2*)(op1 + nv * 8 + 2 * t4) = hi;
    }
}

// ---------------- readout ----------------
__global__ void graph_partial_kernel(const float* __restrict__ x,
                                     const int* __restrict__ lengths,
                                     float* __restrict__ red) {
    int chunk = blockIdx.x, b = blockIdx.y, d = threadIdx.x;
    int len = lengths[b];
    int l0 = chunk * 128;
    int l1 = min(l0 + 128, len);
    float s = 0.f;
    for (int l = l0; l < l1; l++) s += x[((size_t)b * L_ + l) * D_ + d];
    red[((size_t)b * 8 + chunk) * D_ + d] = s;
}

__global__ void graph_final_kernel(const float* __restrict__ red,
                                   const int* __restrict__ lengths,
                                   float* __restrict__ out) {
    int b = blockIdx.x, d = threadIdx.x;
    float s = 0.f;
#pragma unroll
    for (int c = 0; c < 8; c++) s += red[((size_t)b * 8 + c) * D_ + d];
    int cnt = lengths[b] > 1 ? lengths[b] : 1;
    out[b * D_ + d] = s / (float)cnt;
}

__global__ void node_out_kernel(const float* __restrict__ x,
                                const int* __restrict__ lengths,
                                float* __restrict__ out) {
    int row = blockIdx.x, d = threadIdx.x;
    int b = row >> 10, l = row & 1023;
    float v = (l < lengths[b]) ? x[(size_t)row * D_ + d] : 0.f;
    out[(size_t)row * D_ + d] = v;
}

// ---------------- launch ----------------
extern "C" void kernel_launch(void* const* d_in, const int* in_sizes, int n_in,
                              void* d_out, int out_size) {
    const int*   ut      = (const int*)d_in[0];
    const int*   lengths = (const int*)d_in[1];
    const float* emb     = (const float*)d_in[2];
    const float* wqkv    = (const float*)d_in[3];
    const float* bqkv    = (const float*)d_in[4];
    const float* wo      = (const float*)d_in[5];
    const float* bo      = (const float*)d_in[6];
    const float* wlin    = (const float*)d_in[7];
    const float* blin    = (const float*)d_in[8];
    float* out = (float*)d_out;

    float *x, *qkvb, *aob, *h1b, *redb;
    cudaGetSymbolAddress((void**)&x, g_x);
    cudaGetSymbolAddress((void**)&qkvb, g_qkv);
    cudaGetSymbolAddress((void**)&aob, g_ao);
    cudaGetSymbolAddress((void**)&h1b, g_h1);
    cudaGetSymbolAddress((void**)&redb, g_red);

    sched_kernel<<<1, 32>>>(lengths);
    embed_kernel<<<M_, 256>>>(ut, emb, x);

    for (int i = 0; i < NL_; i++) {
        gemm_tc_kernel<<<dim3(768 / 64, M_ / 128), 256>>>(
            x, wqkv + (size_t)i * 3 * D_ * D_, bqkv + (size_t)i * 3 * D_,
            nullptr, qkvb, 3 * D_, D_, 0);
        attn_tc_kernel<<<dim3(H_, B_ * L_ / 64), 128>>>(qkvb, aob, lengths);
        gemm_tc_kernel<<<dim3(D_ / 64, M_ / 128), 256>>>(
            aob, wo + (size_t)i * D_ * D_, bo + (size_t)i * D_,
            x, h1b, D_, D_, 0);
        gemm_tc_kernel<<<dim3(D_ / 64, M_ / 128), 256>>>(
            h1b, wlin + (size_t)i * D_ * D_, blin + (size_t)i * D_,
            nullptr, x, D_, D_, (i < NL_ - 1) ? 1 : 0);
    }

    graph_partial_kernel<<<dim3(8, B_), 256>>>(x, lengths, redb);
    graph_final_kernel<<<B_, 256>>>(redb, lengths, out);
    node_out_kernel<<<M_, 256>>>(x, lengths, out + B_ * D_);
}

// round 13
// speedup vs baseline: 1.4158x; 1.0038x over previous
#include <cuda_runtime.h>
#include <cuda_fp16.h>
#include <math.h>
#include <stdint.h>

#define B_  16
#define L_  1024
#define D_  256
#define H_  8
#define NL_ 3
#define M_  (B_ * L_)   // 16384

// ---------------- scratch ----------------
__device__ float g_x[M_ * D_];
__device__ float g_qkv[M_ * 3 * D_];
__device__ float g_ao[M_ * D_];
__device__ float g_h1[M_ * D_];
__device__ float g_red[B_ * 8 * D_];

// compacted work lists
__device__ int g_nrb;
__device__ int g_rowblk[128];
__device__ int g_nab;
__device__ int g_attnblk[256];

// ---------------- helpers ----------------
__device__ __forceinline__ void mma_f16(float c[4], const uint32_t a[4],
                                        const uint32_t b[2]) {
    asm volatile(
        "mma.sync.aligned.m16n8k16.row.col.f32.f16.f16.f32 "
        "{%0,%1,%2,%3}, {%4,%5,%6,%7}, {%8,%9}, {%0,%1,%2,%3};\n"
        : "+f"(c[0]), "+f"(c[1]), "+f"(c[2]), "+f"(c[3])
        : "r"(a[0]), "r"(a[1]), "r"(a[2]), "r"(a[3]), "r"(b[0]), "r"(b[1]));
}

__device__ __forceinline__ void ldm_x4(uint32_t& r0, uint32_t& r1,
                                       uint32_t& r2, uint32_t& r3,
                                       uint32_t addr) {
    asm volatile(
        "ldmatrix.sync.aligned.m8n8.x4.shared.b16 {%0,%1,%2,%3}, [%4];"
        : "=r"(r0), "=r"(r1), "=r"(r2), "=r"(r3) : "r"(addr));
}

__device__ __forceinline__ void ldm_x4_t(uint32_t& r0, uint32_t& r1,
                                         uint32_t& r2, uint32_t& r3,
                                         uint32_t addr) {
    asm volatile(
        "ldmatrix.sync.aligned.m8n8.x4.trans.shared.b16 {%0,%1,%2,%3}, [%4];"
        : "=r"(r0), "=r"(r1), "=r"(r2), "=r"(r3) : "r"(addr));
}

// ---------------- scheduler ----------------
__global__ void sched_kernel(const int* __restrict__ lengths) {
    if (threadIdx.x != 0) return;
    int idx[B_], len[B_];
#pragma unroll
    for (int b = 0; b < B_; b++) { idx[b] = b; len[b] = lengths[b]; }
#pragma unroll
    for (int i = 0; i < B_ - 1; i++) {
        int best = i;
        for (int j = i + 1; j < B_; j++)
            if (len[j] > len[best] || (len[j] == len[best] && idx[j] < idx[best]))
                best = j;
        int tl = len[i]; len[i] = len[best]; len[best] = tl;
        int ti = idx[i]; idx[i] = idx[best]; idx[best] = ti;
    }
    int n = 0, m = 0;
    for (int i = 0; i < B_; i++) {
        int b = idx[i], ln = len[i];
        int nrb = (ln + 127) >> 7;
        for (int r = 0; r < nrb; r++) g_rowblk[n++] = b * L_ + r * 128;
        int nab = (ln + 63) >> 6;
        for (int q = 0; q < nab; q++) g_attnblk[m++] = (b << 16) | q;
    }
    g_nrb = n;
    g_nab = m;
}

// ---------------- embedding gather ----------------
__global__ void embed_kernel(const int* __restrict__ ut,
                             const float* __restrict__ emb,
                             float* __restrict__ x) {
    int row = blockIdx.x;
    int d = threadIdx.x;
    x[(size_t)row * D_ + d] = emb[(size_t)ut[row] * D_ + d];
}

// ---------------- fp16 tensor-core GEMM: ldmatrix fragments ------------------
#define KPH 72
__global__ void __launch_bounds__(256) gemm_tc_kernel(
    const float* __restrict__ A, const float* __restrict__ W,
    const float* __restrict__ bias, const float* __restrict__ res,
    float* __restrict__ C, int N, int K, int doRelu) {
    if ((int)blockIdx.y >= g_nrb) return;
    const int row0 = g_rowblk[blockIdx.y];

    __shared__ __half Ah[128 * KPH];
    __shared__ __half Bh[64 * KPH];

    const int tid = threadIdx.x;
    const int warp = tid >> 5, lane = tid & 31;
    const int g = lane >> 2, t4 = lane & 3;
    const int gl = lane >> 3, lr = lane & 7;   // ldmatrix group / row-in-group
    const int wm = (warp & 3) * 32;
    const int wn = (warp >> 2) * 32;
    const int col0 = blockIdx.x * 64;

    const int lrow = tid >> 2;
    const int lcol = (tid & 3) * 16;

    const uint32_t ahB = (uint32_t)__cvta_generic_to_shared(Ah);
    const uint32_t bhB = (uint32_t)__cvta_generic_to_shared(Bh);

    float acc[2][4][4];
#pragma unroll
    for (int mi = 0; mi < 2; mi++)
#pragma unroll
        for (int ni = 0; ni < 4; ni++)
#pragma unroll
            for (int j = 0; j < 4; j++) acc[mi][ni][j] = 0.f;

    const float* a0p = A + (size_t)(row0 + lrow) * K + lcol;
    const float* a1p = A + (size_t)(row0 + 64 + lrow) * K + lcol;
    const float* wp  = W + (size_t)(col0 + lrow) * K + lcol;

    for (int kt = 0; kt < K; kt += 64) {
        float4 fa0[4], fa1[4], fw[4];
#pragma unroll
        for (int i = 0; i < 4; i++) {
            fa0[i] = *(const float4*)(a0p + kt + i * 4);
            fa1[i] = *(const float4*)(a1p + kt + i * 4);
            fw[i]  = *(const float4*)(wp + kt + i * 4);
        }
        __syncthreads();
        __half2 h[8];
#pragma unroll
        for (int i = 0; i < 4; i++) {
            h[2 * i]     = __floats2half2_rn(fa0[i].x, fa0[i].y);
            h[2 * i + 1] = __floats2half2_rn(fa0[i].z, fa0[i].w);
        }
        *(uint4*)&Ah[lrow * KPH + lcol]     = *(uint4*)&h[0];
        *(uint4*)&Ah[lrow * KPH + lcol + 8] = *(uint4*)&h[4];
#pragma unroll
        for (int i = 0; i < 4; i++) {
            h[2 * i]     = __floats2half2_rn(fa1[i].x, fa1[i].y);
            h[2 * i + 1] = __floats2half2_rn(fa1[i].z, fa1[i].w);
        }
        *(uint4*)&Ah[(64 + lrow) * KPH + lcol]     = *(uint4*)&h[0];
        *(uint4*)&Ah[(64 + lrow) * KPH + lcol + 8] = *(uint4*)&h[4];
#pragma unroll
        for (int i = 0; i < 4; i++) {
            h[2 * i]     = __floats2half2_rn(fw[i].x, fw[i].y);
            h[2 * i + 1] = __floats2half2_rn(fw[i].z, fw[i].w);
        }
        *(uint4*)&Bh[lrow * KPH + lcol]     = *(uint4*)&h[0];
        *(uint4*)&Bh[lrow * KPH + lcol + 8] = *(uint4*)&h[4];
        __syncthreads();

#pragma unroll
        for (int ks = 0; ks < 4; ks++) {
            const int k0 = ks * 16;
            // A frags via ldmatrix: m0..m3 = (row lo/hi) x (col lo/hi)
            uint32_t a[2][4];
#pragma unroll
            for (int mi = 0; mi < 2; mi++) {
                int row = wm + mi * 16 + (gl & 1) * 8 + lr;
                int col = k0 + (gl >> 1) * 8;
                ldm_x4(a[mi][0], a[mi][1], a[mi][2], a[mi][3],
                       ahB + (row * KPH + col) * 2);
            }
            // B frags via ldmatrix: matrices = (ni-pair) x (k-half)
            uint32_t bf[4][2];
#pragma unroll
            for (int half = 0; half < 2; half++) {
                int row = wn + (half * 2 + (gl >> 1)) * 8 + lr;
                int col = k0 + (gl & 1) * 8;
                ldm_x4(bf[half * 2][0], bf[half * 2][1],
                       bf[half * 2 + 1][0], bf[half * 2 + 1][1],
                       bhB + (row * KPH + col) * 2);
            }
#pragma unroll
            for (int ni = 0; ni < 4; ni++) {
                mma_f16(acc[0][ni], a[0], bf[ni]);
                mma_f16(acc[1][ni], a[1], bf[ni]);
            }
        }
    }

#pragma unroll
    for (int ni = 0; ni < 4; ni++) {
        int c = col0 + wn + ni * 8 + 2 * t4;
        float b0 = bias[c], b1 = bias[c + 1];
#pragma unroll
        for (int mi = 0; mi < 2; mi++) {
#pragma unroll
            for (int half = 0; half < 2; half++) {
                int r = row0 + wm + mi * 16 + g + half * 8;
                float v0 = acc[mi][ni][half * 2 + 0] + b0;
                float v1 = acc[mi][ni][half * 2 + 1] + b1;
                if (res) {
                    float2 rr = *(const float2*)(res + (size_t)r * N + c);
                    v0 += rr.x; v1 += rr.y;
                }
                if (doRelu) { v0 = fmaxf(v0, 0.f); v1 = fmaxf(v1, 0.f); }
                float2 o; o.x = v0; o.y = v1;
                *(float2*)(C + (size_t)r * N + c) = o;
            }
        }
    }
}

// ---------------- attention: all-f16 mma, ldmatrix fragments -----------------
#define KP 40    // halves per row for Qh/Kh/Vs
#define PP 72    // halves per row for Psh
__global__ void __launch_bounds__(128) attn_tc_kernel(
    const float* __restrict__ qkv, float* __restrict__ ao,
    const int* __restrict__ lengths) {
    if ((int)blockIdx.y >= g_nab) return;
    const int packed = g_attnblk[blockIdx.y];
    const int b = packed >> 16;
    const int q0 = (packed & 0xffff) * 64;
    const int h = blockIdx.x;
    const int len = lengths[b];

    __shared__ __half Qh[64 * KP];
    __shared__ __half Kh[64 * KP];
    __shared__ __half Vs[64 * KP];
    __shared__ __half Psh[64 * PP];

    const int tid = threadIdx.x, w = tid >> 5, lane = tid & 31;
    const int g = lane >> 2, t4 = lane & 3;
    const int gl = lane >> 3, lr = lane & 7;
    const int wq = w * 16;
    const float scale = 0.17677669529663687f;  // 1/sqrt(32)
    const float* base = qkv + (size_t)b * L_ * 768;

    const uint32_t khB = (uint32_t)__cvta_generic_to_shared(Kh);
    const uint32_t vsB = (uint32_t)__cvta_generic_to_shared(Vs);
    const uint32_t psB = (uint32_t)__cvta_generic_to_shared(Psh);

#pragma unroll
    for (int i = 0; i < 4; i++) {
        int c = tid + i * 128;
        int row = c >> 3, ch = (c & 7) * 4;
        float4 v = *(const float4*)(base + (size_t)(q0 + row) * 768 + h * 32 + ch);
        __half2 h0 = __floats2half2_rn(v.x, v.y);
        __half2 h1 = __floats2half2_rn(v.z, v.w);
        uint2 u; u.x = *(uint32_t*)&h0; u.y = *(uint32_t*)&h1;
        *(uint2*)&Qh[row * KP + ch] = u;
    }
    __syncthreads();

    uint32_t qa[2][4];
#pragma unroll
    for (int kc = 0; kc < 2; kc++) {
        qa[kc][0] = *(const uint32_t*)&Qh[(wq + g) * KP + kc * 16 + 2 * t4];
        qa[kc][1] = *(const uint32_t*)&Qh[(wq + g + 8) * KP + kc * 16 + 2 * t4];
        qa[kc][2] = *(const uint32_t*)&Qh[(wq + g) * KP + kc * 16 + 2 * t4 + 8];
        qa[kc][3] = *(const uint32_t*)&Qh[(wq + g + 8) * KP + kc * 16 + 2 * t4 + 8];
    }

    float o[4][4];
#pragma unroll
    for (int nv = 0; nv < 4; nv++)
#pragma unroll
        for (int j = 0; j < 4; j++) o[nv][j] = 0.f;
    float m0 = -1e30f, m1 = -1e30f, ls0 = 0.f, ls1 = 0.f;

    for (int kt = 0; kt < len; kt += 64) {
        const bool tailTile = (kt + 64 > len);
        __syncthreads();
#pragma unroll
        for (int i = 0; i < 4; i++) {
            int c = tid + i * 128;
            int row = c >> 3, ch = (c & 7) * 4;
            const float* kp = base + (size_t)(kt + row) * 768 + 256 + h * 32 + ch;
            float4 kv = *(const float4*)kp;
            float4 vv = *(const float4*)(kp + 256);
            __half2 k0 = __floats2half2_rn(kv.x, kv.y);
            __half2 k1 = __floats2half2_rn(kv.z, kv.w);
            __half2 v0 = __floats2half2_rn(vv.x, vv.y);
            __half2 v1 = __floats2half2_rn(vv.z, vv.w);
            uint2 ku; ku.x = *(uint32_t*)&k0; ku.y = *(uint32_t*)&k1;
            uint2 vu; vu.x = *(uint32_t*)&v0; vu.y = *(uint32_t*)&v1;
            *(uint2*)&Kh[row * KP + ch] = ku;
            *(uint2*)&Vs[row * KP + ch] = vu;
        }
        __syncthreads();

        float sc[8][4];
#pragma unroll
        for (int n = 0; n < 8; n++)
            sc[n][0] = sc[n][1] = sc[n][2] = sc[n][3] = 0.f;
#pragma unroll
        for (int kc = 0; kc < 2; kc++) {
            uint32_t kb[8][2];
#pragma unroll
            for (int j = 0; j < 8; j += 2) {
                int key = (j + (gl >> 1)) * 8 + lr;
                int col = kc * 16 + (gl & 1) * 8;
                ldm_x4(kb[j][0], kb[j][1], kb[j + 1][0], kb[j + 1][1],
                       khB + (key * KP + col) * 2);
            }
#pragma unroll
            for (int n = 0; n < 8; n++)
                mma_f16(sc[n], qa[kc], kb[n]);
        }

        float rmax0 = -1e30f, rmax1 = -1e30f;
        if (tailTile) {
#pragma unroll
            for (int n = 0; n < 8; n++) {
                int c0 = kt + n * 8 + 2 * t4;
                bool v0 = c0 < len, v1 = (c0 + 1) < len;
                sc[n][0] = v0 ? sc[n][0] * scale : -1e30f;
                sc[n][1] = v1 ? sc[n][1] * scale : -1e30f;
                sc[n][2] = v0 ? sc[n][2] * scale : -1e30f;
                sc[n][3] = v1 ? sc[n][3] * scale : -1e30f;
                rmax0 = fmaxf(rmax0, fmaxf(sc[n][0], sc[n][1]));
                rmax1 = fmaxf(rmax1, fmaxf(sc[n][2], sc[n][3]));
            }
        } else {
#pragma unroll
            for (int n = 0; n < 8; n++) {
                sc[n][0] *= scale; sc[n][1] *= scale;
                sc[n][2] *= scale; sc[n][3] *= scale;
                rmax0 = fmaxf(rmax0, fmaxf(sc[n][0], sc[n][1]));
                rmax1 = fmaxf(rmax1, fmaxf(sc[n][2], sc[n][3]));
            }
        }
        rmax0 = fmaxf(rmax0, __shfl_xor_sync(0xffffffffu, rmax0, 1));
        rmax0 = fmaxf(rmax0, __shfl_xor_sync(0xffffffffu, rmax0, 2));
        rmax1 = fmaxf(rmax1, __shfl_xor_sync(0xffffffffu, rmax1, 1));
        rmax1 = fmaxf(rmax1, __shfl_xor_sync(0xffffffffu, rmax1, 2));

        float nm0 = fmaxf(m0, rmax0), nm1 = fmaxf(m1, rmax1);
        float cr0 = __expf(m0 - nm0), cr1 = __expf(m1 - nm1);
        ls0 *= cr0; ls1 *= cr1;
#pragma unroll
        for (int nv = 0; nv < 4; nv++) {
            o[nv][0] *= cr0; o[nv][1] *= cr0;
            o[nv][2] *= cr1; o[nv][3] *= cr1;
        }
        m0 = nm0; m1 = nm1;

#pragma unroll
        for (int n = 0; n < 8; n++) {
            float p0 = __expf(sc[n][0] - m0), p1 = __expf(sc[n][1] - m0);
            float p2 = __expf(sc[n][2] - m1), p3 = __expf(sc[n][3] - m1);
            ls0 += p0 + p1;
            ls1 += p2 + p3;
            __half2 lo = __floats2half2_rn(p0, p1);
            __half2 hi = __floats2half2_rn(p2, p3);
            *(uint32_t*)&Psh[(wq + g) * PP + n * 8 + 2 * t4] = *(uint32_t*)&lo;
            *(uint32_t*)&Psh[(wq + g + 8) * PP + n * 8 + 2 * t4] = *(uint32_t*)&hi;
        }
        __syncwarp();

#pragma unroll
        for (int kc2 = 0; kc2 < 4; kc2++) {
            uint32_t pa[4];
            {
                int row = wq + (gl & 1) * 8 + lr;
                int col = kc2 * 16 + (gl >> 1) * 8;
                ldm_x4(pa[0], pa[1], pa[2], pa[3], psB + (row * PP + col) * 2);
            }
            uint32_t vb[4][2];
#pragma unroll
            for (int vh = 0; vh < 2; vh++) {
                int key = kc2 * 16 + (gl & 1) * 8 + lr;
                int dcol = vh * 16 + (gl >> 1) * 8;
                ldm_x4_t(vb[vh * 2][0], vb[vh * 2][1],
                         vb[vh * 2 + 1][0], vb[vh * 2 + 1][1],
                         vsB + (key * KP + dcol) * 2);
            }
#pragma unroll
            for (int nv = 0; nv < 4; nv++)
                mma_f16(o[nv], pa, vb[nv]);
        }
        __syncwarp();
    }

    ls0 += __shfl_xor_sync(0xffffffffu, ls0, 1);
    ls0 += __shfl_xor_sync(0xffffffffu, ls0, 2);
    ls1 += __shfl_xor_sync(0xffffffffu, ls1, 1);
    ls1 += __shfl_xor_sync(0xffffffffu, ls1, 2);
    float i0 = 1.f / ls0, i1 = 1.f / ls1;

    const int r0 = q0 + wq + g;
    float* op0 = ao + (size_t)(b * L_ + r0) * D_ + h * 32;
    float* op1 = ao + (size_t)(b * L_ + r0 + 8) * D_ + h * 32;
#pragma unroll
    for (int nv = 0; nv < 4; nv++) {
        float2 lo, hi;
        lo.x = o[nv][0] * i0; lo.y = o[nv][1] * i0;
        hi.x = o[nv][2] * i1; hi.y = o[nv][3] * i1;
        *(float2*)(op0 + nv * 8 + 2 * t4) = lo;
        *(float2*)(op1 + nv * 8 + 2 * t4) = hi;
    }
}

// ---------------- readout ----------------
__global__ void graph_partial_kernel(const float* __restrict__ x,
                                     const int* __restrict__ lengths,
                                     float* __restrict__ red) {
    int chunk = blockIdx.x, b = blockIdx.y, d = threadIdx.x;
    int len = lengths[b];
    int l0 = chunk * 128;
    int l1 = min(l0 + 128, len);
    float s = 0.f;
    for (int l = l0; l < l1; l++) s += x[((size_t)b * L_ + l) * D_ + d];
    red[((size_t)b * 8 + chunk) * D_ + d] = s;
}

__global__ void graph_final_kernel(const float* __restrict__ red,
                                   const int* __restrict__ lengths,
                                   float* __restrict__ out) {
    int b = blockIdx.x, d = threadIdx.x;
    float s = 0.f;
#pragma unroll
    for (int c = 0; c < 8; c++) s += red[((size_t)b * 8 + c) * D_ + d];
    int cnt = lengths[b] > 1 ? lengths[b] : 1;
    out[b * D_ + d] = s / (float)cnt;
}

__global__ void node_out_kernel(const float* __restrict__ x,
                                const int* __restrict__ lengths,
                                float* __restrict__ out) {
    int row = blockIdx.x, d = threadIdx.x;
    int b = row >> 10, l = row & 1023;
    float v = (l < lengths[b]) ? x[(size_t)row * D_ + d] : 0.f;
    out[(size_t)row * D_ + d] = v;
}

// ---------------- launch ----------------
extern "C" void kernel_launch(void* const* d_in, const int* in_sizes, int n_in,
                              void* d_out, int out_size) {
    const int*   ut      = (const int*)d_in[0];
    const int*   lengths = (const int*)d_in[1];
    const float* emb     = (const float*)d_in[2];
    const float* wqkv    = (const float*)d_in[3];
    const float* bqkv    = (const float*)d_in[4];
    const float* wo      = (const float*)d_in[5];
    const float* bo      = (const float*)d_in[6];
    const float* wlin    = (const float*)d_in[7];
    const float* blin    = (const float*)d_in[8];
    float* out = (float*)d_out;

    float *x, *qkvb, *aob, *h1b, *redb;
    cudaGetSymbolAddress((void**)&x, g_x);
    cudaGetSymbolAddress((void**)&qkvb, g_qkv);
    cudaGetSymbolAddress((void**)&aob, g_ao);
    cudaGetSymbolAddress((void**)&h1b, g_h1);
    cudaGetSymbolAddress((void**)&redb, g_red);

    sched_kernel<<<1, 32>>>(lengths);
    embed_kernel<<<M_, 256>>>(ut, emb, x);

    for (int i = 0; i < NL_; i++) {
        gemm_tc_kernel<<<dim3(768 / 64, M_ / 128), 256>>>(
            x, wqkv + (size_t)i * 3 * D_ * D_, bqkv + (size_t)i * 3 * D_,
            nullptr, qkvb, 3 * D_, D_, 0);
        attn_tc_kernel<<<dim3(H_, B_ * L_ / 64), 128>>>(qkvb, aob, lengths);
        gemm_tc_kernel<<<dim3(D_ / 64, M_ / 128), 256>>>(
            aob, wo + (size_t)i * D_ * D_, bo + (size_t)i * D_,
            x, h1b, D_, D_, 0);
        gemm_tc_kernel<<<dim3(D_ / 64, M_ / 128), 256>>>(
            h1b, wlin + (size_t)i * D_ * D_, blin + (size_t)i * D_,
            nullptr, x, D_, D_, (i < NL_ - 1) ? 1 : 0);
    }

    graph_partial_kernel<<<dim3(8, B_), 256>>>(x, lengths, redb);
    graph_final_kernel<<<B_, 256>>>(redb, lengths, out);
    node_out_kernel<<<M_, 256>>>(x, lengths, out + B_ * D_);
}

// round 15
// speedup vs baseline: 1.5060x; 1.0637x over previous
#include <cuda_runtime.h>
#include <cuda_fp16.h>
#include <math.h>
#include <stdint.h>

#define B_  16
#define L_  1024
#define D_  256
#define H_  8
#define NL_ 3
#define M_  (B_ * L_)   // 16384

// ---------------- scratch ----------------
__device__ float  g_x[M_ * D_];
__device__ __half g_qkv[M_ * 3 * D_];   // fp16 qkv (attention consumes f16)
__device__ __half g_ao[M_ * D_];        // fp16 attention output (wo GEMM consumes f16)
__device__ float  g_h1[M_ * D_];
__device__ float  g_red[B_ * 8 * D_];

// compacted work lists
__device__ int g_nrb;
__device__ int g_rowblk[128];
__device__ int g_nab;
__device__ int g_attnblk[256];

// ---------------- helpers ----------------
__device__ __forceinline__ void mma_f16(float c[4], const uint32_t a[4],
                                        const uint32_t b[2]) {
    asm volatile(
        "mma.sync.aligned.m16n8k16.row.col.f32.f16.f16.f32 "
        "{%0,%1,%2,%3}, {%4,%5,%6,%7}, {%8,%9}, {%0,%1,%2,%3};\n"
        : "+f"(c[0]), "+f"(c[1]), "+f"(c[2]), "+f"(c[3])
        : "r"(a[0]), "r"(a[1]), "r"(a[2]), "r"(a[3]), "r"(b[0]), "r"(b[1]));
}

__device__ __forceinline__ void ldm_x4(uint32_t& r0, uint32_t& r1,
                                       uint32_t& r2, uint32_t& r3,
                                       uint32_t addr) {
    asm volatile(
        "ldmatrix.sync.aligned.m8n8.x4.shared.b16 {%0,%1,%2,%3}, [%4];"
        : "=r"(r0), "=r"(r1), "=r"(r2), "=r"(r3) : "r"(addr));
}

__device__ __forceinline__ void ldm_x4_t(uint32_t& r0, uint32_t& r1,
                                         uint32_t& r2, uint32_t& r3,
                                         uint32_t addr) {
    asm volatile(
        "ldmatrix.sync.aligned.m8n8.x4.trans.shared.b16 {%0,%1,%2,%3}, [%4];"
        : "=r"(r0), "=r"(r1), "=r"(r2), "=r"(r3) : "r"(addr));
}

__device__ __forceinline__ uint32_t packh2(float lo, float hi) {
    __half2 h = __floats2half2_rn(lo, hi);
    return *(uint32_t*)&h;
}

// ---------------- scheduler ----------------
__global__ void sched_kernel(const int* __restrict__ lengths) {
    if (threadIdx.x != 0) return;
    int idx[B_], len[B_];
#pragma unroll
    for (int b = 0; b < B_; b++) { idx[b] = b; len[b] = lengths[b]; }
#pragma unroll
    for (int i = 0; i < B_ - 1; i++) {
        int best = i;
        for (int j = i + 1; j < B_; j++)
            if (len[j] > len[best] || (len[j] == len[best] && idx[j] < idx[best]))
                best = j;
        int tl = len[i]; len[i] = len[best]; len[best] = tl;
        int ti = idx[i]; idx[i] = idx[best]; idx[best] = ti;
    }
    int n = 0, m = 0;
    for (int i = 0; i < B_; i++) {
        int b = idx[i], ln = len[i];
        int nrb = (ln + 127) >> 7;
        for (int r = 0; r < nrb; r++) g_rowblk[n++] = b * L_ + r * 128;
        int nab = (ln + 63) >> 6;
        for (int q = 0; q < nab; q++) g_attnblk[m++] = (b << 16) | q;
    }
    g_nrb = n;
    g_nab = m;
}

// ---------------- embedding gather ----------------
__global__ void embed_kernel(const int* __restrict__ ut,
                             const float* __restrict__ emb,
                             float* __restrict__ x) {
    int row = blockIdx.x;
    int d = threadIdx.x;
    x[(size_t)row * D_ + d] = emb[(size_t)ut[row] * D_ + d];
}

// ---------------- GEMM (A fp32): C = A @ W^T + bias (+res) (relu) ------------
// Cf fp32 output or Ch fp16 output (exactly one non-null).
#define KPH 72
__global__ void __launch_bounds__(256) gemm_a32_kernel(
    const float* __restrict__ A, const float* __restrict__ W,
    const float* __restrict__ bias, const float* __restrict__ res,
    float* __restrict__ Cf, __half* __restrict__ Ch,
    int N, int K, int doRelu) {
    if ((int)blockIdx.y >= g_nrb) return;
    const int row0 = g_rowblk[blockIdx.y];

    __shared__ __half Ah[128 * KPH];
    __shared__ __half Bh[64 * KPH];

    const int tid = threadIdx.x;
    const int warp = tid >> 5, lane = tid & 31;
    const int g = lane >> 2, t4 = lane & 3;
    const int gl = lane >> 3, lr = lane & 7;
    const int wm = (warp & 3) * 32;
    const int wn = (warp >> 2) * 32;
    const int col0 = blockIdx.x * 64;

    const int lrow = tid >> 2;
    const int lcol = (tid & 3) * 16;

    const uint32_t ahB = (uint32_t)__cvta_generic_to_shared(Ah);
    const uint32_t bhB = (uint32_t)__cvta_generic_to_shared(Bh);

    float acc[2][4][4];
#pragma unroll
    for (int mi = 0; mi < 2; mi++)
#pragma unroll
        for (int ni = 0; ni < 4; ni++)
#pragma unroll
            for (int j = 0; j < 4; j++) acc[mi][ni][j] = 0.f;

    const float* a0p = A + (size_t)(row0 + lrow) * K + lcol;
    const float* a1p = A + (size_t)(row0 + 64 + lrow) * K + lcol;
    const float* wp  = W + (size_t)(col0 + lrow) * K + lcol;

    for (int kt = 0; kt < K; kt += 64) {
        float4 fa0[4], fa1[4], fw[4];
#pragma unroll
        for (int i = 0; i < 4; i++) {
            fa0[i] = *(const float4*)(a0p + kt + i * 4);
            fa1[i] = *(const float4*)(a1p + kt + i * 4);
            fw[i]  = *(const float4*)(wp + kt + i * 4);
        }
        __syncthreads();
        __half2 h[8];
#pragma unroll
        for (int i = 0; i < 4; i++) {
            h[2 * i]     = __floats2half2_rn(fa0[i].x, fa0[i].y);
            h[2 * i + 1] = __floats2half2_rn(fa0[i].z, fa0[i].w);
        }
        *(uint4*)&Ah[lrow * KPH + lcol]     = *(uint4*)&h[0];
        *(uint4*)&Ah[lrow * KPH + lcol + 8] = *(uint4*)&h[4];
#pragma unroll
        for (int i = 0; i < 4; i++) {
            h[2 * i]     = __floats2half2_rn(fa1[i].x, fa1[i].y);
            h[2 * i + 1] = __floats2half2_rn(fa1[i].z, fa1[i].w);
        }
        *(uint4*)&Ah[(64 + lrow) * KPH + lcol]     = *(uint4*)&h[0];
        *(uint4*)&Ah[(64 + lrow) * KPH + lcol + 8] = *(uint4*)&h[4];
#pragma unroll
        for (int i = 0; i < 4; i++) {
            h[2 * i]     = __floats2half2_rn(fw[i].x, fw[i].y);
            h[2 * i + 1] = __floats2half2_rn(fw[i].z, fw[i].w);
        }
        *(uint4*)&Bh[lrow * KPH + lcol]     = *(uint4*)&h[0];
        *(uint4*)&Bh[lrow * KPH + lcol + 8] = *(uint4*)&h[4];
        __syncthreads();

#pragma unroll
        for (int ks = 0; ks < 4; ks++) {
            const int k0 = ks * 16;
            uint32_t a[2][4];
#pragma unroll
            for (int mi = 0; mi < 2; mi++) {
                int row = wm + mi * 16 + (gl & 1) * 8 + lr;
                int col = k0 + (gl >> 1) * 8;
                ldm_x4(a[mi][0], a[mi][1], a[mi][2], a[mi][3],
                       ahB + (row * KPH + col) * 2);
            }
            uint32_t bf[4][2];
#pragma unroll
            for (int half = 0; half < 2; half++) {
                int row = wn + (half * 2 + (gl >> 1)) * 8 + lr;
                int col = k0 + (gl & 1) * 8;
                ldm_x4(bf[half * 2][0], bf[half * 2][1],
                       bf[half * 2 + 1][0], bf[half * 2 + 1][1],
                       bhB + (row * KPH + col) * 2);
            }
#pragma unroll
            for (int ni = 0; ni < 4; ni++) {
                mma_f16(acc[0][ni], a[0], bf[ni]);
                mma_f16(acc[1][ni], a[1], bf[ni]);
            }
        }
    }

#pragma unroll
    for (int ni = 0; ni < 4; ni++) {
        int c = col0 + wn + ni * 8 + 2 * t4;
        float b0 = bias[c], b1 = bias[c + 1];
#pragma unroll
        for (int mi = 0; mi < 2; mi++) {
#pragma unroll
            for (int half = 0; half < 2; half++) {
                int r = row0 + wm + mi * 16 + g + half * 8;
                float v0 = acc[mi][ni][half * 2 + 0] + b0;
                float v1 = acc[mi][ni][half * 2 + 1] + b1;
                if (res) {
                    float2 rr = *(const float2*)(res + (size_t)r * N + c);
                    v0 += rr.x; v1 += rr.y;
                }
                if (doRelu) { v0 = fmaxf(v0, 0.f); v1 = fmaxf(v1, 0.f); }
                if (Ch) {
                    *(uint32_t*)(Ch + (size_t)r * N + c) = packh2(v0, v1);
                } else {
                    float2 o; o.x = v0; o.y = v1;
                    *(float2*)(Cf + (size_t)r * N + c) = o;
                }
            }
        }
    }
}

// ---------------- GEMM (A fp16 input): h1 = A @ W^T + bias + res (fp32 out) --
__global__ void __launch_bounds__(256) gemm_a16_kernel(
    const __half* __restrict__ A, const float* __restrict__ W,
    const float* __restrict__ bias, const float* __restrict__ res,
    float* __restrict__ Cf, int N, int K) {
    if ((int)blockIdx.y >= g_nrb) return;
    const int row0 = g_rowblk[blockIdx.y];

    __shared__ __half Ah[128 * KPH];
    __shared__ __half Bh[64 * KPH];

    const int tid = threadIdx.x;
    const int warp = tid >> 5, lane = tid & 31;
    const int g = lane >> 2, t4 = lane & 3;
    const int gl = lane >> 3, lr = lane & 7;
    const int wm = (warp & 3) * 32;
    const int wn = (warp >> 2) * 32;
    const int col0 = blockIdx.x * 64;

    const int lrow = tid >> 2;
    const int lcol = (tid & 3) * 16;

    const uint32_t ahB = (uint32_t)__cvta_generic_to_shared(Ah);
    const uint32_t bhB = (uint32_t)__cvta_generic_to_shared(Bh);

    float acc[2][4][4];
#pragma unroll
    for (int mi = 0; mi < 2; mi++)
#pragma unroll
        for (int ni = 0; ni < 4; ni++)
#pragma unroll
            for (int j = 0; j < 4; j++) acc[mi][ni][j] = 0.f;

    const __half* a0p = A + (size_t)(row0 + lrow) * K + lcol;
    const __half* a1p = A + (size_t)(row0 + 64 + lrow) * K + lcol;
    const float*  wp  = W + (size_t)(col0 + lrow) * K + lcol;

    for (int kt = 0; kt < K; kt += 64) {
        uint4 ha0[2], ha1[2];
        float4 fw[4];
#pragma unroll
        for (int i = 0; i < 2; i++) {
            ha0[i] = *(const uint4*)(a0p + kt + i * 8);
            ha1[i] = *(const uint4*)(a1p + kt + i * 8);
        }
#pragma unroll
        for (int i = 0; i < 4; i++) fw[i] = *(const float4*)(wp + kt + i * 4);
        __syncthreads();
        *(uint4*)&Ah[lrow * KPH + lcol]     = ha0[0];
        *(uint4*)&Ah[lrow * KPH + lcol + 8] = ha0[1];
        *(uint4*)&Ah[(64 + lrow) * KPH + lcol]     = ha1[0];
        *(uint4*)&Ah[(64 + lrow) * KPH + lcol + 8] = ha1[1];
        __half2 h[8];
#pragma unroll
        for (int i = 0; i < 4; i++) {
            h[2 * i]     = __floats2half2_rn(fw[i].x, fw[i].y);
            h[2 * i + 1] = __floats2half2_rn(fw[i].z, fw[i].w);
        }
        *(uint4*)&Bh[lrow * KPH + lcol]     = *(uint4*)&h[0];
        *(uint4*)&Bh[lrow * KPH + lcol + 8] = *(uint4*)&h[4];
        __syncthreads();

#pragma unroll
        for (int ks = 0; ks < 4; ks++) {
            const int k0 = ks * 16;
            uint32_t a[2][4];
#pragma unroll
            for (int mi = 0; mi < 2; mi++) {
                int row = wm + mi * 16 + (gl & 1) * 8 + lr;
                int col = k0 + (gl >> 1) * 8;
                ldm_x4(a[mi][0], a[mi][1], a[mi][2], a[mi][3],
                       ahB + (row * KPH + col) * 2);
            }
            uint32_t bf[4][2];
#pragma unroll
            for (int half = 0; half < 2; half++) {
                int row = wn + (half * 2 + (gl >> 1)) * 8 + lr;
                int col = k0 + (gl & 1) * 8;
                ldm_x4(bf[half * 2][0], bf[half * 2][1],
                       bf[half * 2 + 1][0], bf[half * 2 + 1][1],
                       bhB + (row * KPH + col) * 2);
            }
#pragma unroll
            for (int ni = 0; ni < 4; ni++) {
                mma_f16(acc[0][ni], a[0], bf[ni]);
                mma_f16(acc[1][ni], a[1], bf[ni]);
            }
        }
    }

#pragma unroll
    for (int ni = 0; ni < 4; ni++) {
        int c = col0 + wn + ni * 8 + 2 * t4;
        float b0 = bias[c], b1 = bias[c + 1];
#pragma unroll
        for (int mi = 0; mi < 2; mi++) {
#pragma unroll
            for (int half = 0; half < 2; half++) {
                int r = row0 + wm + mi * 16 + g + half * 8;
                float2 rr = *(const float2*)(res + (size_t)r * N + c);
                float2 o;
                o.x = acc[mi][ni][half * 2 + 0] + b0 + rr.x;
                o.y = acc[mi][ni][half * 2 + 1] + b1 + rr.y;
                *(float2*)(Cf + (size_t)r * N + c) = o;
            }
        }
    }
}

// ---------------- attention: f16 qkv in, f16 ao out, no P round-trip ---------
#define KP 40    // halves per row for Qh/Kh/Vs
__global__ void __launch_bounds__(128) attn_tc_kernel(
    const __half* __restrict__ qkv, __half* __restrict__ ao,
    const int* __restrict__ lengths) {
    if ((int)blockIdx.y >= g_nab) return;
    const int packed = g_attnblk[blockIdx.y];
    const int b = packed >> 16;
    const int q0 = (packed & 0xffff) * 64;
    const int h = blockIdx.x;
    const int len = lengths[b];

    __shared__ __half Qh[64 * KP];
    __shared__ __half Kh[64 * KP];
    __shared__ __half Vs[64 * KP];

    const int tid = threadIdx.x, w = tid >> 5, lane = tid & 31;
    const int g = lane >> 2, t4 = lane & 3;
    const int gl = lane >> 3, lr = lane & 7;
    const int wq = w * 16;
    const float scale = 0.17677669529663687f;  // 1/sqrt(32)
    const __half* base = qkv + (size_t)b * L_ * 768;

    const uint32_t khB = (uint32_t)__cvta_generic_to_shared(Kh);
    const uint32_t vsB = (uint32_t)__cvta_generic_to_shared(Vs);

    // ---- load Q tile (64 x 32 halves) ----
#pragma unroll
    for (int i = 0; i < 4; i++) {
        int c = tid + i * 128;
        int row = c >> 3, ch = (c & 7) * 4;
        uint2 u = *(const uint2*)(base + (size_t)(q0 + row) * 768 + h * 32 + ch);
        *(uint2*)&Qh[row * KP + ch] = u;
    }
    __syncthreads();

    uint32_t qa[2][4];
#pragma unroll
    for (int kc = 0; kc < 2; kc++) {
        qa[kc][0] = *(const uint32_t*)&Qh[(wq + g) * KP + kc * 16 + 2 * t4];
        qa[kc][1] = *(const uint32_t*)&Qh[(wq + g + 8) * KP + kc * 16 + 2 * t4];
        qa[kc][2] = *(const uint32_t*)&Qh[(wq + g) * KP + kc * 16 + 2 * t4 + 8];
        qa[kc][3] = *(const uint32_t*)&Qh[(wq + g + 8) * KP + kc * 16 + 2 * t4 + 8];
    }

    float o[4][4];
#pragma unroll
    for (int nv = 0; nv < 4; nv++)
#pragma unroll
        for (int j = 0; j < 4; j++) o[nv][j] = 0.f;
    float m0 = -1e30f, m1 = -1e30f, ls0 = 0.f, ls1 = 0.f;

    for (int kt = 0; kt < len; kt += 64) {
        const bool tailTile = (kt + 64 > len);
        __syncthreads();
#pragma unroll
        for (int i = 0; i < 4; i++) {
            int c = tid + i * 128;
            int row = c >> 3, ch = (c & 7) * 4;
            const __half* kp = base + (size_t)(kt + row) * 768 + 256 + h * 32 + ch;
            uint2 ku = *(const uint2*)kp;
            uint2 vu = *(const uint2*)(kp + 256);
            *(uint2*)&Kh[row * KP + ch] = ku;
            *(uint2*)&Vs[row * KP + ch] = vu;
        }
        __syncthreads();

        // ---- S = Q @ K^T ----
        float sc[8][4];
#pragma unroll
        for (int n = 0; n < 8; n++)
            sc[n][0] = sc[n][1] = sc[n][2] = sc[n][3] = 0.f;
#pragma unroll
        for (int kc = 0; kc < 2; kc++) {
            uint32_t kb[8][2];
#pragma unroll
            for (int j = 0; j < 8; j += 2) {
                int key = (j + (gl >> 1)) * 8 + lr;
                int col = kc * 16 + (gl & 1) * 8;
                ldm_x4(kb[j][0], kb[j][1], kb[j + 1][0], kb[j + 1][1],
                       khB + (key * KP + col) * 2);
            }
#pragma unroll
            for (int n = 0; n < 8; n++)
                mma_f16(sc[n], qa[kc], kb[n]);
        }

        // ---- scale (+ tail mask) + row max ----
        float rmax0 = -1e30f, rmax1 = -1e30f;
        if (tailTile) {
#pragma unroll
            for (int n = 0; n < 8; n++) {
                int c0 = kt + n * 8 + 2 * t4;
                bool v0 = c0 < len, v1 = (c0 + 1) < len;
                sc[n][0] = v0 ? sc[n][0] * scale : -1e30f;
                sc[n][1] = v1 ? sc[n][1] * scale : -1e30f;
                sc[n][2] = v0 ? sc[n][2] * scale : -1e30f;
                sc[n][3] = v1 ? sc[n][3] * scale : -1e30f;
                rmax0 = fmaxf(rmax0, fmaxf(sc[n][0], sc[n][1]));
                rmax1 = fmaxf(rmax1, fmaxf(sc[n][2], sc[n][3]));
            }
        } else {
#pragma unroll
            for (int n = 0; n < 8; n++) {
                sc[n][0] *= scale; sc[n][1] *= scale;
                sc[n][2] *= scale; sc[n][3] *= scale;
                rmax0 = fmaxf(rmax0, fmaxf(sc[n][0], sc[n][1]));
                rmax1 = fmaxf(rmax1, fmaxf(sc[n][2], sc[n][3]));
            }
        }
        rmax0 = fmaxf(rmax0, __shfl_xor_sync(0xffffffffu, rmax0, 1));
        rmax0 = fmaxf(rmax0, __shfl_xor_sync(0xffffffffu, rmax0, 2));
        rmax1 = fmaxf(rmax1, __shfl_xor_sync(0xffffffffu, rmax1, 1));
        rmax1 = fmaxf(rmax1, __shfl_xor_sync(0xffffffffu, rmax1, 2));

        float nm0 = fmaxf(m0, rmax0), nm1 = fmaxf(m1, rmax1);
        float cr0 = __expf(m0 - nm0), cr1 = __expf(m1 - nm1);
        ls0 *= cr0; ls1 *= cr1;
#pragma unroll
        for (int nv = 0; nv < 4; nv++) {
            o[nv][0] *= cr0; o[nv][1] *= cr0;
            o[nv][2] *= cr1; o[nv][3] *= cr1;
        }
        m0 = nm0; m1 = nm1;

        // ---- exp in registers (overwrite sc) ----
#pragma unroll
        for (int n = 0; n < 8; n++) {
            sc[n][0] = __expf(sc[n][0] - m0);
            sc[n][1] = __expf(sc[n][1] - m0);
            sc[n][2] = __expf(sc[n][2] - m1);
            sc[n][3] = __expf(sc[n][3] - m1);
            ls0 += sc[n][0] + sc[n][1];
            ls1 += sc[n][2] + sc[n][3];
        }

        // ---- O += P @ V : P A-frags packed directly from S C-frags ----------
#pragma unroll
        for (int kc2 = 0; kc2 < 4; kc2++) {
            uint32_t pa[4];
            pa[0] = packh2(sc[2 * kc2][0], sc[2 * kc2][1]);
            pa[1] = packh2(sc[2 * kc2][2], sc[2 * kc2][3]);
            pa[2] = packh2(sc[2 * kc2 + 1][0], sc[2 * kc2 + 1][1]);
            pa[3] = packh2(sc[2 * kc2 + 1][2], sc[2 * kc2 + 1][3]);
            uint32_t vb[4][2];
#pragma unroll
            for (int vh = 0; vh < 2; vh++) {
                int key = kc2 * 16 + (gl & 1) * 8 + lr;
                int dcol = vh * 16 + (gl >> 1) * 8;
                ldm_x4_t(vb[vh * 2][0], vb[vh * 2][1],
                         vb[vh * 2 + 1][0], vb[vh * 2 + 1][1],
                         vsB + (key * KP + dcol) * 2);
            }
#pragma unroll
            for (int nv = 0; nv < 4; nv++)
                mma_f16(o[nv], pa, vb[nv]);
        }
    }

    ls0 += __shfl_xor_sync(0xffffffffu, ls0, 1);
    ls0 += __shfl_xor_sync(0xffffffffu, ls0, 2);
    ls1 += __shfl_xor_sync(0xffffffffu, ls1, 1);
    ls1 += __shfl_xor_sync(0xffffffffu, ls1, 2);
    float i0 = 1.f / ls0, i1 = 1.f / ls1;

    const int r0 = q0 + wq + g;
    __half* op0 = ao + (size_t)(b * L_ + r0) * D_ + h * 32;
    __half* op1 = ao + (size_t)(b * L_ + r0 + 8) * D_ + h * 32;
#pragma unroll
    for (int nv = 0; nv < 4; nv++) {
        *(uint32_t*)(op0 + nv * 8 + 2 * t4) = packh2(o[nv][0] * i0, o[nv][1] * i0);
        *(uint32_t*)(op1 + nv * 8 + 2 * t4) = packh2(o[nv][2] * i1, o[nv][3] * i1);
    }
}

// ---------------- readout ----------------
__global__ void graph_partial_kernel(const float* __restrict__ x,
                                     const int* __restrict__ lengths,
                                     float* __restrict__ red) {
    int chunk = blockIdx.x, b = blockIdx.y, d = threadIdx.x;
    int len = lengths[b];
    int l0 = chunk * 128;
    int l1 = min(l0 + 128, len);
    float s = 0.f;
    for (int l = l0; l < l1; l++) s += x[((size_t)b * L_ + l) * D_ + d];
    red[((size_t)b * 8 + chunk) * D_ + d] = s;
}

__global__ void graph_final_kernel(const float* __restrict__ red,
                                   const int* __restrict__ lengths,
                                   float* __restrict__ out) {
    int b = blockIdx.x, d = threadIdx.x;
    float s = 0.f;
#pragma unroll
    for (int c = 0; c < 8; c++) s += red[((size_t)b * 8 + c) * D_ + d];
    int cnt = lengths[b] > 1 ? lengths[b] : 1;
    out[b * D_ + d] = s / (float)cnt;
}

__global__ void node_out_kernel(const float* __restrict__ x,
                                const int* __restrict__ lengths,
                                float* __restrict__ out) {
    int row = blockIdx.x, d = threadIdx.x;
    int b = row >> 10, l = row & 1023;
    float v = (l < lengths[b]) ? x[(size_t)row * D_ + d] : 0.f;
    out[(size_t)row * D_ + d] = v;
}

// ---------------- launch ----------------
extern "C" void kernel_launch(void* const* d_in, const int* in_sizes, int n_in,
                              void* d_out, int out_size) {
    const int*   ut      = (const int*)d_in[0];
    const int*   lengths = (const int*)d_in[1];
    const float* emb     = (const float*)d_in[2];
    const float* wqkv    = (const float*)d_in[3];
    const float* bqkv    = (const float*)d_in[4];
    const float* wo      = (const float*)d_in[5];
    const float* bo      = (const float*)d_in[6];
    const float* wlin    = (const float*)d_in[7];
    const float* blin    = (const float*)d_in[8];
    float* out = (float*)d_out;

    float *x, *h1b, *redb;
    __half *qkvb, *aob;
    cudaGetSymbolAddress((void**)&x, g_x);
    cudaGetSymbolAddress((void**)&qkvb, g_qkv);
    cudaGetSymbolAddress((void**)&aob, g_ao);
    cudaGetSymbolAddress((void**)&h1b, g_h1);
    cudaGetSymbolAddress((void**)&redb, g_red);

    sched_kernel<<<1, 32>>>(lengths);
    embed_kernel<<<M_, 256>>>(ut, emb, x);

    for (int i = 0; i < NL_; i++) {
        // qkv (fp16 out)
        gemm_a32_kernel<<<dim3(768 / 64, M_ / 128), 256>>>(
            x, wqkv + (size_t)i * 3 * D_ * D_, bqkv + (size_t)i * 3 * D_,
            nullptr, nullptr, qkvb, 3 * D_, D_, 0);
        // attention (fp16 in/out)
        attn_tc_kernel<<<dim3(H_, B_ * L_ / 64), 128>>>(qkvb, aob, lengths);
        // h1 = ao @ Wo^T + bo + x   (fp16 A, fp32 out)
        gemm_a16_kernel<<<dim3(D_ / 64, M_ / 128), 256>>>(
            aob, wo + (size_t)i * D_ * D_, bo + (size_t)i * D_,
            x, h1b, D_, D_);
        // x = relu?(h1 @ Wlin^T + blin)
        gemm_a32_kernel<<<dim3(D_ / 64, M_ / 128), 256>>>(
            h1b, wlin + (size_t)i * D_ * D_, blin + (size_t)i * D_,
            nullptr, x, nullptr, D_, D_, (i < NL_ - 1) ? 1 : 0);
    }

    graph_partial_kernel<<<dim3(8, B_), 256>>>(x, lengths, redb);
    graph_final_kernel<<<B_, 256>>>(redb, lengths, out);
    node_out_kernel<<<M_, 256>>>(x, lengths, out + B_ * D_);
}

// round 17
// speedup vs baseline: 1.5908x; 1.0563x over previous
#include <cuda_runtime.h>
#include <cuda_fp16.h>
#include <math.h>
#include <stdint.h>

#define B_  16
#define L_  1024
#define D_  256
#define H_  8
#define NL_ 3
#define M_  (B_ * L_)   // 16384

// ---------------- scratch ----------------
__device__ float  g_x[M_ * D_];
__device__ __half g_qkv[M_ * 3 * D_];
__device__ __half g_ao[M_ * D_];
__device__ float  g_h1[M_ * D_];
__device__ float  g_red[B_ * 8 * D_];

// compacted work lists
__device__ int g_nrb;
__device__ int g_rowblk[128];
__device__ int g_nab;
__device__ int g_attnblk[256];

// ---------------- helpers ----------------
__device__ __forceinline__ void mma_f16(float c[4], const uint32_t a[4],
                                        const uint32_t b[2]) {
    asm volatile(
        "mma.sync.aligned.m16n8k16.row.col.f32.f16.f16.f32 "
        "{%0,%1,%2,%3}, {%4,%5,%6,%7}, {%8,%9}, {%0,%1,%2,%3};\n"
        : "+f"(c[0]), "+f"(c[1]), "+f"(c[2]), "+f"(c[3])
        : "r"(a[0]), "r"(a[1]), "r"(a[2]), "r"(a[3]), "r"(b[0]), "r"(b[1]));
}

__device__ __forceinline__ void ldm_x4(uint32_t& r0, uint32_t& r1,
                                       uint32_t& r2, uint32_t& r3,
                                       uint32_t addr) {
    asm volatile(
        "ldmatrix.sync.aligned.m8n8.x4.shared.b16 {%0,%1,%2,%3}, [%4];"
        : "=r"(r0), "=r"(r1), "=r"(r2), "=r"(r3) : "r"(addr));
}

__device__ __forceinline__ void ldm_x4_t(uint32_t& r0, uint32_t& r1,
                                         uint32_t& r2, uint32_t& r3,
                                         uint32_t addr) {
    asm volatile(
        "ldmatrix.sync.aligned.m8n8.x4.trans.shared.b16 {%0,%1,%2,%3}, [%4];"
        : "=r"(r0), "=r"(r1), "=r"(r2), "=r"(r3) : "r"(addr));
}

__device__ __forceinline__ uint32_t packh2(float lo, float hi) {
    __half2 h = __floats2half2_rn(lo, hi);
    return *(uint32_t*)&h;
}

__device__ __forceinline__ void cp16(uint32_t smem_dst, const void* gsrc) {
    asm volatile("cp.async.cg.shared.global [%0], [%1], 16;\n"
                 :: "r"(smem_dst), "l"(gsrc));
}
__device__ __forceinline__ void cp_commit() {
    asm volatile("cp.async.commit_group;\n");
}
__device__ __forceinline__ void cp_wait0() {
    asm volatile("cp.async.wait_group 0;\n");
}

// ---------------- scheduler ----------------
__global__ void sched_kernel(const int* __restrict__ lengths) {
    if (threadIdx.x != 0) return;
    int idx[B_], len[B_];
#pragma unroll
    for (int b = 0; b < B_; b++) { idx[b] = b; len[b] = lengths[b]; }
#pragma unroll
    for (int i = 0; i < B_ - 1; i++) {
        int best = i;
        for (int j = i + 1; j < B_; j++)
            if (len[j] > len[best] || (len[j] == len[best] && idx[j] < idx[best]))
                best = j;
        int tl = len[i]; len[i] = len[best]; len[best] = tl;
        int ti = idx[i]; idx[i] = idx[best]; idx[best] = ti;
    }
    int n = 0, m = 0;
    for (int i = 0; i < B_; i++) {
        int b = idx[i], ln = len[i];
        int nrb = (ln + 127) >> 7;
        for (int r = 0; r < nrb; r++) g_rowblk[n++] = b * L_ + r * 128;
        int nab = (ln + 63) >> 6;
        for (int q = 0; q < nab; q++) g_attnblk[m++] = (b << 16) | q;
    }
    g_nrb = n;
    g_nab = m;
}

// ---------------- embedding gather ----------------
__global__ void embed_kernel(const int* __restrict__ ut,
                             const float* __restrict__ emb,
                             float* __restrict__ x) {
    int row = blockIdx.x;
    int d = threadIdx.x;
    x[(size_t)row * D_ + d] = emb[(size_t)ut[row] * D_ + d];
}

// ---------------- GEMM (A fp32): C = A @ W^T + bias (+res) (relu) ------------
#define KPH 72
__global__ void __launch_bounds__(256) gemm_a32_kernel(
    const float* __restrict__ A, const float* __restrict__ W,
    const float* __restrict__ bias, const float* __restrict__ res,
    float* __restrict__ Cf, __half* __restrict__ Ch,
    int N, int K, int doRelu) {
    if ((int)blockIdx.y >= g_nrb) return;
    const int row0 = g_rowblk[blockIdx.y];

    __shared__ __half Ah[128 * KPH];
    __shared__ __half Bh[64 * KPH];

    const int tid = threadIdx.x;
    const int warp = tid >> 5, lane = tid & 31;
    const int g = lane >> 2, t4 = lane & 3;
    const int gl = lane >> 3, lr = lane & 7;
    const int wm = (warp & 3) * 32;
    const int wn = (warp >> 2) * 32;
    const int col0 = blockIdx.x * 64;

    const int lrow = tid >> 2;
    const int lcol = (tid & 3) * 16;

    const uint32_t ahB = (uint32_t)__cvta_generic_to_shared(Ah);
    const uint32_t bhB = (uint32_t)__cvta_generic_to_shared(Bh);

    float acc[2][4][4];
#pragma unroll
    for (int mi = 0; mi < 2; mi++)
#pragma unroll
        for (int ni = 0; ni < 4; ni++)
#pragma unroll
            for (int j = 0; j < 4; j++) acc[mi][ni][j] = 0.f;

    const float* a0p = A + (size_t)(row0 + lrow) * K + lcol;
    const float* a1p = A + (size_t)(row0 + 64 + lrow) * K + lcol;
    const float* wp  = W + (size_t)(col0 + lrow) * K + lcol;

    for (int kt = 0; kt < K; kt += 64) {
        float4 fa0[4], fa1[4], fw[4];
#pragma unroll
        for (int i = 0; i < 4; i++) {
            fa0[i] = *(const float4*)(a0p + kt + i * 4);
            fa1[i] = *(const float4*)(a1p + kt + i * 4);
            fw[i]  = *(const float4*)(wp + kt + i * 4);
        }
        __syncthreads();
        __half2 h[8];
#pragma unroll
        for (int i = 0; i < 4; i++) {
            h[2 * i]     = __floats2half2_rn(fa0[i].x, fa0[i].y);
            h[2 * i + 1] = __floats2half2_rn(fa0[i].z, fa0[i].w);
        }
        *(uint4*)&Ah[lrow * KPH + lcol]     = *(uint4*)&h[0];
        *(uint4*)&Ah[lrow * KPH + lcol + 8] = *(uint4*)&h[4];
#pragma unroll
        for (int i = 0; i < 4; i++) {
            h[2 * i]     = __floats2half2_rn(fa1[i].x, fa1[i].y);
            h[2 * i + 1] = __floats2half2_rn(fa1[i].z, fa1[i].w);
        }
        *(uint4*)&Ah[(64 + lrow) * KPH + lcol]     = *(uint4*)&h[0];
        *(uint4*)&Ah[(64 + lrow) * KPH + lcol + 8] = *(uint4*)&h[4];
#pragma unroll
        for (int i = 0; i < 4; i++) {
            h[2 * i]     = __floats2half2_rn(fw[i].x, fw[i].y);
            h[2 * i + 1] = __floats2half2_rn(fw[i].z, fw[i].w);
        }
        *(uint4*)&Bh[lrow * KPH + lcol]     = *(uint4*)&h[0];
        *(uint4*)&Bh[lrow * KPH + lcol + 8] = *(uint4*)&h[4];
        __syncthreads();

#pragma unroll
        for (int ks = 0; ks < 4; ks++) {
            const int k0 = ks * 16;
            uint32_t a[2][4];
#pragma unroll
            for (int mi = 0; mi < 2; mi++) {
                int row = wm + mi * 16 + (gl & 1) * 8 + lr;
                int col = k0 + (gl >> 1) * 8;
                ldm_x4(a[mi][0], a[mi][1], a[mi][2], a[mi][3],
                       ahB + (row * KPH + col) * 2);
            }
            uint32_t bf[4][2];
#pragma unroll
            for (int half = 0; half < 2; half++) {
                int row = wn + (half * 2 + (gl >> 1)) * 8 + lr;
                int col = k0 + (gl & 1) * 8;
                ldm_x4(bf[half * 2][0], bf[half * 2][1],
                       bf[half * 2 + 1][0], bf[half * 2 + 1][1],
                       bhB + (row * KPH + col) * 2);
            }
#pragma unroll
            for (int ni = 0; ni < 4; ni++) {
                mma_f16(acc[0][ni], a[0], bf[ni]);
                mma_f16(acc[1][ni], a[1], bf[ni]);
            }
        }
    }

#pragma unroll
    for (int ni = 0; ni < 4; ni++) {
        int c = col0 + wn + ni * 8 + 2 * t4;
        float b0 = bias[c], b1 = bias[c + 1];
#pragma unroll
        for (int mi = 0; mi < 2; mi++) {
#pragma unroll
            for (int half = 0; half < 2; half++) {
                int r = row0 + wm + mi * 16 + g + half * 8;
                float v0 = acc[mi][ni][half * 2 + 0] + b0;
                float v1 = acc[mi][ni][half * 2 + 1] + b1;
                if (res) {
                    float2 rr = *(const float2*)(res + (size_t)r * N + c);
                    v0 += rr.x; v1 += rr.y;
                }
                if (doRelu) { v0 = fmaxf(v0, 0.f); v1 = fmaxf(v1, 0.f); }
                if (Ch) {
                    *(uint32_t*)(Ch + (size_t)r * N + c) = packh2(v0, v1);
                } else {
                    float2 o; o.x = v0; o.y = v1;
                    *(float2*)(Cf + (size_t)r * N + c) = o;
                }
            }
        }
    }
}

// ---------------- GEMM (A fp16 input): h1 = A @ W^T + bias + res (fp32 out) --
__global__ void __launch_bounds__(256) gemm_a16_kernel(
    const __half* __restrict__ A, const float* __restrict__ W,
    const float* __restrict__ bias, const float* __restrict__ res,
    float* __restrict__ Cf, int N, int K) {
    if ((int)blockIdx.y >= g_nrb) return;
    const int row0 = g_rowblk[blockIdx.y];

    __shared__ __half Ah[128 * KPH];
    __shared__ __half Bh[64 * KPH];

    const int tid = threadIdx.x;
    const int warp = tid >> 5, lane = tid & 31;
    const int g = lane >> 2, t4 = lane & 3;
    const int gl = lane >> 3, lr = lane & 7;
    const int wm = (warp & 3) * 32;
    const int wn = (warp >> 2) * 32;
    const int col0 = blockIdx.x * 64;

    const int lrow = tid >> 2;
    const int lcol = (tid & 3) * 16;

    const uint32_t ahB = (uint32_t)__cvta_generic_to_shared(Ah);
    const uint32_t bhB = (uint32_t)__cvta_generic_to_shared(Bh);

    float acc[2][4][4];
#pragma unroll
    for (int mi = 0; mi < 2; mi++)
#pragma unroll
        for (int ni = 0; ni < 4; ni++)
#pragma unroll
            for (int j = 0; j < 4; j++) acc[mi][ni][j] = 0.f;

    const __half* a0p = A + (size_t)(row0 + lrow) * K + lcol;
    const __half* a1p = A + (size_t)(row0 + 64 + lrow) * K + lcol;
    const float*  wp  = W + (size_t)(col0 + lrow) * K + lcol;

    for (int kt = 0; kt < K; kt += 64) {
        uint4 ha0[2], ha1[2];
        float4 fw[4];
#pragma unroll
        for (int i = 0; i < 2; i++) {
            ha0[i] = *(const uint4*)(a0p + kt + i * 8);
            ha1[i] = *(const uint4*)(a1p + kt + i * 8);
        }
#pragma unroll
        for (int i = 0; i < 4; i++) fw[i] = *(const float4*)(wp + kt + i * 4);
        __syncthreads();
        *(uint4*)&Ah[lrow * KPH + lcol]     = ha0[0];
        *(uint4*)&Ah[lrow * KPH + lcol + 8] = ha0[1];
        *(uint4*)&Ah[(64 + lrow) * KPH + lcol]     = ha1[0];
        *(uint4*)&Ah[(64 + lrow) * KPH + lcol + 8] = ha1[1];
        __half2 h[8];
#pragma unroll
        for (int i = 0; i < 4; i++) {
            h[2 * i]     = __floats2half2_rn(fw[i].x, fw[i].y);
            h[2 * i + 1] = __floats2half2_rn(fw[i].z, fw[i].w);
        }
        *(uint4*)&Bh[lrow * KPH + lcol]     = *(uint4*)&h[0];
        *(uint4*)&Bh[lrow * KPH + lcol + 8] = *(uint4*)&h[4];
        __syncthreads();

#pragma unroll
        for (int ks = 0; ks < 4; ks++) {
            const int k0 = ks * 16;
            uint32_t a[2][4];
#pragma unroll
            for (int mi = 0; mi < 2; mi++) {
                int row = wm + mi * 16 + (gl & 1) * 8 + lr;
                int col = k0 + (gl >> 1) * 8;
                ldm_x4(a[mi][0], a[mi][1], a[mi][2], a[mi][3],
                       ahB + (row * KPH + col) * 2);
            }
            uint32_t bf[4][2];
#pragma unroll
            for (int half = 0; half < 2; half++) {
                int row = wn + (half * 2 + (gl >> 1)) * 8 + lr;
                int col = k0 + (gl & 1) * 8;
                ldm_x4(bf[half * 2][0], bf[half * 2][1],
                       bf[half * 2 + 1][0], bf[half * 2 + 1][1],
                       bhB + (row * KPH + col) * 2);
            }
#pragma unroll
            for (int ni = 0; ni < 4; ni++) {
                mma_f16(acc[0][ni], a[0], bf[ni]);
                mma_f16(acc[1][ni], a[1], bf[ni]);
            }
        }
    }

#pragma unroll
    for (int ni = 0; ni < 4; ni++) {
        int c = col0 + wn + ni * 8 + 2 * t4;
        float b0 = bias[c], b1 = bias[c + 1];
#pragma unroll
        for (int mi = 0; mi < 2; mi++) {
#pragma unroll
            for (int half = 0; half < 2; half++) {
                int r = row0 + wm + mi * 16 + g + half * 8;
                float2 rr = *(const float2*)(res + (size_t)r * N + c);
                float2 o;
                o.x = acc[mi][ni][half * 2 + 0] + b0 + rr.x;
                o.y = acc[mi][ni][half * 2 + 1] + b1 + rr.y;
                *(float2*)(Cf + (size_t)r * N + c) = o;
            }
        }
    }
}

// ---------------- attention: base-2 softmax, cp.async K/V double buffer ------
#define KP 40    // halves per row
#define KVT (64 * KP)   // halves per K (or V) tile buffer
__global__ void __launch_bounds__(128) attn_tc_kernel(
    const __half* __restrict__ qkv, __half* __restrict__ ao,
    const int* __restrict__ lengths) {
    if ((int)blockIdx.y >= g_nab) return;
    const int packed = g_attnblk[blockIdx.y];
    const int b = packed >> 16;
    const int q0 = (packed & 0xffff) * 64;
    const int h = blockIdx.x;
    const int len = lengths[b];

    __shared__ __half Qh[64 * KP];
    __shared__ __half Kh[2][KVT];
    __shared__ __half Vs[2][KVT];

    const int tid = threadIdx.x, w = tid >> 5, lane = tid & 31;
    const int g = lane >> 2, t4 = lane & 3;
    const int gl = lane >> 3, lr = lane & 7;
    const int wq = w * 16;
    const __half* base = qkv + (size_t)b * L_ * 768;

    const uint32_t khB = (uint32_t)__cvta_generic_to_shared(&Kh[0][0]);
    const uint32_t vsB = (uint32_t)__cvta_generic_to_shared(&Vs[0][0]);
    const uint32_t bufB = KVT * 2;  // byte stride between buffers

    // ---- load Q tile ----
#pragma unroll
    for (int i = 0; i < 4; i++) {
        int c = tid + i * 128;
        int row = c >> 3, ch = (c & 7) * 4;
        uint2 u = *(const uint2*)(base + (size_t)(q0 + row) * 768 + h * 32 + ch);
        *(uint2*)&Qh[row * KP + ch] = u;
    }

    // cp.async mapping for K/V tiles: 2 chunks of 16B each per tensor
    const int chunk0 = tid * 2;
    const int krow0 = chunk0 >> 2, kch0 = (chunk0 & 3) * 8;
    const int krow1 = (chunk0 + 1) >> 2, kch1 = ((chunk0 + 1) & 3) * 8;

    // prologue: issue tile 0
    {
        const __half* kp0 = base + (size_t)krow0 * 768 + 256 + h * 32 + kch0;
        const __half* kp1 = base + (size_t)krow1 * 768 + 256 + h * 32 + kch1;
        cp16(khB + (krow0 * KP + kch0) * 2, kp0);
        cp16(khB + (krow1 * KP + kch1) * 2, kp1);
        cp16(vsB + (krow0 * KP + kch0) * 2, kp0 + 256);
        cp16(vsB + (krow1 * KP + kch1) * 2, kp1 + 256);
    }
    cp_commit();
    __syncthreads();   // Qh visible

    // ---- Q A-fragments scaled by (1/sqrt(hd)) * log2(e) ----
    const __half2 qs = __float2half2_rn(0.17677669529663687f * 1.4426950408889634f);
    uint32_t qa[2][4];
#pragma unroll
    for (int kc = 0; kc < 2; kc++) {
        __half2 v0 = *(__half2*)&Qh[(wq + g) * KP + kc * 16 + 2 * t4];
        __half2 v1 = *(__half2*)&Qh[(wq + g + 8) * KP + kc * 16 + 2 * t4];
        __half2 v2 = *(__half2*)&Qh[(wq + g) * KP + kc * 16 + 2 * t4 + 8];
        __half2 v3 = *(__half2*)&Qh[(wq + g + 8) * KP + kc * 16 + 2 * t4 + 8];
        v0 = __hmul2(v0, qs); v1 = __hmul2(v1, qs);
        v2 = __hmul2(v2, qs); v3 = __hmul2(v3, qs);
        qa[kc][0] = *(uint32_t*)&v0; qa[kc][1] = *(uint32_t*)&v1;
        qa[kc][2] = *(uint32_t*)&v2; qa[kc][3] = *(uint32_t*)&v3;
    }

    float o[4][4];
#pragma unroll
    for (int nv = 0; nv < 4; nv++)
#pragma unroll
        for (int j = 0; j < 4; j++) o[nv][j] = 0.f;
    float m0 = -1e30f, m1 = -1e30f, ls0 = 0.f, ls1 = 0.f;

    const int ntiles = (len + 63) >> 6;
    for (int t = 0; t < ntiles; t++) {
        const int kt = t * 64;
        const bool tailTile = (kt + 64 > len);
        const int cur = t & 1;
        cp_wait0();
        __syncthreads();

        if (t + 1 < ntiles) {   // issue next K/V tile under current compute
            const int kn = kt + 64;
            const uint32_t kd = khB + (cur ? 0u : bufB);
            const uint32_t vd = vsB + (cur ? 0u : bufB);
            const __half* kp0 = base + (size_t)(kn + krow0) * 768 + 256 + h * 32 + kch0;
            const __half* kp1 = base + (size_t)(kn + krow1) * 768 + 256 + h * 32 + kch1;
            cp16(kd + (krow0 * KP + kch0) * 2, kp0);
            cp16(kd + (krow1 * KP + kch1) * 2, kp1);
            cp16(vd + (krow0 * KP + kch0) * 2, kp0 + 256);
            cp16(vd + (krow1 * KP + kch1) * 2, kp1 + 256);
            cp_commit();
        }

        const uint32_t khC = khB + cur * bufB;
        const uint32_t vsC = vsB + cur * bufB;

        // ---- S2 = (Q*scale*log2e) @ K^T ----
        float sc[8][4];
#pragma unroll
        for (int n = 0; n < 8; n++)
            sc[n][0] = sc[n][1] = sc[n][2] = sc[n][3] = 0.f;
#pragma unroll
        for (int kc = 0; kc < 2; kc++) {
            uint32_t kb[8][2];
#pragma unroll
            for (int j = 0; j < 8; j += 2) {
                int key = (j + (gl >> 1)) * 8 + lr;
                int col = kc * 16 + (gl & 1) * 8;
                ldm_x4(kb[j][0], kb[j][1], kb[j + 1][0], kb[j + 1][1],
                       khC + (key * KP + col) * 2);
            }
#pragma unroll
            for (int n = 0; n < 8; n++)
                mma_f16(sc[n], qa[kc], kb[n]);
        }

        // ---- mask (tail only) + row max ----
        float rmax0 = -1e30f, rmax1 = -1e30f;
        if (tailTile) {
#pragma unroll
            for (int n = 0; n < 8; n++) {
                int c0 = kt + n * 8 + 2 * t4;
                bool v0 = c0 < len, v1 = (c0 + 1) < len;
                sc[n][0] = v0 ? sc[n][0] : -1e30f;
                sc[n][1] = v1 ? sc[n][1] : -1e30f;
                sc[n][2] = v0 ? sc[n][2] : -1e30f;
                sc[n][3] = v1 ? sc[n][3] : -1e30f;
                rmax0 = fmaxf(rmax0, fmaxf(sc[n][0], sc[n][1]));
                rmax1 = fmaxf(rmax1, fmaxf(sc[n][2], sc[n][3]));
            }
        } else {
#pragma unroll
            for (int n = 0; n < 8; n++) {
                rmax0 = fmaxf(rmax0, fmaxf(sc[n][0], sc[n][1]));
                rmax1 = fmaxf(rmax1, fmaxf(sc[n][2], sc[n][3]));
            }
        }
        rmax0 = fmaxf(rmax0, __shfl_xor_sync(0xffffffffu, rmax0, 1));
        rmax0 = fmaxf(rmax0, __shfl_xor_sync(0xffffffffu, rmax0, 2));
        rmax1 = fmaxf(rmax1, __shfl_xor_sync(0xffffffffu, rmax1, 1));
        rmax1 = fmaxf(rmax1, __shfl_xor_sync(0xffffffffu, rmax1, 2));

        float nm0 = fmaxf(m0, rmax0), nm1 = fmaxf(m1, rmax1);
        float cr0 = exp2f(m0 - nm0), cr1 = exp2f(m1 - nm1);
        ls0 *= cr0; ls1 *= cr1;
#pragma unroll
        for (int nv = 0; nv < 4; nv++) {
            o[nv][0] *= cr0; o[nv][1] *= cr0;
            o[nv][2] *= cr1; o[nv][3] *= cr1;
        }
        m0 = nm0; m1 = nm1;

        // ---- p = exp2(s2 - m) ----
#pragma unroll
        for (int n = 0; n < 8; n++) {
            sc[n][0] = exp2f(sc[n][0] - m0);
            sc[n][1] = exp2f(sc[n][1] - m0);
            sc[n][2] = exp2f(sc[n][2] - m1);
            sc[n][3] = exp2f(sc[n][3] - m1);
            ls0 += sc[n][0] + sc[n][1];
            ls1 += sc[n][2] + sc[n][3];
        }

        // ---- O += P @ V (C-frag -> A-frag direct) ----
#pragma unroll
        for (int kc2 = 0; kc2 < 4; kc2++) {
            uint32_t pa[4];
            pa[0] = packh2(sc[2 * kc2][0], sc[2 * kc2][1]);
            pa[1] = packh2(sc[2 * kc2][2], sc[2 * kc2][3]);
            pa[2] = packh2(sc[2 * kc2 + 1][0], sc[2 * kc2 + 1][1]);
            pa[3] = packh2(sc[2 * kc2 + 1][2], sc[2 * kc2 + 1][3]);
            uint32_t vb[4][2];
#pragma unroll
            for (int vh = 0; vh < 2; vh++) {
                int key = kc2 * 16 + (gl & 1) * 8 + lr;
                int dcol = vh * 16 + (gl >> 1) * 8;
                ldm_x4_t(vb[vh * 2][0], vb[vh * 2][1],
                         vb[vh * 2 + 1][0], vb[vh * 2 + 1][1],
                         vsC + (key * KP + dcol) * 2);
            }
#pragma unroll
            for (int nv = 0; nv < 4; nv++)
                mma_f16(o[nv], pa, vb[nv]);
        }
        __syncthreads();   // done with cur buffers before next overwrite
    }

    ls0 += __shfl_xor_sync(0xffffffffu, ls0, 1);
    ls0 += __shfl_xor_sync(0xffffffffu, ls0, 2);
    ls1 += __shfl_xor_sync(0xffffffffu, ls1, 1);
    ls1 += __shfl_xor_sync(0xffffffffu, ls1, 2);
    float i0 = 1.f / ls0, i1 = 1.f / ls1;

    const int r0 = q0 + wq + g;
    __half* op0 = ao + (size_t)(b * L_ + r0) * D_ + h * 32;
    __half* op1 = ao + (size_t)(b * L_ + r0 + 8) * D_ + h * 32;
#pragma unroll
    for (int nv = 0; nv < 4; nv++) {
        *(uint32_t*)(op0 + nv * 8 + 2 * t4) = packh2(o[nv][0] * i0, o[nv][1] * i0);
        *(uint32_t*)(op1 + nv * 8 + 2 * t4) = packh2(o[nv][2] * i1, o[nv][3] * i1);
    }
}

// ---------------- readout ----------------
__global__ void graph_partial_kernel(const float* __restrict__ x,
                                     const int* __restrict__ lengths,
                                     float* __restrict__ red) {
    int chunk = blockIdx.x, b = blockIdx.y, d = threadIdx.x;
    int len = lengths[b];
    int l0 = chunk * 128;
    int l1 = min(l0 + 128, len);
    float s = 0.f;
    for (int l = l0; l < l1; l++) s += x[((size_t)b * L_ + l) * D_ + d];
    red[((size_t)b * 8 + chunk) * D_ + d] = s;
}

__global__ void graph_final_kernel(const float* __restrict__ red,
                                   const int* __restrict__ lengths,
                                   float* __restrict__ out) {
    int b = blockIdx.x, d = threadIdx.x;
    float s = 0.f;
#pragma unroll
    for (int c = 0; c < 8; c++) s += red[((size_t)b * 8 + c) * D_ + d];
    int cnt = lengths[b] > 1 ? lengths[b] : 1;
    out[b * D_ + d] = s / (float)cnt;
}

__global__ void node_out_kernel(const float* __restrict__ x,
                                const int* __restrict__ lengths,
                                float* __restrict__ out) {
    int row = blockIdx.x, d = threadIdx.x;
    int b = row >> 10, l = row & 1023;
    float v = (l < lengths[b]) ? x[(size_t)row * D_ + d] : 0.f;
    out[(size_t)row * D_ + d] = v;
}

// ---------------- launch ----------------
extern "C" void kernel_launch(void* const* d_in, const int* in_sizes, int n_in,
                              void* d_out, int out_size) {
    const int*   ut      = (const int*)d_in[0];
    const int*   lengths = (const int*)d_in[1];
    const float* emb     = (const float*)d_in[2];
    const float* wqkv    = (const float*)d_in[3];
    const float* bqkv    = (const float*)d_in[4];
    const float* wo      = (const float*)d_in[5];
    const float* bo      = (const float*)d_in[6];
    const float* wlin    = (const float*)d_in[7];
    const float* blin    = (const float*)d_in[8];
    float* out = (float*)d_out;

    float *x, *h1b, *redb;
    __half *qkvb, *aob;
    cudaGetSymbolAddress((void**)&x, g_x);
    cudaGetSymbolAddress((void**)&qkvb, g_qkv);
    cudaGetSymbolAddress((void**)&aob, g_ao);
    cudaGetSymbolAddress((void**)&h1b, g_h1);
    cudaGetSymbolAddress((void**)&redb, g_red);

    sched_kernel<<<1, 32>>>(lengths);
    embed_kernel<<<M_, 256>>>(ut, emb, x);

    for (int i = 0; i < NL_; i++) {
        gemm_a32_kernel<<<dim3(768 / 64, M_ / 128), 256>>>(
            x, wqkv + (size_t)i * 3 * D_ * D_, bqkv + (size_t)i * 3 * D_,
            nullptr, nullptr, qkvb, 3 * D_, D_, 0);
        attn_tc_kernel<<<dim3(H_, B_ * L_ / 64), 128>>>(qkvb, aob, lengths);
        gemm_a16_kernel<<<dim3(D_ / 64, M_ / 128), 256>>>(
            aob, wo + (size_t)i * D_ * D_, bo + (size_t)i * D_,
            x, h1b, D_, D_);
        gemm_a32_kernel<<<dim3(D_ / 64, M_ / 128), 256>>>(
            h1b, wlin + (size_t)i * D_ * D_, blin + (size_t)i * D_,
            nullptr, x, nullptr, D_, D_, (i < NL_ - 1) ? 1 : 0);
    }

    graph_partial_kernel<<<dim3(8, B_), 256>>>(x, lengths, redb);
    graph_final_kernel<<<B_, 256>>>(redb, lengths, out);
    node_out_kernel<<<M_, 256>>>(x, lengths, out + B_ * D_);
}